// round 1
// baseline (speedup 1.0000x reference)
#include <cuda_runtime.h>
#include <cuda_bf16.h>
#include <math.h>

// ---------------------------------------------------------------------------
// Problem constants
// ---------------------------------------------------------------------------
#define S    2048
#define DIM  1024
#define HQ   8
#define G    4
#define D    128
#define KOUT 4

// ---------------------------------------------------------------------------
// Scratch (device globals; no runtime allocation allowed)
// ---------------------------------------------------------------------------
__device__ float g_q[S * HQ * D];      // (S, 1024)
__device__ float g_k[S * G * D];       // (S, 512)
__device__ float g_v[S * G * D];       // (S, 512)
__device__ float g_attn[S * HQ * D];   // (S, 1024)
__device__ float g_o[S * DIM];         // (S, 1024)
__device__ float g_h1[S * DIM * 4];    // (S, 4096)

// ---------------------------------------------------------------------------
// Generic fp32 NT GEMM:  C[M,N] = A[M,KK] @ W[N,KK]^T + bias[N]  (+ SiLU)
// 128x128 tile, BK=16, 256 threads, 8x8 per-thread micro-tile.
// ---------------------------------------------------------------------------
#define BM 128
#define BN 128
#define BK 16
#define SPAD 4

__global__ void __launch_bounds__(256, 2)
gemm_nt(const float* __restrict__ A, const float* __restrict__ W,
        const float* __restrict__ bias, float* __restrict__ C,
        int M, int N, int KK, int act)
{
    __shared__ float As[BK][BM + SPAD];
    __shared__ float Ws[BK][BN + SPAD];

    const int bm = blockIdx.y * BM;
    const int bn = blockIdx.x * BN;
    const int tid = threadIdx.x;
    const int tx = tid & 15;        // 0..15 -> n
    const int ty = tid >> 4;        // 0..15 -> m

    // load mapping: each thread loads 2x float4 for A and 2x float4 for W
    const int lr = tid >> 2;            // 0..63
    const int lc = (tid & 3) << 2;      // 0,4,8,12

    float acc[8][8];
#pragma unroll
    for (int i = 0; i < 8; i++)
#pragma unroll
        for (int j = 0; j < 8; j++) acc[i][j] = 0.f;

    for (int k0 = 0; k0 < KK; k0 += BK) {
#pragma unroll
        for (int r = 0; r < 2; r++) {
            const int row = lr + r * 64;
            float4 a4 = *(const float4*)(A + (size_t)(bm + row) * KK + k0 + lc);
            As[lc + 0][row] = a4.x; As[lc + 1][row] = a4.y;
            As[lc + 2][row] = a4.z; As[lc + 3][row] = a4.w;
            float4 w4 = *(const float4*)(W + (size_t)(bn + row) * KK + k0 + lc);
            Ws[lc + 0][row] = w4.x; Ws[lc + 1][row] = w4.y;
            Ws[lc + 2][row] = w4.z; Ws[lc + 3][row] = w4.w;
        }
        __syncthreads();

#pragma unroll
        for (int kk = 0; kk < BK; kk++) {
            float4 a0 = *(const float4*)&As[kk][ty * 8];
            float4 a1 = *(const float4*)&As[kk][ty * 8 + 4];
            float4 b0 = *(const float4*)&Ws[kk][tx * 8];
            float4 b1 = *(const float4*)&Ws[kk][tx * 8 + 4];
            float a[8] = {a0.x, a0.y, a0.z, a0.w, a1.x, a1.y, a1.z, a1.w};
            float b[8] = {b0.x, b0.y, b0.z, b0.w, b1.x, b1.y, b1.z, b1.w};
#pragma unroll
            for (int i = 0; i < 8; i++)
#pragma unroll
                for (int j = 0; j < 8; j++)
                    acc[i][j] = fmaf(a[i], b[j], acc[i][j]);
        }
        __syncthreads();
    }

#pragma unroll
    for (int i = 0; i < 8; i++) {
        const int row = bm + ty * 8 + i;
#pragma unroll
        for (int j = 0; j < 8; j++) {
            const int col = bn + tx * 8 + j;
            float c = acc[i][j] + bias[col];
            if (act == 1) c = c / (1.f + expf(-c));   // SiLU
            C[(size_t)row * N + col] = c;
        }
    }
}

// ---------------------------------------------------------------------------
// RoPE applied in place to q (S,1024) and k (S,512).
// One thread per (s, head, d<64) rotation pair.
// ---------------------------------------------------------------------------
__global__ void rope_kernel(float* __restrict__ q, float* __restrict__ k)
{
    const int NQ = S * HQ * 64;   // q pairs
    const int NK = S * G * 64;    // k pairs
    int i = blockIdx.x * blockDim.x + threadIdx.x;
    if (i >= NQ + NK) return;

    float* ptr;
    int s, hd, base;
    if (i < NQ) {
        s = i / (HQ * 64);
        hd = i - s * (HQ * 64);
        const int h = hd >> 6;
        const int d = hd & 63;
        base = s * (HQ * D) + h * D + d;
        ptr = q;
        hd = d;
    } else {
        int j = i - NQ;
        s = j / (G * 64);
        int rem = j - s * (G * 64);
        const int g = rem >> 6;
        const int d = rem & 63;
        base = s * (G * D) + g * D + d;
        ptr = k;
        hd = d;
    }
    // inv_freq = 10000^(-2d/128)
    const float inv = powf(10000.f, -(float)(2 * hd) / 128.f);
    const float f = (float)s * inv;
    float sn, cs;
    sincosf(f, &sn, &cs);
    const float x1 = ptr[base];
    const float x2 = ptr[base + 64];
    ptr[base]      = x1 * cs - x2 * sn;
    ptr[base + 64] = x2 * cs + x1 * sn;
}

// ---------------------------------------------------------------------------
// Attention: for each head h, out_h = sum_g softmax_causal(q_h k_g^T / sqrt(D)) v_g
// Block: one (h, 32-row tile). Online softmax over 32-col tiles, per-g, then
// per-g normalized output accumulated into registers (deterministic, no atomics).
// 256 threads: row = tid/8 (32 rows), lane = tid%8. Scores: 4 cols/thread.
// Output: d = lane*16 .. lane*16+15 per thread.
// ---------------------------------------------------------------------------
#define AR 32
#define AC 32

__global__ void __launch_bounds__(256, 4)
attn_kernel(const float* __restrict__ q, const float* __restrict__ k,
            const float* __restrict__ v, float* __restrict__ out)
{
    __shared__ float qs[AR][D + 4];
    __shared__ float kv[AC][D + 4];     // holds K tile, then reused for V tile
    __shared__ float ps[AR][AC];

    const int h = blockIdx.y;
    const int it = blockIdx.x;
    const int row0 = it * AR;
    const int tid = threadIdx.x;
    const int row = tid >> 3;
    const int lane = tid & 7;

    // load q tile (32 x 128)
    for (int x = tid; x < AR * (D / 4); x += 256) {
        const int r = x >> 5;
        const int c4 = x & 31;
        *(float4*)&qs[r][c4 * 4] =
            *(const float4*)(q + (size_t)(row0 + r) * (HQ * D) + h * D + c4 * 4);
    }

    float accT[16];
#pragma unroll
    for (int i = 0; i < 16; i++) accT[i] = 0.f;

    const float scale = 0.08838834764831845f;   // 1/sqrt(128)

    for (int g = 0; g < G; g++) {
        float m = -1e30f, l = 0.f;
        float acc[16];
#pragma unroll
        for (int i = 0; i < 16; i++) acc[i] = 0.f;

        for (int jt = 0; jt <= it; jt++) {
            const int col0 = jt * AC;
            __syncthreads();   // protect kv reuse (previous V reads / q load done)

            // load K tile (32 x 128)
            for (int x = tid; x < AC * (D / 4); x += 256) {
                const int r = x >> 5;
                const int c4 = x & 31;
                *(float4*)&kv[r][c4 * 4] =
                    *(const float4*)(k + (size_t)(col0 + r) * (G * D) + g * D + c4 * 4);
            }
            __syncthreads();

            // scores: 4 columns per thread
            float sc[4] = {0.f, 0.f, 0.f, 0.f};
#pragma unroll 4
            for (int d4 = 0; d4 < D / 4; d4++) {
                const float4 qv = *(const float4*)&qs[row][d4 * 4];
#pragma unroll
                for (int c = 0; c < 4; c++) {
                    const float4 kk4 = *(const float4*)&kv[lane * 4 + c][d4 * 4];
                    sc[c] += qv.x * kk4.x + qv.y * kk4.y + qv.z * kk4.z + qv.w * kk4.w;
                }
            }
#pragma unroll
            for (int c = 0; c < 4; c++) {
                const int jc = col0 + lane * 4 + c;
                sc[c] = (jc <= row0 + row) ? sc[c] * scale : -1e30f;
            }

            // row-wide max over the 8 lanes of this row
            float mt = fmaxf(fmaxf(sc[0], sc[1]), fmaxf(sc[2], sc[3]));
#pragma unroll
            for (int off = 4; off >= 1; off >>= 1)
                mt = fmaxf(mt, __shfl_xor_sync(0xffffffffu, mt, off));
            const float mnew = fmaxf(m, mt);
            const float corr = __expf(m - mnew);

            float p[4], psum = 0.f;
#pragma unroll
            for (int c = 0; c < 4; c++) { p[c] = __expf(sc[c] - mnew); psum += p[c]; }
#pragma unroll
            for (int off = 4; off >= 1; off >>= 1)
                psum += __shfl_xor_sync(0xffffffffu, psum, off);

            l = l * corr + psum;
            m = mnew;
#pragma unroll
            for (int i = 0; i < 16; i++) acc[i] *= corr;

#pragma unroll
            for (int c = 0; c < 4; c++) ps[row][lane * 4 + c] = p[c];

            __syncthreads();   // score reads of kv done; ps visible

            // load V tile into kv
            for (int x = tid; x < AC * (D / 4); x += 256) {
                const int r = x >> 5;
                const int c4 = x & 31;
                *(float4*)&kv[r][c4 * 4] =
                    *(const float4*)(v + (size_t)(col0 + r) * (G * D) + g * D + c4 * 4);
            }
            __syncthreads();

            // O += P @ V   (thread owns d = lane*16 .. +15)
#pragma unroll 4
            for (int c = 0; c < AC; c++) {
                const float pv = ps[row][c];
#pragma unroll
                for (int i4 = 0; i4 < 4; i4++) {
                    const float4 vv = *(const float4*)&kv[c][lane * 16 + i4 * 4];
                    acc[i4 * 4 + 0] = fmaf(pv, vv.x, acc[i4 * 4 + 0]);
                    acc[i4 * 4 + 1] = fmaf(pv, vv.y, acc[i4 * 4 + 1]);
                    acc[i4 * 4 + 2] = fmaf(pv, vv.z, acc[i4 * 4 + 2]);
                    acc[i4 * 4 + 3] = fmaf(pv, vv.w, acc[i4 * 4 + 3]);
                }
            }
        } // jt

        const float invl = 1.f / l;
#pragma unroll
        for (int i = 0; i < 16; i++) accT[i] += acc[i] * invl;
    } // g

    // write out (S, H*D)
#pragma unroll
    for (int i4 = 0; i4 < 4; i4++) {
        float4 o;
        o.x = accT[i4 * 4 + 0]; o.y = accT[i4 * 4 + 1];
        o.z = accT[i4 * 4 + 2]; o.w = accT[i4 * 4 + 3];
        *(float4*)(out + (size_t)(row0 + row) * (HQ * D) + h * D + lane * 16 + i4 * 4) = o;
    }
}

// ---------------------------------------------------------------------------
// Launch
// ---------------------------------------------------------------------------
extern "C" void kernel_launch(void* const* d_in, const int* in_sizes, int n_in,
                              void* d_out, int out_size)
{
    const float* x  = (const float*)d_in[0];
    const float* Wq = (const float*)d_in[1];
    const float* bq = (const float*)d_in[2];
    const float* Wk = (const float*)d_in[3];
    const float* bk = (const float*)d_in[4];
    const float* Wv = (const float*)d_in[5];
    const float* bv = (const float*)d_in[6];
    const float* Wo = (const float*)d_in[7];
    const float* bo = (const float*)d_in[8];
    const float* W1 = (const float*)d_in[9];
    const float* b1 = (const float*)d_in[10];
    const float* W2 = (const float*)d_in[11];
    const float* b2 = (const float*)d_in[12];
    float* out = (float*)d_out;

    float *qp, *kp, *vp, *ap, *op, *h1p;
    cudaGetSymbolAddress((void**)&qp,  g_q);
    cudaGetSymbolAddress((void**)&kp,  g_k);
    cudaGetSymbolAddress((void**)&vp,  g_v);
    cudaGetSymbolAddress((void**)&ap,  g_attn);
    cudaGetSymbolAddress((void**)&op,  g_o);
    cudaGetSymbolAddress((void**)&h1p, g_h1);

    // QKV projections
    gemm_nt<<<dim3(HQ * D / BN, S / BM), 256>>>(x, Wq, bq, qp, S, HQ * D, DIM, 0);
    gemm_nt<<<dim3(G * D / BN,  S / BM), 256>>>(x, Wk, bk, kp, S, G * D,  DIM, 0);
    gemm_nt<<<dim3(G * D / BN,  S / BM), 256>>>(x, Wv, bv, vp, S, G * D,  DIM, 0);

    // RoPE
    {
        const int total = S * HQ * 64 + S * G * 64;
        rope_kernel<<<(total + 255) / 256, 256>>>(qp, kp);
    }

    // Attention
    attn_kernel<<<dim3(S / AR, HQ), 256>>>(qp, kp, vp, ap);

    // O projection
    gemm_nt<<<dim3(DIM / BN, S / BM), 256>>>(ap, Wo, bo, op, S, DIM, HQ * D, 0);

    // FFN
    gemm_nt<<<dim3(4 * DIM / BN, S / BM), 256>>>(op,  W1, b1, h1p, S, 4 * DIM, DIM,     1);
    gemm_nt<<<dim3(KOUT * DIM / BN, S / BM), 256>>>(h1p, W2, b2, out, S, KOUT * DIM, 4 * DIM, 0);
}

// round 2
// speedup vs baseline: 1.1279x; 1.1279x over previous
#include <cuda_runtime.h>
#include <cuda_bf16.h>
#include <math.h>
#include <stdint.h>

// ---------------------------------------------------------------------------
// Problem constants
// ---------------------------------------------------------------------------
#define S    2048
#define DIM  1024
#define HQ   8
#define G    4
#define D    128
#define KOUT 4

// ---------------------------------------------------------------------------
// Scratch (device globals; no runtime allocation allowed)
// ---------------------------------------------------------------------------
__device__ float g_q[S * HQ * D];      // (S, 1024)
__device__ float g_k[S * G * D];       // (S, 512)
__device__ float g_v[S * G * D];       // (S, 512)
__device__ float g_attn[S * HQ * D];   // (S, 1024)
__device__ float g_o[S * DIM];         // (S, 1024)
__device__ float g_h1[S * DIM * 4];    // (S, 4096)

// ---------------------------------------------------------------------------
// TF32 tensor-core NT GEMM: C[M,N] = A[M,KK] @ W[N,KK]^T + bias[N] (+ SiLU)
// 128x128x32 tile, 256 threads (8 warps as 2m x 4n), warp tile 64x32,
// mma.sync.aligned.m16n8k8.row.col.f32.tf32.tf32.f32
// smem stride 36 words: fragment LDS conflict-free (bank = 4*row + k),
// packed uint4 STS.128 conflict-free.
// ---------------------------------------------------------------------------
#define TBM 128
#define TBN 128
#define TBK 32
#define TST 36   // TBK + 4

__device__ __forceinline__ uint32_t f2tf32(float v) {
    uint32_t u;
    asm("cvt.rna.tf32.f32 %0, %1;" : "=r"(u) : "f"(v));
    return u;
}

__global__ void __launch_bounds__(256)
gemm_tf32(const float* __restrict__ A, const float* __restrict__ W,
          const float* __restrict__ bias, float* __restrict__ C,
          int M, int N, int KK, int act)
{
    __shared__ uint32_t As[TBM][TST];
    __shared__ uint32_t Ws[TBN][TST];

    const int bm = blockIdx.y * TBM;
    const int bn = blockIdx.x * TBN;
    const int tid = threadIdx.x;
    const int wid = tid >> 5;
    const int lane = tid & 31;
    const int wm = (wid & 1) * 64;     // warp m-offset within tile
    const int wn = (wid >> 1) * 32;    // warp n-offset within tile
    const int qrow = lane >> 2;        // 0..7
    const int qcol = lane & 3;         // 0..3

    float acc[4][4][4];
#pragma unroll
    for (int mt = 0; mt < 4; mt++)
#pragma unroll
        for (int nt = 0; nt < 4; nt++)
#pragma unroll
            for (int r = 0; r < 4; r++) acc[mt][nt][r] = 0.f;

    for (int k0 = 0; k0 < KK; k0 += TBK) {
        // ---- global -> smem (tf32-rounded, packed 128-bit stores) ----
#pragma unroll
        for (int r = 0; r < 4; r++) {
            const int idx = tid + r * 256;       // 0..1023
            const int row = idx >> 3;            // 0..127
            const int c4 = (idx & 7) << 2;       // 0,4,...,28
            float4 a4 = *(const float4*)(A + (size_t)(bm + row) * KK + k0 + c4);
            uint4 ua;
            ua.x = f2tf32(a4.x); ua.y = f2tf32(a4.y);
            ua.z = f2tf32(a4.z); ua.w = f2tf32(a4.w);
            *(uint4*)&As[row][c4] = ua;
            float4 w4 = *(const float4*)(W + (size_t)(bn + row) * KK + k0 + c4);
            uint4 uw;
            uw.x = f2tf32(w4.x); uw.y = f2tf32(w4.y);
            uw.z = f2tf32(w4.z); uw.w = f2tf32(w4.w);
            *(uint4*)&Ws[row][c4] = uw;
        }
        __syncthreads();

        // ---- 4 k-steps of 8 ----
#pragma unroll
        for (int ks = 0; ks < 4; ks++) {
            const int kb = ks * 8;
            uint32_t af[4][4], bf[4][2];
#pragma unroll
            for (int mt = 0; mt < 4; mt++) {
                const int r0 = wm + mt * 16 + qrow;
                af[mt][0] = As[r0][kb + qcol];
                af[mt][1] = As[r0 + 8][kb + qcol];
                af[mt][2] = As[r0][kb + qcol + 4];
                af[mt][3] = As[r0 + 8][kb + qcol + 4];
            }
#pragma unroll
            for (int nt = 0; nt < 4; nt++) {
                const int c0 = wn + nt * 8 + qrow;
                bf[nt][0] = Ws[c0][kb + qcol];
                bf[nt][1] = Ws[c0][kb + qcol + 4];
            }
#pragma unroll
            for (int mt = 0; mt < 4; mt++)
#pragma unroll
                for (int nt = 0; nt < 4; nt++) {
                    asm volatile(
                        "mma.sync.aligned.m16n8k8.row.col.f32.tf32.tf32.f32 "
                        "{%0,%1,%2,%3}, {%4,%5,%6,%7}, {%8,%9}, {%0,%1,%2,%3};"
                        : "+f"(acc[mt][nt][0]), "+f"(acc[mt][nt][1]),
                          "+f"(acc[mt][nt][2]), "+f"(acc[mt][nt][3])
                        : "r"(af[mt][0]), "r"(af[mt][1]),
                          "r"(af[mt][2]), "r"(af[mt][3]),
                          "r"(bf[nt][0]), "r"(bf[nt][1]));
                }
        }
        __syncthreads();
    }

    // ---- epilogue: bias (+ SiLU), float2 stores ----
#pragma unroll
    for (int mt = 0; mt < 4; mt++) {
        const int row = bm + wm + mt * 16 + qrow;
#pragma unroll
        for (int nt = 0; nt < 4; nt++) {
            const int col = bn + wn + nt * 8 + qcol * 2;
            const float b0 = bias[col];
            const float b1 = bias[col + 1];
            float v0 = acc[mt][nt][0] + b0;
            float v1 = acc[mt][nt][1] + b1;
            float v2 = acc[mt][nt][2] + b0;
            float v3 = acc[mt][nt][3] + b1;
            if (act == 1) {
                v0 = v0 / (1.f + expf(-v0));
                v1 = v1 / (1.f + expf(-v1));
                v2 = v2 / (1.f + expf(-v2));
                v3 = v3 / (1.f + expf(-v3));
            }
            float2 p0; p0.x = v0; p0.y = v1;
            float2 p1; p1.x = v2; p1.y = v3;
            *(float2*)(C + (size_t)row * N + col) = p0;
            *(float2*)(C + (size_t)(row + 8) * N + col) = p1;
        }
    }
}

// ---------------------------------------------------------------------------
// RoPE applied in place to q (S,1024) and k (S,512).
// ---------------------------------------------------------------------------
__global__ void rope_kernel(float* __restrict__ q, float* __restrict__ k)
{
    const int NQ = S * HQ * 64;
    const int NK = S * G * 64;
    int i = blockIdx.x * blockDim.x + threadIdx.x;
    if (i >= NQ + NK) return;

    float* ptr;
    int s, hd, base;
    if (i < NQ) {
        s = i / (HQ * 64);
        hd = i - s * (HQ * 64);
        const int h = hd >> 6;
        const int d = hd & 63;
        base = s * (HQ * D) + h * D + d;
        ptr = q;
        hd = d;
    } else {
        int j = i - NQ;
        s = j / (G * 64);
        int rem = j - s * (G * 64);
        const int g = rem >> 6;
        const int d = rem & 63;
        base = s * (G * D) + g * D + d;
        ptr = k;
        hd = d;
    }
    const float inv = powf(10000.f, -(float)(2 * hd) / 128.f);
    const float f = (float)s * inv;
    float sn, cs;
    sincosf(f, &sn, &cs);
    const float x1 = ptr[base];
    const float x2 = ptr[base + 64];
    ptr[base]      = x1 * cs - x2 * sn;
    ptr[base + 64] = x2 * cs + x1 * sn;
}

// ---------------------------------------------------------------------------
// Attention (fp32 SIMT, unchanged this round)
// ---------------------------------------------------------------------------
#define AR 32
#define AC 32

__global__ void __launch_bounds__(256, 4)
attn_kernel(const float* __restrict__ q, const float* __restrict__ k,
            const float* __restrict__ v, float* __restrict__ out)
{
    __shared__ float qs[AR][D + 4];
    __shared__ float kv[AC][D + 4];
    __shared__ float ps[AR][AC];

    const int h = blockIdx.y;
    const int it = blockIdx.x;
    const int row0 = it * AR;
    const int tid = threadIdx.x;
    const int row = tid >> 3;
    const int lane = tid & 7;

    for (int x = tid; x < AR * (D / 4); x += 256) {
        const int r = x >> 5;
        const int c4 = x & 31;
        *(float4*)&qs[r][c4 * 4] =
            *(const float4*)(q + (size_t)(row0 + r) * (HQ * D) + h * D + c4 * 4);
    }

    float accT[16];
#pragma unroll
    for (int i = 0; i < 16; i++) accT[i] = 0.f;

    const float scale = 0.08838834764831845f;

    for (int g = 0; g < G; g++) {
        float m = -1e30f, l = 0.f;
        float acc[16];
#pragma unroll
        for (int i = 0; i < 16; i++) acc[i] = 0.f;

        for (int jt = 0; jt <= it; jt++) {
            const int col0 = jt * AC;
            __syncthreads();

            for (int x = tid; x < AC * (D / 4); x += 256) {
                const int r = x >> 5;
                const int c4 = x & 31;
                *(float4*)&kv[r][c4 * 4] =
                    *(const float4*)(k + (size_t)(col0 + r) * (G * D) + g * D + c4 * 4);
            }
            __syncthreads();

            float sc[4] = {0.f, 0.f, 0.f, 0.f};
#pragma unroll 4
            for (int d4 = 0; d4 < D / 4; d4++) {
                const float4 qv = *(const float4*)&qs[row][d4 * 4];
#pragma unroll
                for (int c = 0; c < 4; c++) {
                    const float4 kk4 = *(const float4*)&kv[lane * 4 + c][d4 * 4];
                    sc[c] += qv.x * kk4.x + qv.y * kk4.y + qv.z * kk4.z + qv.w * kk4.w;
                }
            }
#pragma unroll
            for (int c = 0; c < 4; c++) {
                const int jc = col0 + lane * 4 + c;
                sc[c] = (jc <= row0 + row) ? sc[c] * scale : -1e30f;
            }

            float mt = fmaxf(fmaxf(sc[0], sc[1]), fmaxf(sc[2], sc[3]));
#pragma unroll
            for (int off = 4; off >= 1; off >>= 1)
                mt = fmaxf(mt, __shfl_xor_sync(0xffffffffu, mt, off));
            const float mnew = fmaxf(m, mt);
            const float corr = __expf(m - mnew);

            float p[4], psum = 0.f;
#pragma unroll
            for (int c = 0; c < 4; c++) { p[c] = __expf(sc[c] - mnew); psum += p[c]; }
#pragma unroll
            for (int off = 4; off >= 1; off >>= 1)
                psum += __shfl_xor_sync(0xffffffffu, psum, off);

            l = l * corr + psum;
            m = mnew;
#pragma unroll
            for (int i = 0; i < 16; i++) acc[i] *= corr;

#pragma unroll
            for (int c = 0; c < 4; c++) ps[row][lane * 4 + c] = p[c];

            __syncthreads();

            for (int x = tid; x < AC * (D / 4); x += 256) {
                const int r = x >> 5;
                const int c4 = x & 31;
                *(float4*)&kv[r][c4 * 4] =
                    *(const float4*)(v + (size_t)(col0 + r) * (G * D) + g * D + c4 * 4);
            }
            __syncthreads();

#pragma unroll 4
            for (int c = 0; c < AC; c++) {
                const float pv = ps[row][c];
#pragma unroll
                for (int i4 = 0; i4 < 4; i4++) {
                    const float4 vv = *(const float4*)&kv[c][lane * 16 + i4 * 4];
                    acc[i4 * 4 + 0] = fmaf(pv, vv.x, acc[i4 * 4 + 0]);
                    acc[i4 * 4 + 1] = fmaf(pv, vv.y, acc[i4 * 4 + 1]);
                    acc[i4 * 4 + 2] = fmaf(pv, vv.z, acc[i4 * 4 + 2]);
                    acc[i4 * 4 + 3] = fmaf(pv, vv.w, acc[i4 * 4 + 3]);
                }
            }
        } // jt

        const float invl = 1.f / l;
#pragma unroll
        for (int i = 0; i < 16; i++) accT[i] += acc[i] * invl;
    } // g

#pragma unroll
    for (int i4 = 0; i4 < 4; i4++) {
        float4 o;
        o.x = accT[i4 * 4 + 0]; o.y = accT[i4 * 4 + 1];
        o.z = accT[i4 * 4 + 2]; o.w = accT[i4 * 4 + 3];
        *(float4*)(out + (size_t)(row0 + row) * (HQ * D) + h * D + lane * 16 + i4 * 4) = o;
    }
}

// ---------------------------------------------------------------------------
// Launch
// ---------------------------------------------------------------------------
extern "C" void kernel_launch(void* const* d_in, const int* in_sizes, int n_in,
                              void* d_out, int out_size)
{
    const float* x  = (const float*)d_in[0];
    const float* Wq = (const float*)d_in[1];
    const float* bq = (const float*)d_in[2];
    const float* Wk = (const float*)d_in[3];
    const float* bk = (const float*)d_in[4];
    const float* Wv = (const float*)d_in[5];
    const float* bv = (const float*)d_in[6];
    const float* Wo = (const float*)d_in[7];
    const float* bo = (const float*)d_in[8];
    const float* W1 = (const float*)d_in[9];
    const float* b1 = (const float*)d_in[10];
    const float* W2 = (const float*)d_in[11];
    const float* b2 = (const float*)d_in[12];
    float* out = (float*)d_out;

    float *qp, *kp, *vp, *ap, *op, *h1p;
    cudaGetSymbolAddress((void**)&qp,  g_q);
    cudaGetSymbolAddress((void**)&kp,  g_k);
    cudaGetSymbolAddress((void**)&vp,  g_v);
    cudaGetSymbolAddress((void**)&ap,  g_attn);
    cudaGetSymbolAddress((void**)&op,  g_o);
    cudaGetSymbolAddress((void**)&h1p, g_h1);

    // QKV projections (tf32 tensor cores)
    gemm_tf32<<<dim3(HQ * D / TBN, S / TBM), 256>>>(x, Wq, bq, qp, S, HQ * D, DIM, 0);
    gemm_tf32<<<dim3(G * D / TBN,  S / TBM), 256>>>(x, Wk, bk, kp, S, G * D,  DIM, 0);
    gemm_tf32<<<dim3(G * D / TBN,  S / TBM), 256>>>(x, Wv, bv, vp, S, G * D,  DIM, 0);

    // RoPE
    {
        const int total = S * HQ * 64 + S * G * 64;
        rope_kernel<<<(total + 255) / 256, 256>>>(qp, kp);
    }

    // Attention
    attn_kernel<<<dim3(S / AR, HQ), 256>>>(qp, kp, vp, ap);

    // O projection
    gemm_tf32<<<dim3(DIM / TBN, S / TBM), 256>>>(ap, Wo, bo, op, S, DIM, HQ * D, 0);

    // FFN
    gemm_tf32<<<dim3(4 * DIM / TBN, S / TBM), 256>>>(op,  W1, b1, h1p, S, 4 * DIM, DIM,     1);
    gemm_tf32<<<dim3(KOUT * DIM / TBN, S / TBM), 256>>>(h1p, W2, b2, out, S, KOUT * DIM, 4 * DIM, 0);
}

// round 3
// speedup vs baseline: 3.5760x; 3.1704x over previous
#include <cuda_runtime.h>
#include <cuda_bf16.h>
#include <math.h>
#include <stdint.h>

// ---------------------------------------------------------------------------
// Problem constants
// ---------------------------------------------------------------------------
#define S    2048
#define DIM  1024
#define HQ   8
#define G    4
#define D    128
#define KOUT 4

// ---------------------------------------------------------------------------
// Scratch (device globals; no runtime allocation allowed)
// ---------------------------------------------------------------------------
__device__ float g_q[S * HQ * D];
__device__ float g_k[S * G * D];
__device__ float g_v[S * G * D];
__device__ float g_attn[S * HQ * D];
__device__ float g_o[S * DIM];
__device__ float g_h1[S * DIM * 4];

// ---------------------------------------------------------------------------
// TF32 tensor-core NT GEMM, double-buffered smem (TBK=16), XOR swizzle.
// C[M,N] = A[M,KK] @ W[N,KK]^T + bias (+SiLU).
// 128x128 tile, 256 threads (8 warps 2m x 4n), warp tile 64x32.
// ---------------------------------------------------------------------------
#define TBM 128
#define TBN 128
#define TBK 16

__device__ __forceinline__ uint32_t f2tf32(float v) {
    uint32_t u;
    asm("cvt.rna.tf32.f32 %0, %1;" : "=r"(u) : "f"(v));
    return u;
}

// swizzled word index within a 128x16 buffer
__device__ __forceinline__ int swz(int row, int col) {
    return row * TBK + (col ^ ((row & 3) << 2));
}

__global__ void __launch_bounds__(256)
gemm_tf32(const float* __restrict__ A, const float* __restrict__ W,
          const float* __restrict__ bias, float* __restrict__ C,
          int M, int N, int KK, int act)
{
    __shared__ uint32_t As[2][TBM * TBK];   // 2 x 8KB
    __shared__ uint32_t Ws[2][TBN * TBK];   // 2 x 8KB

    const int bm = blockIdx.y * TBM;
    const int bn = blockIdx.x * TBN;
    const int tid = threadIdx.x;
    const int wid = tid >> 5;
    const int lane = tid & 31;
    const int wm = (wid & 1) * 64;
    const int wn = (wid >> 1) * 32;
    const int qrow = lane >> 2;
    const int qcol = lane & 3;

    // loader mapping: 2 float4 per array per thread
    const int lrow = tid >> 2;            // 0..63 (+64 on 2nd)
    const int lc4 = (tid & 3) << 2;       // 0,4,8,12

    float acc[4][4][4];
#pragma unroll
    for (int mt = 0; mt < 4; mt++)
#pragma unroll
        for (int nt = 0; nt < 4; nt++)
#pragma unroll
            for (int r = 0; r < 4; r++) acc[mt][nt][r] = 0.f;

    // ---- prologue: load tile 0 into buffer 0 ----
    {
#pragma unroll
        for (int r = 0; r < 2; r++) {
            const int row = lrow + r * 64;
            float4 a4 = *(const float4*)(A + (size_t)(bm + row) * KK + lc4);
            uint4 ua = { f2tf32(a4.x), f2tf32(a4.y), f2tf32(a4.z), f2tf32(a4.w) };
            *(uint4*)&As[0][swz(row, lc4)] = ua;
            float4 w4 = *(const float4*)(W + (size_t)(bn + row) * KK + lc4);
            uint4 uw = { f2tf32(w4.x), f2tf32(w4.y), f2tf32(w4.z), f2tf32(w4.w) };
            *(uint4*)&Ws[0][swz(row, lc4)] = uw;
        }
    }
    __syncthreads();

    const int niter = KK / TBK;
    for (int it = 0; it < niter; it++) {
        const int cur = it & 1;
        const int k0n = (it + 1) * TBK;

        // stage next tile in registers
        float4 na[2], nw[2];
        if (it + 1 < niter) {
#pragma unroll
            for (int r = 0; r < 2; r++) {
                const int row = lrow + r * 64;
                na[r] = *(const float4*)(A + (size_t)(bm + row) * KK + k0n + lc4);
                nw[r] = *(const float4*)(W + (size_t)(bn + row) * KK + k0n + lc4);
            }
        }

        // compute 2 k-steps of 8
#pragma unroll
        for (int ks = 0; ks < 2; ks++) {
            const int kb = ks * 8;
            uint32_t af[4][4], bf[4][2];
#pragma unroll
            for (int mt = 0; mt < 4; mt++) {
                const int r0 = wm + mt * 16 + qrow;
                af[mt][0] = As[cur][swz(r0,     kb + qcol)];
                af[mt][1] = As[cur][swz(r0 + 8, kb + qcol)];
                af[mt][2] = As[cur][swz(r0,     kb + qcol + 4)];
                af[mt][3] = As[cur][swz(r0 + 8, kb + qcol + 4)];
            }
#pragma unroll
            for (int nt = 0; nt < 4; nt++) {
                const int c0 = wn + nt * 8 + qrow;
                bf[nt][0] = Ws[cur][swz(c0, kb + qcol)];
                bf[nt][1] = Ws[cur][swz(c0, kb + qcol + 4)];
            }
#pragma unroll
            for (int mt = 0; mt < 4; mt++)
#pragma unroll
                for (int nt = 0; nt < 4; nt++) {
                    asm volatile(
                        "mma.sync.aligned.m16n8k8.row.col.f32.tf32.tf32.f32 "
                        "{%0,%1,%2,%3}, {%4,%5,%6,%7}, {%8,%9}, {%0,%1,%2,%3};"
                        : "+f"(acc[mt][nt][0]), "+f"(acc[mt][nt][1]),
                          "+f"(acc[mt][nt][2]), "+f"(acc[mt][nt][3])
                        : "r"(af[mt][0]), "r"(af[mt][1]),
                          "r"(af[mt][2]), "r"(af[mt][3]),
                          "r"(bf[nt][0]), "r"(bf[nt][1]));
                }
        }

        // store staged tile into other buffer
        if (it + 1 < niter) {
            const int nxt = cur ^ 1;
#pragma unroll
            for (int r = 0; r < 2; r++) {
                const int row = lrow + r * 64;
                uint4 ua = { f2tf32(na[r].x), f2tf32(na[r].y),
                             f2tf32(na[r].z), f2tf32(na[r].w) };
                *(uint4*)&As[nxt][swz(row, lc4)] = ua;
                uint4 uw = { f2tf32(nw[r].x), f2tf32(nw[r].y),
                             f2tf32(nw[r].z), f2tf32(nw[r].w) };
                *(uint4*)&Ws[nxt][swz(row, lc4)] = uw;
            }
        }
        __syncthreads();
    }

    // ---- epilogue ----
#pragma unroll
    for (int mt = 0; mt < 4; mt++) {
        const int row = bm + wm + mt * 16 + qrow;
#pragma unroll
        for (int nt = 0; nt < 4; nt++) {
            const int col = bn + wn + nt * 8 + qcol * 2;
            const float b0 = bias[col];
            const float b1 = bias[col + 1];
            float v0 = acc[mt][nt][0] + b0;
            float v1 = acc[mt][nt][1] + b1;
            float v2 = acc[mt][nt][2] + b0;
            float v3 = acc[mt][nt][3] + b1;
            if (act == 1) {
                v0 = v0 / (1.f + expf(-v0));
                v1 = v1 / (1.f + expf(-v1));
                v2 = v2 / (1.f + expf(-v2));
                v3 = v3 / (1.f + expf(-v3));
            }
            float2 p0; p0.x = v0; p0.y = v1;
            float2 p1; p1.x = v2; p1.y = v3;
            *(float2*)(C + (size_t)row * N + col) = p0;
            *(float2*)(C + (size_t)(row + 8) * N + col) = p1;
        }
    }
}

// ---------------------------------------------------------------------------
// RoPE (unchanged)
// ---------------------------------------------------------------------------
__global__ void rope_kernel(float* __restrict__ q, float* __restrict__ k)
{
    const int NQ = S * HQ * 64;
    const int NK = S * G * 64;
    int i = blockIdx.x * blockDim.x + threadIdx.x;
    if (i >= NQ + NK) return;

    float* ptr;
    int s, hd, base;
    if (i < NQ) {
        s = i / (HQ * 64);
        hd = i - s * (HQ * 64);
        const int h = hd >> 6;
        const int d = hd & 63;
        base = s * (HQ * D) + h * D + d;
        ptr = q;
        hd = d;
    } else {
        int j = i - NQ;
        s = j / (G * 64);
        int rem = j - s * (G * 64);
        const int g = rem >> 6;
        const int d = rem & 63;
        base = s * (G * D) + g * D + d;
        ptr = k;
        hd = d;
    }
    const float inv = powf(10000.f, -(float)(2 * hd) / 128.f);
    const float f = (float)s * inv;
    float sn, cs;
    sincosf(f, &sn, &cs);
    const float x1 = ptr[base];
    const float x2 = ptr[base + 64];
    ptr[base]      = x1 * cs - x2 * sn;
    ptr[base + 64] = x2 * cs + x1 * sn;
}

// ---------------------------------------------------------------------------
// Attention, conflict-free mapping.
// thread: rp = tid>>4 -> rows {2rp, 2rp+1};  cp = tid&15.
// scores: cols {cp, cp+16} (2x2 register block).
// P@V:    d-chunks {cp*4..cp*4+3, cp*4+64..cp*4+67}.
// All smem reads: bank stride 4 (distinct) or broadcast.
// ---------------------------------------------------------------------------
#define AR 32
#define AC 32

__global__ void __launch_bounds__(256, 2)
attn_kernel(const float* __restrict__ q, const float* __restrict__ k,
            const float* __restrict__ v, float* __restrict__ out)
{
    __shared__ float qs[AR][D + 4];
    __shared__ float kv[AC][D + 4];
    __shared__ float ps[AR][AC + 1];

    const int h = blockIdx.y;
    const int it = blockIdx.x;
    const int row0 = it * AR;
    const int tid = threadIdx.x;
    const int rp = tid >> 4;            // 0..15
    const int cp = tid & 15;            // 0..15
    const int r0 = 2 * rp;
    const int r1 = 2 * rp + 1;

    // load q tile (32 x 128)
    for (int x = tid; x < AR * (D / 4); x += 256) {
        const int r = x >> 5;
        const int c4 = x & 31;
        *(float4*)&qs[r][c4 * 4] =
            *(const float4*)(q + (size_t)(row0 + r) * (HQ * D) + h * D + c4 * 4);
    }

    float accT[2][2][4];
#pragma unroll
    for (int i = 0; i < 2; i++)
#pragma unroll
        for (int j = 0; j < 2; j++)
#pragma unroll
            for (int r = 0; r < 4; r++) accT[i][j][r] = 0.f;

    const float scale = 0.08838834764831845f;   // 1/sqrt(128)

    for (int g = 0; g < G; g++) {
        float m[2] = {-1e30f, -1e30f};
        float l[2] = {0.f, 0.f};
        float acc[2][2][4];
#pragma unroll
        for (int i = 0; i < 2; i++)
#pragma unroll
            for (int j = 0; j < 2; j++)
#pragma unroll
                for (int r = 0; r < 4; r++) acc[i][j][r] = 0.f;

        for (int jt = 0; jt <= it; jt++) {
            const int col0 = jt * AC;
            __syncthreads();

            // load K tile
            for (int x = tid; x < AC * (D / 4); x += 256) {
                const int r = x >> 5;
                const int c4 = x & 31;
                *(float4*)&kv[r][c4 * 4] =
                    *(const float4*)(k + (size_t)(col0 + r) * (G * D) + g * D + c4 * 4);
            }
            __syncthreads();

            // scores: 2 rows x 2 cols per thread
            float sc[2][2] = {{0.f, 0.f}, {0.f, 0.f}};
#pragma unroll 4
            for (int d4 = 0; d4 < D / 4; d4++) {
                const float4 q0 = *(const float4*)&qs[r0][d4 * 4];
                const float4 q1 = *(const float4*)&qs[r1][d4 * 4];
                const float4 k0 = *(const float4*)&kv[cp][d4 * 4];
                const float4 k1 = *(const float4*)&kv[cp + 16][d4 * 4];
                sc[0][0] += q0.x*k0.x + q0.y*k0.y + q0.z*k0.z + q0.w*k0.w;
                sc[0][1] += q0.x*k1.x + q0.y*k1.y + q0.z*k1.z + q0.w*k1.w;
                sc[1][0] += q1.x*k0.x + q1.y*k0.y + q1.z*k0.z + q1.w*k0.w;
                sc[1][1] += q1.x*k1.x + q1.y*k1.y + q1.z*k1.z + q1.w*k1.w;
            }

            const int jc0 = col0 + cp;
            const int jc1 = col0 + cp + 16;
#pragma unroll
            for (int i = 0; i < 2; i++) {
                const int ri = row0 + r0 + i;
                sc[i][0] = (jc0 <= ri) ? sc[i][0] * scale : -1e30f;
                sc[i][1] = (jc1 <= ri) ? sc[i][1] * scale : -1e30f;
            }

            // softmax update per row (reduce over 16 threads sharing rp)
            float p[2][2];
#pragma unroll
            for (int i = 0; i < 2; i++) {
                float mt = fmaxf(sc[i][0], sc[i][1]);
#pragma unroll
                for (int off = 8; off >= 1; off >>= 1)
                    mt = fmaxf(mt, __shfl_xor_sync(0xffffffffu, mt, off));
                const float mnew = fmaxf(m[i], mt);
                const float corr = __expf(m[i] - mnew);
                p[i][0] = __expf(sc[i][0] - mnew);
                p[i][1] = __expf(sc[i][1] - mnew);
                float psum = p[i][0] + p[i][1];
#pragma unroll
                for (int off = 8; off >= 1; off >>= 1)
                    psum += __shfl_xor_sync(0xffffffffu, psum, off);
                l[i] = l[i] * corr + psum;
                m[i] = mnew;
#pragma unroll
                for (int j = 0; j < 2; j++)
#pragma unroll
                    for (int r = 0; r < 4; r++) acc[i][j][r] *= corr;
            }

            ps[r0][cp]      = p[0][0];
            ps[r0][cp + 16] = p[0][1];
            ps[r1][cp]      = p[1][0];
            ps[r1][cp + 16] = p[1][1];

            __syncthreads();

            // load V tile into kv
            for (int x = tid; x < AC * (D / 4); x += 256) {
                const int r = x >> 5;
                const int c4 = x & 31;
                *(float4*)&kv[r][c4 * 4] =
                    *(const float4*)(v + (size_t)(col0 + r) * (G * D) + g * D + c4 * 4);
            }
            __syncthreads();

            // O += P @ V : thread owns d = {cp*4..+3, cp*4+64..+67}
#pragma unroll 4
            for (int c = 0; c < AC; c++) {
                const float pv0 = ps[r0][c];
                const float pv1 = ps[r1][c];
                const float4 va = *(const float4*)&kv[c][cp * 4];
                const float4 vb = *(const float4*)&kv[c][cp * 4 + 64];
                acc[0][0][0] = fmaf(pv0, va.x, acc[0][0][0]);
                acc[0][0][1] = fmaf(pv0, va.y, acc[0][0][1]);
                acc[0][0][2] = fmaf(pv0, va.z, acc[0][0][2]);
                acc[0][0][3] = fmaf(pv0, va.w, acc[0][0][3]);
                acc[0][1][0] = fmaf(pv0, vb.x, acc[0][1][0]);
                acc[0][1][1] = fmaf(pv0, vb.y, acc[0][1][1]);
                acc[0][1][2] = fmaf(pv0, vb.z, acc[0][1][2]);
                acc[0][1][3] = fmaf(pv0, vb.w, acc[0][1][3]);
                acc[1][0][0] = fmaf(pv1, va.x, acc[1][0][0]);
                acc[1][0][1] = fmaf(pv1, va.y, acc[1][0][1]);
                acc[1][0][2] = fmaf(pv1, va.z, acc[1][0][2]);
                acc[1][0][3] = fmaf(pv1, va.w, acc[1][0][3]);
                acc[1][1][0] = fmaf(pv1, vb.x, acc[1][1][0]);
                acc[1][1][1] = fmaf(pv1, vb.y, acc[1][1][1]);
                acc[1][1][2] = fmaf(pv1, vb.z, acc[1][1][2]);
                acc[1][1][3] = fmaf(pv1, vb.w, acc[1][1][3]);
            }
        } // jt

#pragma unroll
        for (int i = 0; i < 2; i++) {
            const float invl = 1.f / l[i];
#pragma unroll
            for (int j = 0; j < 2; j++)
#pragma unroll
                for (int r = 0; r < 4; r++)
                    accT[i][j][r] += acc[i][j][r] * invl;
        }
    } // g

    // write out (S, H*D)
#pragma unroll
    for (int i = 0; i < 2; i++) {
        const int row = row0 + r0 + i;
#pragma unroll
        for (int j = 0; j < 2; j++) {
            float4 o;
            o.x = accT[i][j][0]; o.y = accT[i][j][1];
            o.z = accT[i][j][2]; o.w = accT[i][j][3];
            *(float4*)(out + (size_t)row * (HQ * D) + h * D + cp * 4 + j * 64) = o;
        }
    }
}

// ---------------------------------------------------------------------------
// Launch
// ---------------------------------------------------------------------------
extern "C" void kernel_launch(void* const* d_in, const int* in_sizes, int n_in,
                              void* d_out, int out_size)
{
    const float* x  = (const float*)d_in[0];
    const float* Wq = (const float*)d_in[1];
    const float* bq = (const float*)d_in[2];
    const float* Wk = (const float*)d_in[3];
    const float* bk = (const float*)d_in[4];
    const float* Wv = (const float*)d_in[5];
    const float* bv = (const float*)d_in[6];
    const float* Wo = (const float*)d_in[7];
    const float* bo = (const float*)d_in[8];
    const float* W1 = (const float*)d_in[9];
    const float* b1 = (const float*)d_in[10];
    const float* W2 = (const float*)d_in[11];
    const float* b2 = (const float*)d_in[12];
    float* out = (float*)d_out;

    float *qp, *kp, *vp, *ap, *op, *h1p;
    cudaGetSymbolAddress((void**)&qp,  g_q);
    cudaGetSymbolAddress((void**)&kp,  g_k);
    cudaGetSymbolAddress((void**)&vp,  g_v);
    cudaGetSymbolAddress((void**)&ap,  g_attn);
    cudaGetSymbolAddress((void**)&op,  g_o);
    cudaGetSymbolAddress((void**)&h1p, g_h1);

    gemm_tf32<<<dim3(HQ * D / TBN, S / TBM), 256>>>(x, Wq, bq, qp, S, HQ * D, DIM, 0);
    gemm_tf32<<<dim3(G * D / TBN,  S / TBM), 256>>>(x, Wk, bk, kp, S, G * D,  DIM, 0);
    gemm_tf32<<<dim3(G * D / TBN,  S / TBM), 256>>>(x, Wv, bv, vp, S, G * D,  DIM, 0);

    {
        const int total = S * HQ * 64 + S * G * 64;
        rope_kernel<<<(total + 255) / 256, 256>>>(qp, kp);
    }

    attn_kernel<<<dim3(S / AR, HQ), 256>>>(qp, kp, vp, ap);

    gemm_tf32<<<dim3(DIM / TBN, S / TBM), 256>>>(ap, Wo, bo, op, S, DIM, HQ * D, 0);

    gemm_tf32<<<dim3(4 * DIM / TBN, S / TBM), 256>>>(op,  W1, b1, h1p, S, 4 * DIM, DIM,     1);
    gemm_tf32<<<dim3(KOUT * DIM / TBN, S / TBM), 256>>>(h1p, W2, b2, out, S, KOUT * DIM, 4 * DIM, 0);
}

// round 4
// speedup vs baseline: 6.9545x; 1.9448x over previous
#include <cuda_runtime.h>
#include <cuda_bf16.h>
#include <math.h>
#include <stdint.h>

// ---------------------------------------------------------------------------
// Problem constants
// ---------------------------------------------------------------------------
#define S    2048
#define DIM  1024
#define HQ   8
#define G    4
#define D    128
#define KOUT 4

// ---------------------------------------------------------------------------
// Scratch
// ---------------------------------------------------------------------------
__device__ float g_q[S * HQ * D];
__device__ float g_k[S * G * D];
__device__ float g_v[S * G * D];
__device__ float g_attng[G * S * HQ * D];   // per-group attention outputs
__device__ float g_attn[S * HQ * D];
__device__ float g_o[S * DIM];
__device__ float g_h1[S * DIM * 4];

__device__ __forceinline__ uint32_t f2tf32(float v) {
    uint32_t u;
    asm("cvt.rna.tf32.f32 %0, %1;" : "=r"(u) : "f"(v));
    return u;
}

#define MMA_TF32(d, a0,a1,a2,a3, b0,b1)                                       \
    asm volatile(                                                             \
        "mma.sync.aligned.m16n8k8.row.col.f32.tf32.tf32.f32 "                 \
        "{%0,%1,%2,%3}, {%4,%5,%6,%7}, {%8,%9}, {%0,%1,%2,%3};"               \
        : "+f"((d)[0]), "+f"((d)[1]), "+f"((d)[2]), "+f"((d)[3])              \
        : "r"(a0), "r"(a1), "r"(a2), "r"(a3), "r"(b0), "r"(b1))

// ---------------------------------------------------------------------------
// TF32 tensor-core NT GEMM (unchanged from R3)
// ---------------------------------------------------------------------------
#define TBM 128
#define TBN 128
#define TBK 16

__device__ __forceinline__ int swz(int row, int col) {
    return row * TBK + (col ^ ((row & 3) << 2));
}

__global__ void __launch_bounds__(256)
gemm_tf32(const float* __restrict__ A, const float* __restrict__ W,
          const float* __restrict__ bias, float* __restrict__ C,
          int M, int N, int KK, int act)
{
    __shared__ uint32_t As[2][TBM * TBK];
    __shared__ uint32_t Ws[2][TBN * TBK];

    const int bm = blockIdx.y * TBM;
    const int bn = blockIdx.x * TBN;
    const int tid = threadIdx.x;
    const int wid = tid >> 5;
    const int lane = tid & 31;
    const int wm = (wid & 1) * 64;
    const int wn = (wid >> 1) * 32;
    const int qrow = lane >> 2;
    const int qcol = lane & 3;

    const int lrow = tid >> 2;
    const int lc4 = (tid & 3) << 2;

    float acc[4][4][4];
#pragma unroll
    for (int mt = 0; mt < 4; mt++)
#pragma unroll
        for (int nt = 0; nt < 4; nt++)
#pragma unroll
            for (int r = 0; r < 4; r++) acc[mt][nt][r] = 0.f;

#pragma unroll
    for (int r = 0; r < 2; r++) {
        const int row = lrow + r * 64;
        float4 a4 = *(const float4*)(A + (size_t)(bm + row) * KK + lc4);
        uint4 ua = { f2tf32(a4.x), f2tf32(a4.y), f2tf32(a4.z), f2tf32(a4.w) };
        *(uint4*)&As[0][swz(row, lc4)] = ua;
        float4 w4 = *(const float4*)(W + (size_t)(bn + row) * KK + lc4);
        uint4 uw = { f2tf32(w4.x), f2tf32(w4.y), f2tf32(w4.z), f2tf32(w4.w) };
        *(uint4*)&Ws[0][swz(row, lc4)] = uw;
    }
    __syncthreads();

    const int niter = KK / TBK;
    for (int it = 0; it < niter; it++) {
        const int cur = it & 1;
        const int k0n = (it + 1) * TBK;

        float4 na[2], nw[2];
        if (it + 1 < niter) {
#pragma unroll
            for (int r = 0; r < 2; r++) {
                const int row = lrow + r * 64;
                na[r] = *(const float4*)(A + (size_t)(bm + row) * KK + k0n + lc4);
                nw[r] = *(const float4*)(W + (size_t)(bn + row) * KK + k0n + lc4);
            }
        }

#pragma unroll
        for (int ks = 0; ks < 2; ks++) {
            const int kb = ks * 8;
            uint32_t af[4][4], bf[4][2];
#pragma unroll
            for (int mt = 0; mt < 4; mt++) {
                const int r0 = wm + mt * 16 + qrow;
                af[mt][0] = As[cur][swz(r0,     kb + qcol)];
                af[mt][1] = As[cur][swz(r0 + 8, kb + qcol)];
                af[mt][2] = As[cur][swz(r0,     kb + qcol + 4)];
                af[mt][3] = As[cur][swz(r0 + 8, kb + qcol + 4)];
            }
#pragma unroll
            for (int nt = 0; nt < 4; nt++) {
                const int c0 = wn + nt * 8 + qrow;
                bf[nt][0] = Ws[cur][swz(c0, kb + qcol)];
                bf[nt][1] = Ws[cur][swz(c0, kb + qcol + 4)];
            }
#pragma unroll
            for (int mt = 0; mt < 4; mt++)
#pragma unroll
                for (int nt = 0; nt < 4; nt++)
                    MMA_TF32(acc[mt][nt], af[mt][0], af[mt][1], af[mt][2], af[mt][3],
                             bf[nt][0], bf[nt][1]);
        }

        if (it + 1 < niter) {
            const int nxt = cur ^ 1;
#pragma unroll
            for (int r = 0; r < 2; r++) {
                const int row = lrow + r * 64;
                uint4 ua = { f2tf32(na[r].x), f2tf32(na[r].y),
                             f2tf32(na[r].z), f2tf32(na[r].w) };
                *(uint4*)&As[nxt][swz(row, lc4)] = ua;
                uint4 uw = { f2tf32(nw[r].x), f2tf32(nw[r].y),
                             f2tf32(nw[r].z), f2tf32(nw[r].w) };
                *(uint4*)&Ws[nxt][swz(row, lc4)] = uw;
            }
        }
        __syncthreads();
    }

#pragma unroll
    for (int mt = 0; mt < 4; mt++) {
        const int row = bm + wm + mt * 16 + qrow;
#pragma unroll
        for (int nt = 0; nt < 4; nt++) {
            const int col = bn + wn + nt * 8 + qcol * 2;
            const float b0 = bias[col];
            const float b1 = bias[col + 1];
            float v0 = acc[mt][nt][0] + b0;
            float v1 = acc[mt][nt][1] + b1;
            float v2 = acc[mt][nt][2] + b0;
            float v3 = acc[mt][nt][3] + b1;
            if (act == 1) {
                v0 = v0 / (1.f + expf(-v0));
                v1 = v1 / (1.f + expf(-v1));
                v2 = v2 / (1.f + expf(-v2));
                v3 = v3 / (1.f + expf(-v3));
            }
            float2 p0; p0.x = v0; p0.y = v1;
            float2 p1; p1.x = v2; p1.y = v3;
            *(float2*)(C + (size_t)row * N + col) = p0;
            *(float2*)(C + (size_t)(row + 8) * N + col) = p1;
        }
    }
}

// ---------------------------------------------------------------------------
// RoPE (unchanged)
// ---------------------------------------------------------------------------
__global__ void rope_kernel(float* __restrict__ q, float* __restrict__ k)
{
    const int NQ = S * HQ * 64;
    const int NK = S * G * 64;
    int i = blockIdx.x * blockDim.x + threadIdx.x;
    if (i >= NQ + NK) return;

    float* ptr;
    int s, hd, base;
    if (i < NQ) {
        s = i / (HQ * 64);
        hd = i - s * (HQ * 64);
        const int h = hd >> 6;
        const int d = hd & 63;
        base = s * (HQ * D) + h * D + d;
        ptr = q;
        hd = d;
    } else {
        int j = i - NQ;
        s = j / (G * 64);
        int rem = j - s * (G * 64);
        const int g = rem >> 6;
        const int d = rem & 63;
        base = s * (G * D) + g * D + d;
        ptr = k;
        hd = d;
    }
    const float inv = powf(10000.f, -(float)(2 * hd) / 128.f);
    const float f = (float)s * inv;
    float sn, cs;
    sincosf(f, &sn, &cs);
    const float x1 = ptr[base];
    const float x2 = ptr[base + 64];
    ptr[base]      = x1 * cs - x2 * sn;
    ptr[base + 64] = x2 * cs + x1 * sn;
}

// ---------------------------------------------------------------------------
// Tensor-core flash attention (tf32 mma).
// Block = (rowtile 128, head, group). 8 warps x 16 rows. BC = 64.
// Q kept in register fragments; its smem region is reused for P.
// Smem strides chosen for provably conflict-free fragment access:
//   K: 132 (bank 4*qrow+qcol), V: 136 (bank 8*qcol+qrow), P: 76 (12*qrow+qcol)
// ---------------------------------------------------------------------------
#define BRR 128
#define BCC 64
#define QS_ST 132
#define KS_ST 132
#define VS_ST 136
#define PS_ST 76
#define R0_WORDS (BRR * QS_ST)              // 16896 (P needs 128*76=9728, fits)
#define KS_OFF   R0_WORDS
#define VS_OFF   (KS_OFF + BCC * KS_ST)
#define ATT_SMEM_WORDS (VS_OFF + BCC * VS_ST)

__global__ void __launch_bounds__(256, 1)
attn_tc(const float* __restrict__ q, const float* __restrict__ k,
        const float* __restrict__ v, float* __restrict__ outg)
{
    extern __shared__ uint32_t sm[];
    uint32_t* R0 = sm;                 // Q staging, then P tile
    uint32_t* KS = sm + KS_OFF;
    uint32_t* VS = sm + VS_OFF;

    const int rt = (int)(gridDim.x - 1) - (int)blockIdx.x;   // heavy tiles first
    const int h  = blockIdx.y;
    const int g  = blockIdx.z;
    const int row0 = rt * BRR;
    float* out = outg + (size_t)g * (S * HQ * D);

    const int tid = threadIdx.x;
    const int wid = tid >> 5;
    const int lane = tid & 31;
    const int qrow = lane >> 2;
    const int qcol = lane & 3;
    const int wrow = wid * 16;

    // ---- Q: global -> smem (tf32) ----
    for (int idx = tid; idx < BRR * (D / 4); idx += 256) {
        const int r = idx >> 5, c4 = (idx & 31) << 2;
        float4 x = *(const float4*)(q + (size_t)(row0 + r) * (HQ * D) + h * D + c4);
        uint4 u = { f2tf32(x.x), f2tf32(x.y), f2tf32(x.z), f2tf32(x.w) };
        *(uint4*)&R0[r * QS_ST + c4] = u;
    }
    __syncthreads();

    // ---- Q fragments into registers ----
    uint32_t qf[16][4];
#pragma unroll
    for (int ks = 0; ks < 16; ks++) {
        qf[ks][0] = R0[(wrow + qrow)     * QS_ST + ks * 8 + qcol];
        qf[ks][1] = R0[(wrow + qrow + 8) * QS_ST + ks * 8 + qcol];
        qf[ks][2] = R0[(wrow + qrow)     * QS_ST + ks * 8 + qcol + 4];
        qf[ks][3] = R0[(wrow + qrow + 8) * QS_ST + ks * 8 + qcol + 4];
    }
    __syncthreads();   // R0 now free for P

    float pv[16][4];
#pragma unroll
    for (int nt = 0; nt < 16; nt++)
#pragma unroll
        for (int r = 0; r < 4; r++) pv[nt][r] = 0.f;

    float m0 = -1e30f, m1 = -1e30f, l0 = 0.f, l1 = 0.f;
    const float scale = 0.08838834764831845f;   // 1/sqrt(128)
    const int ri0 = row0 + wrow + qrow;
    const int ri1 = ri0 + 8;
    const int njt = 2 * rt + 2;

    for (int jt = 0; jt < njt; jt++) {
        const int col0 = jt * BCC;

        // ---- load K, V tiles (tf32) ----
        for (int idx = tid; idx < BCC * (D / 4); idx += 256) {
            const int j = idx >> 5, c4 = (idx & 31) << 2;
            float4 kx = *(const float4*)(k + (size_t)(col0 + j) * (G * D) + g * D + c4);
            uint4 ku = { f2tf32(kx.x), f2tf32(kx.y), f2tf32(kx.z), f2tf32(kx.w) };
            *(uint4*)&KS[j * KS_ST + c4] = ku;
            float4 vx = *(const float4*)(v + (size_t)(col0 + j) * (G * D) + g * D + c4);
            uint4 vu = { f2tf32(vx.x), f2tf32(vx.y), f2tf32(vx.z), f2tf32(vx.w) };
            *(uint4*)&VS[j * VS_ST + c4] = vu;
        }
        __syncthreads();

        // ---- scores: S = Q K^T ----
        float sc[8][4];
#pragma unroll
        for (int nt = 0; nt < 8; nt++)
#pragma unroll
            for (int r = 0; r < 4; r++) sc[nt][r] = 0.f;

#pragma unroll
        for (int ks = 0; ks < 16; ks++) {
#pragma unroll
            for (int nt = 0; nt < 8; nt++) {
                const uint32_t b0 = KS[(nt * 8 + qrow) * KS_ST + ks * 8 + qcol];
                const uint32_t b1 = KS[(nt * 8 + qrow) * KS_ST + ks * 8 + qcol + 4];
                MMA_TF32(sc[nt], qf[ks][0], qf[ks][1], qf[ks][2], qf[ks][3], b0, b1);
            }
        }

        // ---- mask + scale + row max ----
        float mt0 = -1e30f, mt1 = -1e30f;
#pragma unroll
        for (int nt = 0; nt < 8; nt++) {
            const int j0 = col0 + nt * 8 + 2 * qcol;
            sc[nt][0] = (j0     <= ri0) ? sc[nt][0] * scale : -1e30f;
            sc[nt][1] = (j0 + 1 <= ri0) ? sc[nt][1] * scale : -1e30f;
            sc[nt][2] = (j0     <= ri1) ? sc[nt][2] * scale : -1e30f;
            sc[nt][3] = (j0 + 1 <= ri1) ? sc[nt][3] * scale : -1e30f;
            mt0 = fmaxf(mt0, fmaxf(sc[nt][0], sc[nt][1]));
            mt1 = fmaxf(mt1, fmaxf(sc[nt][2], sc[nt][3]));
        }
#pragma unroll
        for (int off = 1; off <= 2; off <<= 1) {
            mt0 = fmaxf(mt0, __shfl_xor_sync(0xffffffffu, mt0, off));
            mt1 = fmaxf(mt1, __shfl_xor_sync(0xffffffffu, mt1, off));
        }
        const float mn0 = fmaxf(m0, mt0);
        const float mn1 = fmaxf(m1, mt1);
        const float cr0 = __expf(m0 - mn0);
        const float cr1 = __expf(m1 - mn1);

        // ---- exp, P store, row sum ----
        float ps0 = 0.f, ps1 = 0.f;
#pragma unroll
        for (int nt = 0; nt < 8; nt++) {
            const float p0 = __expf(sc[nt][0] - mn0);
            const float p1 = __expf(sc[nt][1] - mn0);
            const float p2 = __expf(sc[nt][2] - mn1);
            const float p3 = __expf(sc[nt][3] - mn1);
            ps0 += p0 + p1;
            ps1 += p2 + p3;
            uint2 u01; u01.x = f2tf32(p0); u01.y = f2tf32(p1);
            *(uint2*)&R0[(wrow + qrow) * PS_ST + nt * 8 + 2 * qcol] = u01;
            uint2 u23; u23.x = f2tf32(p2); u23.y = f2tf32(p3);
            *(uint2*)&R0[(wrow + qrow + 8) * PS_ST + nt * 8 + 2 * qcol] = u23;
        }
#pragma unroll
        for (int off = 1; off <= 2; off <<= 1) {
            ps0 += __shfl_xor_sync(0xffffffffu, ps0, off);
            ps1 += __shfl_xor_sync(0xffffffffu, ps1, off);
        }
        l0 = l0 * cr0 + ps0;
        l1 = l1 * cr1 + ps1;
        m0 = mn0;
        m1 = mn1;
#pragma unroll
        for (int nt = 0; nt < 16; nt++) {
            pv[nt][0] *= cr0; pv[nt][1] *= cr0;
            pv[nt][2] *= cr1; pv[nt][3] *= cr1;
        }
        __syncwarp();   // P tile is warp-private; make stores visible to own lanes

        // ---- O += P V ----
#pragma unroll
        for (int ks = 0; ks < 8; ks++) {
            const uint32_t a0 = R0[(wrow + qrow)     * PS_ST + ks * 8 + qcol];
            const uint32_t a1 = R0[(wrow + qrow + 8) * PS_ST + ks * 8 + qcol];
            const uint32_t a2 = R0[(wrow + qrow)     * PS_ST + ks * 8 + qcol + 4];
            const uint32_t a3 = R0[(wrow + qrow + 8) * PS_ST + ks * 8 + qcol + 4];
#pragma unroll
            for (int nt = 0; nt < 16; nt++) {
                const uint32_t b0 = VS[(ks * 8 + qcol)     * VS_ST + nt * 8 + qrow];
                const uint32_t b1 = VS[(ks * 8 + qcol + 4) * VS_ST + nt * 8 + qrow];
                MMA_TF32(pv[nt], a0, a1, a2, a3, b0, b1);
            }
        }
        __syncthreads();   // protect KS/VS for next iteration's loads
    }

    // ---- epilogue ----
    const float il0 = 1.f / l0;
    const float il1 = 1.f / l1;
#pragma unroll
    for (int nt = 0; nt < 16; nt++) {
        float2 o0; o0.x = pv[nt][0] * il0; o0.y = pv[nt][1] * il0;
        *(float2*)(out + (size_t)ri0 * (HQ * D) + h * D + nt * 8 + 2 * qcol) = o0;
        float2 o1; o1.x = pv[nt][2] * il1; o1.y = pv[nt][3] * il1;
        *(float2*)(out + (size_t)ri1 * (HQ * D) + h * D + nt * 8 + 2 * qcol) = o1;
    }
}

// ---------------------------------------------------------------------------
// Sum the 4 per-group attention outputs
// ---------------------------------------------------------------------------
__global__ void sum4_kernel(const float4* __restrict__ a, float4* __restrict__ o)
{
    const int N4 = S * HQ * D / 4;
    int i = blockIdx.x * 256 + threadIdx.x;
    if (i >= N4) return;
    float4 x0 = a[i];
    float4 x1 = a[i + N4];
    float4 x2 = a[i + 2 * N4];
    float4 x3 = a[i + 3 * N4];
    float4 r;
    r.x = x0.x + x1.x + x2.x + x3.x;
    r.y = x0.y + x1.y + x2.y + x3.y;
    r.z = x0.z + x1.z + x2.z + x3.z;
    r.w = x0.w + x1.w + x2.w + x3.w;
    o[i] = r;
}

// ---------------------------------------------------------------------------
// Launch
// ---------------------------------------------------------------------------
extern "C" void kernel_launch(void* const* d_in, const int* in_sizes, int n_in,
                              void* d_out, int out_size)
{
    const float* x  = (const float*)d_in[0];
    const float* Wq = (const float*)d_in[1];
    const float* bq = (const float*)d_in[2];
    const float* Wk = (const float*)d_in[3];
    const float* bk = (const float*)d_in[4];
    const float* Wv = (const float*)d_in[5];
    const float* bv = (const float*)d_in[6];
    const float* Wo = (const float*)d_in[7];
    const float* bo = (const float*)d_in[8];
    const float* W1 = (const float*)d_in[9];
    const float* b1 = (const float*)d_in[10];
    const float* W2 = (const float*)d_in[11];
    const float* b2 = (const float*)d_in[12];
    float* out = (float*)d_out;

    float *qp, *kp, *vp, *agp, *ap, *op, *h1p;
    cudaGetSymbolAddress((void**)&qp,  g_q);
    cudaGetSymbolAddress((void**)&kp,  g_k);
    cudaGetSymbolAddress((void**)&vp,  g_v);
    cudaGetSymbolAddress((void**)&agp, g_attng);
    cudaGetSymbolAddress((void**)&ap,  g_attn);
    cudaGetSymbolAddress((void**)&op,  g_o);
    cudaGetSymbolAddress((void**)&h1p, g_h1);

    static int smem_set = 0;
    if (!smem_set) {
        cudaFuncSetAttribute(attn_tc, cudaFuncAttributeMaxDynamicSharedMemorySize,
                             ATT_SMEM_WORDS * 4);
        smem_set = 1;
    }

    // QKV projections
    gemm_tf32<<<dim3(HQ * D / TBN, S / TBM), 256>>>(x, Wq, bq, qp, S, HQ * D, DIM, 0);
    gemm_tf32<<<dim3(G * D / TBN,  S / TBM), 256>>>(x, Wk, bk, kp, S, G * D,  DIM, 0);
    gemm_tf32<<<dim3(G * D / TBN,  S / TBM), 256>>>(x, Wv, bv, vp, S, G * D,  DIM, 0);

    // RoPE
    {
        const int total = S * HQ * 64 + S * G * 64;
        rope_kernel<<<(total + 255) / 256, 256>>>(qp, kp);
    }

    // Attention (tensor cores), then g-sum
    attn_tc<<<dim3(S / BRR, HQ, G), 256, ATT_SMEM_WORDS * 4>>>(qp, kp, vp, agp);
    sum4_kernel<<<(S * HQ * D / 4 + 255) / 256, 256>>>((const float4*)agp, (float4*)ap);

    // O projection
    gemm_tf32<<<dim3(DIM / TBN, S / TBM), 256>>>(ap, Wo, bo, op, S, DIM, HQ * D, 0);

    // FFN
    gemm_tf32<<<dim3(4 * DIM / TBN, S / TBM), 256>>>(op,  W1, b1, h1p, S, 4 * DIM, DIM,     1);
    gemm_tf32<<<dim3(KOUT * DIM / TBN, S / TBM), 256>>>(h1p, W2, b2, out, S, KOUT * DIM, 4 * DIM, 0);
}

// round 5
// speedup vs baseline: 10.4414x; 1.5014x over previous
#include <cuda_runtime.h>
#include <cuda_bf16.h>
#include <math.h>
#include <stdint.h>

// ---------------------------------------------------------------------------
// Problem constants
// ---------------------------------------------------------------------------
#define S    2048
#define DIM  1024
#define HQ   8
#define G    4
#define D    128
#define KOUT 4

// ---------------------------------------------------------------------------
// Scratch
// ---------------------------------------------------------------------------
__device__ float g_q[S * HQ * D];
__device__ float g_k[S * G * D];
__device__ float g_v[S * G * D];
__device__ float g_attng[G * S * HQ * D];
__device__ float g_attn[S * HQ * D];
__device__ float g_o[S * DIM];
__device__ float g_h1[S * DIM * 4];

__device__ __forceinline__ uint32_t f2tf32(float v) {
    uint32_t u;
    asm("cvt.rna.tf32.f32 %0, %1;" : "=r"(u) : "f"(v));
    return u;
}

#define MMA_TF32(d, a0,a1,a2,a3, b0,b1)                                       \
    asm volatile(                                                             \
        "mma.sync.aligned.m16n8k8.row.col.f32.tf32.tf32.f32 "                 \
        "{%0,%1,%2,%3}, {%4,%5,%6,%7}, {%8,%9}, {%0,%1,%2,%3};"               \
        : "+f"((d)[0]), "+f"((d)[1]), "+f"((d)[2]), "+f"((d)[3])              \
        : "r"(a0), "r"(a1), "r"(a2), "r"(a3), "r"(b0), "r"(b1))

__device__ __forceinline__ void cp16(uint32_t saddr, const void* g) {
    asm volatile("cp.async.ca.shared.global [%0], [%1], 16;" :: "r"(saddr), "l"(g));
}
__device__ __forceinline__ void cp_commit() {
    asm volatile("cp.async.commit_group;");
}
template<int N_>
__device__ __forceinline__ void cp_wait() {
    asm volatile("cp.async.wait_group %0;" :: "n"(N_));
}

// ---------------------------------------------------------------------------
// Pipelined TF32 NT GEMM: C[M,N] = A @ W^T + bias (+SiLU)
// 3-stage cp.async pipeline, TBK=16, block tile 128 x BN_ (BN_=128 or 256),
// 8 warps (2m x 4n), warp tile 64 x (BN_/4). fp32 in smem, cvt on frag load.
// ---------------------------------------------------------------------------
#define TBM 128
#define TBK 16

__device__ __forceinline__ int swz(int row, int col) {
    return row * TBK + (col ^ ((row & 3) << 2));
}

template<int BN_, int NT, int MINCTA>
__global__ void __launch_bounds__(256, MINCTA)
gemm_tf32_pipe(const float* __restrict__ A, const float* __restrict__ W,
               const float* __restrict__ bias, float* __restrict__ C,
               int M, int N, int KK, int act)
{
    constexpr int ASTG = TBM * TBK;     // words per A stage
    constexpr int BSTG = BN_ * TBK;     // words per B stage
    constexpr int BLD  = BN_ / 64;      // float4 B loads per thread per stage

    extern __shared__ float sm[];
    float* As = sm;                      // [3][ASTG]
    float* Ws = sm + 3 * ASTG;           // [3][BSTG]
    const uint32_t as_base = (uint32_t)__cvta_generic_to_shared(As);
    const uint32_t ws_base = (uint32_t)__cvta_generic_to_shared(Ws);

    const int bm = blockIdx.y * TBM;
    const int bn = blockIdx.x * BN_;
    const int tid = threadIdx.x;
    const int wid = tid >> 5;
    const int lane = tid & 31;
    const int wm = (wid & 1) * 64;
    const int wn = (wid >> 1) * (BN_ / 4);
    const int qrow = lane >> 2;
    const int qcol = lane & 3;

    const int lrow = tid >> 2;            // 0..63
    const int lc4 = (tid & 3) << 2;       // 0,4,8,12

    float acc[4][NT][4];
#pragma unroll
    for (int mt = 0; mt < 4; mt++)
#pragma unroll
        for (int nt = 0; nt < NT; nt++)
#pragma unroll
            for (int r = 0; r < 4; r++) acc[mt][nt][r] = 0.f;

    const int niter = KK / TBK;

    // issue one stage's loads
    auto issue = [&](int it, int stg) {
        const int k0 = it * TBK;
#pragma unroll
        for (int r = 0; r < 2; r++) {
            const int row = lrow + r * 64;
            cp16(as_base + (uint32_t)(stg * ASTG + swz(row, lc4)) * 4u,
                 A + (size_t)(bm + row) * KK + k0 + lc4);
        }
#pragma unroll
        for (int r = 0; r < BLD; r++) {
            const int row = lrow + r * 64;
            cp16(ws_base + (uint32_t)(stg * BSTG + swz(row, lc4)) * 4u,
                 W + (size_t)(bn + row) * KK + k0 + lc4);
        }
    };

    // prologue: stages 0,1
    issue(0, 0); cp_commit();
    issue(1, 1); cp_commit();
    cp_wait<1>();
    __syncthreads();

    for (int it = 0; it < niter; it++) {
        const int stg = it % 3;
        const float* as = As + stg * ASTG;
        const float* ws = Ws + stg * BSTG;

#pragma unroll
        for (int ks = 0; ks < 2; ks++) {
            const int kb = ks * 8;
            uint32_t af[4][4], bf[NT][2];
#pragma unroll
            for (int mt = 0; mt < 4; mt++) {
                const int r0 = wm + mt * 16 + qrow;
                af[mt][0] = f2tf32(as[swz(r0,     kb + qcol)]);
                af[mt][1] = f2tf32(as[swz(r0 + 8, kb + qcol)]);
                af[mt][2] = f2tf32(as[swz(r0,     kb + qcol + 4)]);
                af[mt][3] = f2tf32(as[swz(r0 + 8, kb + qcol + 4)]);
            }
#pragma unroll
            for (int nt = 0; nt < NT; nt++) {
                const int c0 = wn + nt * 8 + qrow;
                bf[nt][0] = f2tf32(ws[swz(c0, kb + qcol)]);
                bf[nt][1] = f2tf32(ws[swz(c0, kb + qcol + 4)]);
            }
#pragma unroll
            for (int mt = 0; mt < 4; mt++)
#pragma unroll
                for (int nt = 0; nt < NT; nt++)
                    MMA_TF32(acc[mt][nt], af[mt][0], af[mt][1], af[mt][2], af[mt][3],
                             bf[nt][0], bf[nt][1]);
        }

        if (it + 2 < niter) {
            issue(it + 2, (it + 2) % 3);
            cp_commit();
            cp_wait<1>();
        } else {
            cp_wait<0>();
        }
        __syncthreads();
    }

    // ---- epilogue ----
#pragma unroll
    for (int mt = 0; mt < 4; mt++) {
        const int row = bm + wm + mt * 16 + qrow;
#pragma unroll
        for (int nt = 0; nt < NT; nt++) {
            const int col = bn + wn + nt * 8 + qcol * 2;
            const float b0 = bias[col];
            const float b1 = bias[col + 1];
            float v0 = acc[mt][nt][0] + b0;
            float v1 = acc[mt][nt][1] + b1;
            float v2 = acc[mt][nt][2] + b0;
            float v3 = acc[mt][nt][3] + b1;
            if (act == 1) {
                v0 = v0 / (1.f + expf(-v0));
                v1 = v1 / (1.f + expf(-v1));
                v2 = v2 / (1.f + expf(-v2));
                v3 = v3 / (1.f + expf(-v3));
            }
            float2 p0; p0.x = v0; p0.y = v1;
            float2 p1; p1.x = v2; p1.y = v3;
            *(float2*)(C + (size_t)row * N + col) = p0;
            *(float2*)(C + (size_t)(row + 8) * N + col) = p1;
        }
    }
}

// smem sizes for the two instantiations
#define SMEM128 (3 * (TBM * TBK + 128 * TBK) * 4)
#define SMEM256 (3 * (TBM * TBK + 256 * TBK) * 4)

// ---------------------------------------------------------------------------
// RoPE (unchanged)
// ---------------------------------------------------------------------------
__global__ void rope_kernel(float* __restrict__ q, float* __restrict__ k)
{
    const int NQ = S * HQ * 64;
    const int NK = S * G * 64;
    int i = blockIdx.x * blockDim.x + threadIdx.x;
    if (i >= NQ + NK) return;

    float* ptr;
    int s, hd, base;
    if (i < NQ) {
        s = i / (HQ * 64);
        hd = i - s * (HQ * 64);
        const int h = hd >> 6;
        const int d = hd & 63;
        base = s * (HQ * D) + h * D + d;
        ptr = q;
        hd = d;
    } else {
        int j = i - NQ;
        s = j / (G * 64);
        int rem = j - s * (G * 64);
        const int g = rem >> 6;
        const int d = rem & 63;
        base = s * (G * D) + g * D + d;
        ptr = k;
        hd = d;
    }
    const float inv = powf(10000.f, -(float)(2 * hd) / 128.f);
    const float f = (float)s * inv;
    float sn, cs;
    sincosf(f, &sn, &cs);
    const float x1 = ptr[base];
    const float x2 = ptr[base + 64];
    ptr[base]      = x1 * cs - x2 * sn;
    ptr[base + 64] = x2 * cs + x1 * sn;
}

// ---------------------------------------------------------------------------
// Tensor-core flash attention (unchanged from R4)
// ---------------------------------------------------------------------------
#define BRR 128
#define BCC 64
#define QS_ST 132
#define KS_ST 132
#define VS_ST 136
#define PS_ST 76
#define R0_WORDS (BRR * QS_ST)
#define KS_OFF   R0_WORDS
#define VS_OFF   (KS_OFF + BCC * KS_ST)
#define ATT_SMEM_WORDS (VS_OFF + BCC * VS_ST)

__global__ void __launch_bounds__(256, 1)
attn_tc(const float* __restrict__ q, const float* __restrict__ k,
        const float* __restrict__ v, float* __restrict__ outg)
{
    extern __shared__ uint32_t smu[];
    uint32_t* R0 = smu;
    uint32_t* KS = smu + KS_OFF;
    uint32_t* VS = smu + VS_OFF;

    const int rt = (int)(gridDim.x - 1) - (int)blockIdx.x;
    const int h  = blockIdx.y;
    const int g  = blockIdx.z;
    const int row0 = rt * BRR;
    float* out = outg + (size_t)g * (S * HQ * D);

    const int tid = threadIdx.x;
    const int wid = tid >> 5;
    const int lane = tid & 31;
    const int qrow = lane >> 2;
    const int qcol = lane & 3;
    const int wrow = wid * 16;

    for (int idx = tid; idx < BRR * (D / 4); idx += 256) {
        const int r = idx >> 5, c4 = (idx & 31) << 2;
        float4 x = *(const float4*)(q + (size_t)(row0 + r) * (HQ * D) + h * D + c4);
        uint4 u = { f2tf32(x.x), f2tf32(x.y), f2tf32(x.z), f2tf32(x.w) };
        *(uint4*)&R0[r * QS_ST + c4] = u;
    }
    __syncthreads();

    uint32_t qf[16][4];
#pragma unroll
    for (int ks = 0; ks < 16; ks++) {
        qf[ks][0] = R0[(wrow + qrow)     * QS_ST + ks * 8 + qcol];
        qf[ks][1] = R0[(wrow + qrow + 8) * QS_ST + ks * 8 + qcol];
        qf[ks][2] = R0[(wrow + qrow)     * QS_ST + ks * 8 + qcol + 4];
        qf[ks][3] = R0[(wrow + qrow + 8) * QS_ST + ks * 8 + qcol + 4];
    }
    __syncthreads();

    float pv[16][4];
#pragma unroll
    for (int nt = 0; nt < 16; nt++)
#pragma unroll
        for (int r = 0; r < 4; r++) pv[nt][r] = 0.f;

    float m0 = -1e30f, m1 = -1e30f, l0 = 0.f, l1 = 0.f;
    const float scale = 0.08838834764831845f;
    const int ri0 = row0 + wrow + qrow;
    const int ri1 = ri0 + 8;
    const int njt = 2 * rt + 2;

    for (int jt = 0; jt < njt; jt++) {
        const int col0 = jt * BCC;

        for (int idx = tid; idx < BCC * (D / 4); idx += 256) {
            const int j = idx >> 5, c4 = (idx & 31) << 2;
            float4 kx = *(const float4*)(k + (size_t)(col0 + j) * (G * D) + g * D + c4);
            uint4 ku = { f2tf32(kx.x), f2tf32(kx.y), f2tf32(kx.z), f2tf32(kx.w) };
            *(uint4*)&KS[j * KS_ST + c4] = ku;
            float4 vx = *(const float4*)(v + (size_t)(col0 + j) * (G * D) + g * D + c4);
            uint4 vu = { f2tf32(vx.x), f2tf32(vx.y), f2tf32(vx.z), f2tf32(vx.w) };
            *(uint4*)&VS[j * VS_ST + c4] = vu;
        }
        __syncthreads();

        float sc[8][4];
#pragma unroll
        for (int nt = 0; nt < 8; nt++)
#pragma unroll
            for (int r = 0; r < 4; r++) sc[nt][r] = 0.f;

#pragma unroll
        for (int ks = 0; ks < 16; ks++) {
#pragma unroll
            for (int nt = 0; nt < 8; nt++) {
                const uint32_t b0 = KS[(nt * 8 + qrow) * KS_ST + ks * 8 + qcol];
                const uint32_t b1 = KS[(nt * 8 + qrow) * KS_ST + ks * 8 + qcol + 4];
                MMA_TF32(sc[nt], qf[ks][0], qf[ks][1], qf[ks][2], qf[ks][3], b0, b1);
            }
        }

        float mt0 = -1e30f, mt1 = -1e30f;
#pragma unroll
        for (int nt = 0; nt < 8; nt++) {
            const int j0 = col0 + nt * 8 + 2 * qcol;
            sc[nt][0] = (j0     <= ri0) ? sc[nt][0] * scale : -1e30f;
            sc[nt][1] = (j0 + 1 <= ri0) ? sc[nt][1] * scale : -1e30f;
            sc[nt][2] = (j0     <= ri1) ? sc[nt][2] * scale : -1e30f;
            sc[nt][3] = (j0 + 1 <= ri1) ? sc[nt][3] * scale : -1e30f;
            mt0 = fmaxf(mt0, fmaxf(sc[nt][0], sc[nt][1]));
            mt1 = fmaxf(mt1, fmaxf(sc[nt][2], sc[nt][3]));
        }
#pragma unroll
        for (int off = 1; off <= 2; off <<= 1) {
            mt0 = fmaxf(mt0, __shfl_xor_sync(0xffffffffu, mt0, off));
            mt1 = fmaxf(mt1, __shfl_xor_sync(0xffffffffu, mt1, off));
        }
        const float mn0 = fmaxf(m0, mt0);
        const float mn1 = fmaxf(m1, mt1);
        const float cr0 = __expf(m0 - mn0);
        const float cr1 = __expf(m1 - mn1);

        float ps0 = 0.f, ps1 = 0.f;
#pragma unroll
        for (int nt = 0; nt < 8; nt++) {
            const float p0 = __expf(sc[nt][0] - mn0);
            const float p1 = __expf(sc[nt][1] - mn0);
            const float p2 = __expf(sc[nt][2] - mn1);
            const float p3 = __expf(sc[nt][3] - mn1);
            ps0 += p0 + p1;
            ps1 += p2 + p3;
            uint2 u01; u01.x = f2tf32(p0); u01.y = f2tf32(p1);
            *(uint2*)&R0[(wrow + qrow) * PS_ST + nt * 8 + 2 * qcol] = u01;
            uint2 u23; u23.x = f2tf32(p2); u23.y = f2tf32(p3);
            *(uint2*)&R0[(wrow + qrow + 8) * PS_ST + nt * 8 + 2 * qcol] = u23;
        }
#pragma unroll
        for (int off = 1; off <= 2; off <<= 1) {
            ps0 += __shfl_xor_sync(0xffffffffu, ps0, off);
            ps1 += __shfl_xor_sync(0xffffffffu, ps1, off);
        }
        l0 = l0 * cr0 + ps0;
        l1 = l1 * cr1 + ps1;
        m0 = mn0;
        m1 = mn1;
#pragma unroll
        for (int nt = 0; nt < 16; nt++) {
            pv[nt][0] *= cr0; pv[nt][1] *= cr0;
            pv[nt][2] *= cr1; pv[nt][3] *= cr1;
        }
        __syncwarp();

#pragma unroll
        for (int ks = 0; ks < 8; ks++) {
            const uint32_t a0 = R0[(wrow + qrow)     * PS_ST + ks * 8 + qcol];
            const uint32_t a1 = R0[(wrow + qrow + 8) * PS_ST + ks * 8 + qcol];
            const uint32_t a2 = R0[(wrow + qrow)     * PS_ST + ks * 8 + qcol + 4];
            const uint32_t a3 = R0[(wrow + qrow + 8) * PS_ST + ks * 8 + qcol + 4];
#pragma unroll
            for (int nt = 0; nt < 16; nt++) {
                const uint32_t b0 = VS[(ks * 8 + qcol)     * VS_ST + nt * 8 + qrow];
                const uint32_t b1 = VS[(ks * 8 + qcol + 4) * VS_ST + nt * 8 + qrow];
                MMA_TF32(pv[nt], a0, a1, a2, a3, b0, b1);
            }
        }
        __syncthreads();
    }

    const float il0 = 1.f / l0;
    const float il1 = 1.f / l1;
#pragma unroll
    for (int nt = 0; nt < 16; nt++) {
        float2 o0; o0.x = pv[nt][0] * il0; o0.y = pv[nt][1] * il0;
        *(float2*)(out + (size_t)ri0 * (HQ * D) + h * D + nt * 8 + 2 * qcol) = o0;
        float2 o1; o1.x = pv[nt][2] * il1; o1.y = pv[nt][3] * il1;
        *(float2*)(out + (size_t)ri1 * (HQ * D) + h * D + nt * 8 + 2 * qcol) = o1;
    }
}

// ---------------------------------------------------------------------------
// Sum the 4 per-group attention outputs
// ---------------------------------------------------------------------------
__global__ void sum4_kernel(const float4* __restrict__ a, float4* __restrict__ o)
{
    const int N4 = S * HQ * D / 4;
    int i = blockIdx.x * 256 + threadIdx.x;
    if (i >= N4) return;
    float4 x0 = a[i];
    float4 x1 = a[i + N4];
    float4 x2 = a[i + 2 * N4];
    float4 x3 = a[i + 3 * N4];
    float4 r;
    r.x = x0.x + x1.x + x2.x + x3.x;
    r.y = x0.y + x1.y + x2.y + x3.y;
    r.z = x0.z + x1.z + x2.z + x3.z;
    r.w = x0.w + x1.w + x2.w + x3.w;
    o[i] = r;
}

// ---------------------------------------------------------------------------
// Launch
// ---------------------------------------------------------------------------
extern "C" void kernel_launch(void* const* d_in, const int* in_sizes, int n_in,
                              void* d_out, int out_size)
{
    const float* x  = (const float*)d_in[0];
    const float* Wq = (const float*)d_in[1];
    const float* bq = (const float*)d_in[2];
    const float* Wk = (const float*)d_in[3];
    const float* bk = (const float*)d_in[4];
    const float* Wv = (const float*)d_in[5];
    const float* bv = (const float*)d_in[6];
    const float* Wo = (const float*)d_in[7];
    const float* bo = (const float*)d_in[8];
    const float* W1 = (const float*)d_in[9];
    const float* b1 = (const float*)d_in[10];
    const float* W2 = (const float*)d_in[11];
    const float* b2 = (const float*)d_in[12];
    float* out = (float*)d_out;

    float *qp, *kp, *vp, *agp, *ap, *op, *h1p;
    cudaGetSymbolAddress((void**)&qp,  g_q);
    cudaGetSymbolAddress((void**)&kp,  g_k);
    cudaGetSymbolAddress((void**)&vp,  g_v);
    cudaGetSymbolAddress((void**)&agp, g_attng);
    cudaGetSymbolAddress((void**)&ap,  g_attn);
    cudaGetSymbolAddress((void**)&op,  g_o);
    cudaGetSymbolAddress((void**)&h1p, g_h1);

    cudaFuncSetAttribute((const void*)gemm_tf32_pipe<128, 4, 2>,
                         cudaFuncAttributeMaxDynamicSharedMemorySize, SMEM128);
    cudaFuncSetAttribute((const void*)gemm_tf32_pipe<256, 8, 1>,
                         cudaFuncAttributeMaxDynamicSharedMemorySize, SMEM256);
    cudaFuncSetAttribute(attn_tc, cudaFuncAttributeMaxDynamicSharedMemorySize,
                         ATT_SMEM_WORDS * 4);

    // QKV projections
    gemm_tf32_pipe<128, 4, 2><<<dim3(HQ * D / 128, S / TBM), 256, SMEM128>>>(
        x, Wq, bq, qp, S, HQ * D, DIM, 0);
    gemm_tf32_pipe<128, 4, 2><<<dim3(G * D / 128, S / TBM), 256, SMEM128>>>(
        x, Wk, bk, kp, S, G * D, DIM, 0);
    gemm_tf32_pipe<128, 4, 2><<<dim3(G * D / 128, S / TBM), 256, SMEM128>>>(
        x, Wv, bv, vp, S, G * D, DIM, 0);

    // RoPE
    {
        const int total = S * HQ * 64 + S * G * 64;
        rope_kernel<<<(total + 255) / 256, 256>>>(qp, kp);
    }

    // Attention (tensor cores) + g-sum
    attn_tc<<<dim3(S / BRR, HQ, G), 256, ATT_SMEM_WORDS * 4>>>(qp, kp, vp, agp);
    sum4_kernel<<<(S * HQ * D / 4 + 255) / 256, 256>>>((const float4*)agp, (float4*)ap);

    // O projection
    gemm_tf32_pipe<128, 4, 2><<<dim3(DIM / 128, S / TBM), 256, SMEM128>>>(
        ap, Wo, bo, op, S, DIM, HQ * D, 0);

    // FFN
    gemm_tf32_pipe<256, 8, 1><<<dim3(4 * DIM / 256, S / TBM), 256, SMEM256>>>(
        op, W1, b1, h1p, S, 4 * DIM, DIM, 1);
    gemm_tf32_pipe<256, 8, 1><<<dim3(KOUT * DIM / 256, S / TBM), 256, SMEM256>>>(
        h1p, W2, b2, out, S, KOUT * DIM, 4 * DIM, 0);
}

// round 7
// speedup vs baseline: 11.6084x; 1.1118x over previous
#include <cuda_runtime.h>
#include <cuda_bf16.h>
#include <math.h>
#include <stdint.h>

// ---------------------------------------------------------------------------
// Problem constants
// ---------------------------------------------------------------------------
#define S    2048
#define DIM  1024
#define HQ   8
#define G    4
#define D    128
#define KOUT 4

// ---------------------------------------------------------------------------
// Scratch
// ---------------------------------------------------------------------------
__device__ float g_qkv[S * 2048];          // fused q(1024) | k(512) | v(512)
__device__ float g_attng[G * S * HQ * D];
__device__ float g_attn[S * HQ * D];
__device__ float g_o[S * DIM];
__device__ float g_h1[S * DIM * 4];
// tf32-RNA-rounded inputs/weights
__device__ float g_x  [S * DIM];
__device__ float g_wqkv[2048 * DIM];       // rounded Wq|Wk|Wv rows
__device__ float g_bqkv[2048];
__device__ float g_wo[DIM * HQ * D];
__device__ float g_w1[4 * DIM * DIM];
__device__ float g_w2[KOUT * DIM * 4 * DIM];

__device__ __forceinline__ uint32_t f2tf32(float v) {
    uint32_t u;
    asm("cvt.rna.tf32.f32 %0, %1;" : "=r"(u) : "f"(v));
    return u;
}
__device__ __forceinline__ float rndf(float v) { return __uint_as_float(f2tf32(v)); }

#define MMA_TF32(d, a0,a1,a2,a3, b0,b1)                                       \
    asm volatile(                                                             \
        "mma.sync.aligned.m16n8k8.row.col.f32.tf32.tf32.f32 "                 \
        "{%0,%1,%2,%3}, {%4,%5,%6,%7}, {%8,%9}, {%0,%1,%2,%3};"               \
        : "+f"((d)[0]), "+f"((d)[1]), "+f"((d)[2]), "+f"((d)[3])              \
        : "r"(a0), "r"(a1), "r"(a2), "r"(a3), "r"(b0), "r"(b1))

__device__ __forceinline__ void cp16(uint32_t saddr, const void* g) {
    asm volatile("cp.async.ca.shared.global [%0], [%1], 16;" :: "r"(saddr), "l"(g));
}
__device__ __forceinline__ void cp_commit() { asm volatile("cp.async.commit_group;"); }
template<int N_>
__device__ __forceinline__ void cp_wait() {
    asm volatile("cp.async.wait_group %0;" :: "n"(N_));
}

// ---------------------------------------------------------------------------
// Pipelined TF32 NT GEMM (operands pre-rounded; NO cvt in mainloop)
// C[M,N] = A @ W^T + bias (+SiLU) (+tf32 round on store)
// 3-stage cp.async, TBK=16, tile 128 x BN_, 8 warps (2m x 4n)
// ---------------------------------------------------------------------------
#define TBM 128
#define TBK 16

__device__ __forceinline__ int swz(int row, int col) {
    return row * TBK + (col ^ ((row & 3) << 2));
}

template<int BN_, int NT, int MINCTA>
__global__ void __launch_bounds__(256, MINCTA)
gemm_tf32_pipe(const float* __restrict__ A, const float* __restrict__ W,
               const float* __restrict__ bias, float* __restrict__ C,
               int M, int N, int KK, int act, int rnd)
{
    constexpr int ASTG = TBM * TBK;
    constexpr int BSTG = BN_ * TBK;
    constexpr int BLD  = BN_ / 64;

    extern __shared__ float sm[];
    float* As = sm;
    float* Ws = sm + 3 * ASTG;
    const uint32_t as_base = (uint32_t)__cvta_generic_to_shared(As);
    const uint32_t ws_base = (uint32_t)__cvta_generic_to_shared(Ws);

    const int bm = blockIdx.y * TBM;
    const int bn = blockIdx.x * BN_;
    const int tid = threadIdx.x;
    const int wid = tid >> 5;
    const int lane = tid & 31;
    const int wm = (wid & 1) * 64;
    const int wn = (wid >> 1) * (BN_ / 4);
    const int qrow = lane >> 2;
    const int qcol = lane & 3;

    const int lrow = tid >> 2;
    const int lc4 = (tid & 3) << 2;

    float acc[4][NT][4];
#pragma unroll
    for (int mt = 0; mt < 4; mt++)
#pragma unroll
        for (int nt = 0; nt < NT; nt++)
#pragma unroll
            for (int r = 0; r < 4; r++) acc[mt][nt][r] = 0.f;

    const int niter = KK / TBK;

    auto issue = [&](int it, int stg) {
        const int k0 = it * TBK;
#pragma unroll
        for (int r = 0; r < 2; r++) {
            const int row = lrow + r * 64;
            cp16(as_base + (uint32_t)(stg * ASTG + swz(row, lc4)) * 4u,
                 A + (size_t)(bm + row) * KK + k0 + lc4);
        }
#pragma unroll
        for (int r = 0; r < BLD; r++) {
            const int row = lrow + r * 64;
            cp16(ws_base + (uint32_t)(stg * BSTG + swz(row, lc4)) * 4u,
                 W + (size_t)(bn + row) * KK + k0 + lc4);
        }
    };

    issue(0, 0); cp_commit();
    issue(1, 1); cp_commit();
    cp_wait<1>();
    __syncthreads();

    for (int it = 0; it < niter; it++) {
        const int stg = it % 3;
        const uint32_t* as = (const uint32_t*)(As + stg * ASTG);
        const uint32_t* ws = (const uint32_t*)(Ws + stg * BSTG);

#pragma unroll
        for (int ks = 0; ks < 2; ks++) {
            const int kb = ks * 8;
            uint32_t af[4][4], bf[NT][2];
#pragma unroll
            for (int mt = 0; mt < 4; mt++) {
                const int r0 = wm + mt * 16 + qrow;
                af[mt][0] = as[swz(r0,     kb + qcol)];
                af[mt][1] = as[swz(r0 + 8, kb + qcol)];
                af[mt][2] = as[swz(r0,     kb + qcol + 4)];
                af[mt][3] = as[swz(r0 + 8, kb + qcol + 4)];
            }
#pragma unroll
            for (int nt = 0; nt < NT; nt++) {
                const int c0 = wn + nt * 8 + qrow;
                bf[nt][0] = ws[swz(c0, kb + qcol)];
                bf[nt][1] = ws[swz(c0, kb + qcol + 4)];
            }
#pragma unroll
            for (int mt = 0; mt < 4; mt++)
#pragma unroll
                for (int nt = 0; nt < NT; nt++)
                    MMA_TF32(acc[mt][nt], af[mt][0], af[mt][1], af[mt][2], af[mt][3],
                             bf[nt][0], bf[nt][1]);
        }

        if (it + 2 < niter) {
            issue(it + 2, (it + 2) % 3);
            cp_commit();
            cp_wait<1>();
        } else {
            cp_wait<0>();
        }
        __syncthreads();
    }

    // ---- epilogue ----
#pragma unroll
    for (int mt = 0; mt < 4; mt++) {
        const int row = bm + wm + mt * 16 + qrow;
#pragma unroll
        for (int nt = 0; nt < NT; nt++) {
            const int col = bn + wn + nt * 8 + qcol * 2;
            const float b0 = bias[col];
            const float b1 = bias[col + 1];
            float v0 = acc[mt][nt][0] + b0;
            float v1 = acc[mt][nt][1] + b1;
            float v2 = acc[mt][nt][2] + b0;
            float v3 = acc[mt][nt][3] + b1;
            if (act == 1) {
                v0 = v0 / (1.f + expf(-v0));
                v1 = v1 / (1.f + expf(-v1));
                v2 = v2 / (1.f + expf(-v2));
                v3 = v3 / (1.f + expf(-v3));
            }
            if (rnd) { v0 = rndf(v0); v1 = rndf(v1); v2 = rndf(v2); v3 = rndf(v3); }
            float2 p0; p0.x = v0; p0.y = v1;
            float2 p1; p1.x = v2; p1.y = v3;
            *(float2*)(C + (size_t)row * N + col) = p0;
            *(float2*)(C + (size_t)(row + 8) * N + col) = p1;
        }
    }
}

#define SMEM128 (3 * (TBM * TBK + 128 * TBK) * 4)
#define SMEM256 (3 * (TBM * TBK + 256 * TBK) * 4)

// ---------------------------------------------------------------------------
// tf32 RNA rounding pre-pass
// ---------------------------------------------------------------------------
__global__ void round4_kernel(const float4* __restrict__ src, float4* __restrict__ dst, int n4)
{
    int i = blockIdx.x * 256 + threadIdx.x;
    if (i >= n4) return;
    float4 v = src[i];
    v.x = rndf(v.x); v.y = rndf(v.y); v.z = rndf(v.z); v.w = rndf(v.w);
    dst[i] = v;
}

__global__ void concat_bias(const float* __restrict__ bq, const float* __restrict__ bk,
                            const float* __restrict__ bv, float* __restrict__ dst)
{
    int i = blockIdx.x * 256 + threadIdx.x;
    if (i < 1024) dst[i] = bq[i];
    else if (i < 1536) dst[i] = bk[i - 1024];
    else if (i < 2048) dst[i] = bv[i - 1536];
}

// ---------------------------------------------------------------------------
// RoPE in place on fused qkv buffer (row stride 2048)
// ---------------------------------------------------------------------------
__global__ void rope_kernel(float* __restrict__ qkv)
{
    const int NQ = S * HQ * 64;
    const int NK = S * G * 64;
    int i = blockIdx.x * blockDim.x + threadIdx.x;
    if (i >= NQ + NK) return;

    int s, d, base;
    if (i < NQ) {
        s = i / (HQ * 64);
        const int hd = i - s * (HQ * 64);
        const int h = hd >> 6;
        d = hd & 63;
        base = s * 2048 + h * D + d;
    } else {
        const int j = i - NQ;
        s = j / (G * 64);
        const int rem = j - s * (G * 64);
        const int g = rem >> 6;
        d = rem & 63;
        base = s * 2048 + 1024 + g * D + d;
    }
    const float inv = powf(10000.f, -(float)(2 * d) / 128.f);
    const float f = (float)s * inv;
    float sn, cs;
    sincosf(f, &sn, &cs);
    const float x1 = qkv[base];
    const float x2 = qkv[base + 64];
    qkv[base]      = x1 * cs - x2 * sn;
    qkv[base + 64] = x2 * cs + x1 * sn;
}

// ---------------------------------------------------------------------------
// Tensor-core flash attention (reads fused qkv, stride 2048)
// ---------------------------------------------------------------------------
#define BRR 128
#define BCC 64
#define QS_ST 132
#define KS_ST 132
#define VS_ST 136
#define PS_ST 76
#define R0_WORDS (BRR * QS_ST)
#define KS_OFF   R0_WORDS
#define VS_OFF   (KS_OFF + BCC * KS_ST)
#define ATT_SMEM_WORDS (VS_OFF + BCC * VS_ST)

__global__ void __launch_bounds__(256, 1)
attn_tc(const float* __restrict__ qkv, float* __restrict__ outg)
{
    extern __shared__ uint32_t smu[];
    uint32_t* R0 = smu;
    uint32_t* KS = smu + KS_OFF;
    uint32_t* VS = smu + VS_OFF;

    const int rt = (int)(gridDim.x - 1) - (int)blockIdx.x;
    const int h  = blockIdx.y;
    const int g  = blockIdx.z;
    const int row0 = rt * BRR;
    float* out = outg + (size_t)g * (S * HQ * D);

    const int tid = threadIdx.x;
    const int wid = tid >> 5;
    const int lane = tid & 31;
    const int qrow = lane >> 2;
    const int qcol = lane & 3;
    const int wrow = wid * 16;

    for (int idx = tid; idx < BRR * (D / 4); idx += 256) {
        const int r = idx >> 5, c4 = (idx & 31) << 2;
        float4 x = *(const float4*)(qkv + (size_t)(row0 + r) * 2048 + h * D + c4);
        uint4 u = { f2tf32(x.x), f2tf32(x.y), f2tf32(x.z), f2tf32(x.w) };
        *(uint4*)&R0[r * QS_ST + c4] = u;
    }
    __syncthreads();

    uint32_t qf[16][4];
#pragma unroll
    for (int ks = 0; ks < 16; ks++) {
        qf[ks][0] = R0[(wrow + qrow)     * QS_ST + ks * 8 + qcol];
        qf[ks][1] = R0[(wrow + qrow + 8) * QS_ST + ks * 8 + qcol];
        qf[ks][2] = R0[(wrow + qrow)     * QS_ST + ks * 8 + qcol + 4];
        qf[ks][3] = R0[(wrow + qrow + 8) * QS_ST + ks * 8 + qcol + 4];
    }
    __syncthreads();

    float pv[16][4];
#pragma unroll
    for (int nt = 0; nt < 16; nt++)
#pragma unroll
        for (int r = 0; r < 4; r++) pv[nt][r] = 0.f;

    float m0 = -1e30f, m1 = -1e30f, l0 = 0.f, l1 = 0.f;
    const float scale = 0.08838834764831845f;
    const int ri0 = row0 + wrow + qrow;
    const int ri1 = ri0 + 8;
    const int njt = 2 * rt + 2;

    for (int jt = 0; jt < njt; jt++) {
        const int col0 = jt * BCC;

        for (int idx = tid; idx < BCC * (D / 4); idx += 256) {
            const int j = idx >> 5, c4 = (idx & 31) << 2;
            float4 kx = *(const float4*)(qkv + (size_t)(col0 + j) * 2048 + 1024 + g * D + c4);
            uint4 ku = { f2tf32(kx.x), f2tf32(kx.y), f2tf32(kx.z), f2tf32(kx.w) };
            *(uint4*)&KS[j * KS_ST + c4] = ku;
            float4 vx = *(const float4*)(qkv + (size_t)(col0 + j) * 2048 + 1536 + g * D + c4);
            uint4 vu = { f2tf32(vx.x), f2tf32(vx.y), f2tf32(vx.z), f2tf32(vx.w) };
            *(uint4*)&VS[j * VS_ST + c4] = vu;
        }
        __syncthreads();

        float sc[8][4];
#pragma unroll
        for (int nt = 0; nt < 8; nt++)
#pragma unroll
            for (int r = 0; r < 4; r++) sc[nt][r] = 0.f;

#pragma unroll
        for (int ks = 0; ks < 16; ks++) {
#pragma unroll
            for (int nt = 0; nt < 8; nt++) {
                const uint32_t b0 = KS[(nt * 8 + qrow) * KS_ST + ks * 8 + qcol];
                const uint32_t b1 = KS[(nt * 8 + qrow) * KS_ST + ks * 8 + qcol + 4];
                MMA_TF32(sc[nt], qf[ks][0], qf[ks][1], qf[ks][2], qf[ks][3], b0, b1);
            }
        }

        float mt0 = -1e30f, mt1 = -1e30f;
#pragma unroll
        for (int nt = 0; nt < 8; nt++) {
            const int j0 = col0 + nt * 8 + 2 * qcol;
            sc[nt][0] = (j0     <= ri0) ? sc[nt][0] * scale : -1e30f;
            sc[nt][1] = (j0 + 1 <= ri0) ? sc[nt][1] * scale : -1e30f;
            sc[nt][2] = (j0     <= ri1) ? sc[nt][2] * scale : -1e30f;
            sc[nt][3] = (j0 + 1 <= ri1) ? sc[nt][3] * scale : -1e30f;
            mt0 = fmaxf(mt0, fmaxf(sc[nt][0], sc[nt][1]));
            mt1 = fmaxf(mt1, fmaxf(sc[nt][2], sc[nt][3]));
        }
#pragma unroll
        for (int off = 1; off <= 2; off <<= 1) {
            mt0 = fmaxf(mt0, __shfl_xor_sync(0xffffffffu, mt0, off));
            mt1 = fmaxf(mt1, __shfl_xor_sync(0xffffffffu, mt1, off));
        }
        const float mn0 = fmaxf(m0, mt0);
        const float mn1 = fmaxf(m1, mt1);
        const float cr0 = __expf(m0 - mn0);
        const float cr1 = __expf(m1 - mn1);

        float ps0 = 0.f, ps1 = 0.f;
#pragma unroll
        for (int nt = 0; nt < 8; nt++) {
            const float p0 = __expf(sc[nt][0] - mn0);
            const float p1 = __expf(sc[nt][1] - mn0);
            const float p2 = __expf(sc[nt][2] - mn1);
            const float p3 = __expf(sc[nt][3] - mn1);
            ps0 += p0 + p1;
            ps1 += p2 + p3;
            uint2 u01; u01.x = f2tf32(p0); u01.y = f2tf32(p1);
            *(uint2*)&R0[(wrow + qrow) * PS_ST + nt * 8 + 2 * qcol] = u01;
            uint2 u23; u23.x = f2tf32(p2); u23.y = f2tf32(p3);
            *(uint2*)&R0[(wrow + qrow + 8) * PS_ST + nt * 8 + 2 * qcol] = u23;
        }
#pragma unroll
        for (int off = 1; off <= 2; off <<= 1) {
            ps0 += __shfl_xor_sync(0xffffffffu, ps0, off);
            ps1 += __shfl_xor_sync(0xffffffffu, ps1, off);
        }
        l0 = l0 * cr0 + ps0;
        l1 = l1 * cr1 + ps1;
        m0 = mn0;
        m1 = mn1;
#pragma unroll
        for (int nt = 0; nt < 16; nt++) {
            pv[nt][0] *= cr0; pv[nt][1] *= cr0;
            pv[nt][2] *= cr1; pv[nt][3] *= cr1;
        }
        __syncwarp();

#pragma unroll
        for (int ks = 0; ks < 8; ks++) {
            const uint32_t a0 = R0[(wrow + qrow)     * PS_ST + ks * 8 + qcol];
            const uint32_t a1 = R0[(wrow + qrow + 8) * PS_ST + ks * 8 + qcol];
            const uint32_t a2 = R0[(wrow + qrow)     * PS_ST + ks * 8 + qcol + 4];
            const uint32_t a3 = R0[(wrow + qrow + 8) * PS_ST + ks * 8 + qcol + 4];
#pragma unroll
            for (int nt = 0; nt < 16; nt++) {
                const uint32_t b0 = VS[(ks * 8 + qcol)     * VS_ST + nt * 8 + qrow];
                const uint32_t b1 = VS[(ks * 8 + qcol + 4) * VS_ST + nt * 8 + qrow];
                MMA_TF32(pv[nt], a0, a1, a2, a3, b0, b1);
            }
        }
        __syncthreads();
    }

    const float il0 = 1.f / l0;
    const float il1 = 1.f / l1;
#pragma unroll
    for (int nt = 0; nt < 16; nt++) {
        float2 o0; o0.x = pv[nt][0] * il0; o0.y = pv[nt][1] * il0;
        *(float2*)(out + (size_t)ri0 * (HQ * D) + h * D + nt * 8 + 2 * qcol) = o0;
        float2 o1; o1.x = pv[nt][2] * il1; o1.y = pv[nt][3] * il1;
        *(float2*)(out + (size_t)ri1 * (HQ * D) + h * D + nt * 8 + 2 * qcol) = o1;
    }
}

// ---------------------------------------------------------------------------
// Sum per-group outputs + round to tf32 (feeds Wo GEMM)
// ---------------------------------------------------------------------------
__global__ void sum4_kernel(const float4* __restrict__ a, float4* __restrict__ o)
{
    const int N4 = S * HQ * D / 4;
    int i = blockIdx.x * 256 + threadIdx.x;
    if (i >= N4) return;
    float4 x0 = a[i];
    float4 x1 = a[i + N4];
    float4 x2 = a[i + 2 * N4];
    float4 x3 = a[i + 3 * N4];
    float4 r;
    r.x = rndf(x0.x + x1.x + x2.x + x3.x);
    r.y = rndf(x0.y + x1.y + x2.y + x3.y);
    r.z = rndf(x0.z + x1.z + x2.z + x3.z);
    r.w = rndf(x0.w + x1.w + x2.w + x3.w);
    o[i] = r;
}

// ---------------------------------------------------------------------------
// Launch
// ---------------------------------------------------------------------------
extern "C" void kernel_launch(void* const* d_in, const int* in_sizes, int n_in,
                              void* d_out, int out_size)
{
    const float* x  = (const float*)d_in[0];
    const float* Wq = (const float*)d_in[1];
    const float* bq = (const float*)d_in[2];
    const float* Wk = (const float*)d_in[3];
    const float* bk = (const float*)d_in[4];
    const float* Wv = (const float*)d_in[5];
    const float* bv = (const float*)d_in[6];
    const float* Wo = (const float*)d_in[7];
    const float* bo = (const float*)d_in[8];
    const float* W1 = (const float*)d_in[9];
    const float* b1 = (const float*)d_in[10];
    const float* W2 = (const float*)d_in[11];
    const float* b2 = (const float*)d_in[12];
    float* out = (float*)d_out;

    float *qkvp, *agp, *ap, *op, *h1p;
    float *xr, *wqkvr, *bqkvr, *wor, *w1r, *w2r;
    cudaGetSymbolAddress((void**)&qkvp, g_qkv);
    cudaGetSymbolAddress((void**)&agp, g_attng);
    cudaGetSymbolAddress((void**)&ap,  g_attn);
    cudaGetSymbolAddress((void**)&op,  g_o);
    cudaGetSymbolAddress((void**)&h1p, g_h1);
    cudaGetSymbolAddress((void**)&xr,  g_x);
    cudaGetSymbolAddress((void**)&wqkvr, g_wqkv);
    cudaGetSymbolAddress((void**)&bqkvr, g_bqkv);
    cudaGetSymbolAddress((void**)&wor, g_wo);
    cudaGetSymbolAddress((void**)&w1r, g_w1);
    cudaGetSymbolAddress((void**)&w2r, g_w2);

    cudaFuncSetAttribute((const void*)gemm_tf32_pipe<128, 4, 2>,
                         cudaFuncAttributeMaxDynamicSharedMemorySize, SMEM128);
    cudaFuncSetAttribute((const void*)gemm_tf32_pipe<256, 8, 1>,
                         cudaFuncAttributeMaxDynamicSharedMemorySize, SMEM256);
    cudaFuncSetAttribute(attn_tc, cudaFuncAttributeMaxDynamicSharedMemorySize,
                         ATT_SMEM_WORDS * 4);

    // tf32-RNA pre-rounding; Wq/Wk/Wv concatenated row-wise into wqkvr
    auto rnd_launch = [&](const float* src, float* dst, int n) {
        round4_kernel<<<(n / 4 + 255) / 256, 256>>>((const float4*)src, (float4*)dst, n / 4);
    };
    rnd_launch(x,  xr,  S * DIM);
    rnd_launch(Wq, wqkvr,                 HQ * D * DIM);
    rnd_launch(Wk, wqkvr + 1024 * DIM,    G * D * DIM);
    rnd_launch(Wv, wqkvr + 1536 * DIM,    G * D * DIM);
    rnd_launch(Wo, wor, DIM * HQ * D);
    rnd_launch(W1, w1r, 4 * DIM * DIM);
    rnd_launch(W2, w2r, KOUT * DIM * 4 * DIM);
    concat_bias<<<8, 256>>>(bq, bk, bv, bqkvr);

    // Fused QKV projection: [2048,2048] = x @ Wqkv^T
    gemm_tf32_pipe<256, 8, 1><<<dim3(2048 / 256, S / TBM), 256, SMEM256>>>(
        xr, wqkvr, bqkvr, qkvp, S, 2048, DIM, 0, 0);

    // RoPE (in place on fused buffer)
    {
        const int total = S * HQ * 64 + S * G * 64;
        rope_kernel<<<(total + 255) / 256, 256>>>(qkvp);
    }

    // Attention + g-sum (sum4 rounds for Wo)
    attn_tc<<<dim3(S / BRR, HQ, G), 256, ATT_SMEM_WORDS * 4>>>(qkvp, agp);
    sum4_kernel<<<(S * HQ * D / 4 + 255) / 256, 256>>>((const float4*)agp, (float4*)ap);

    // O projection (rounded out — feeds W1)
    gemm_tf32_pipe<128, 4, 2><<<dim3(DIM / 128, S / TBM), 256, SMEM128>>>(
        ap, wor, bo, op, S, DIM, HQ * D, 0, 1);

    // FFN: W1 (SiLU, rounded — feeds W2), W2 (raw fp32 output)
    gemm_tf32_pipe<256, 8, 1><<<dim3(4 * DIM / 256, S / TBM), 256, SMEM256>>>(
        op, w1r, b1, h1p, S, 4 * DIM, DIM, 1, 1);
    gemm_tf32_pipe<256, 8, 1><<<dim3(KOUT * DIM / 256, S / TBM), 256, SMEM256>>>(
        h1p, w2r, b2, out, S, KOUT * DIM, 4 * DIM, 0, 0);
}

// round 8
// speedup vs baseline: 19.4921x; 1.6791x over previous
#include <cuda_runtime.h>
#include <cuda_fp16.h>
#include <math.h>
#include <stdint.h>

// ---------------------------------------------------------------------------
// Problem constants
// ---------------------------------------------------------------------------
#define S    2048
#define DIM  1024
#define HQ   8
#define G    4
#define D    128
#define KOUT 4

// ---------------------------------------------------------------------------
// Scratch
// ---------------------------------------------------------------------------
__device__ float  g_qkv[S * 2048];          // fused q|k|v (fp32, feeds RoPE+attn)
__device__ float  g_attng[G * S * HQ * D];
__device__ __half h_attn[S * HQ * D];       // summed attention (fp16, feeds Wo)
__device__ __half h_o[S * DIM];             // o (fp16, feeds W1)
__device__ __half h_h1[S * DIM * 4];        // h1 (fp16, feeds W2)
__device__ __half h_x[S * DIM];
__device__ __half h_wqkv[2048 * DIM];
__device__ float  g_bqkv[2048];
__device__ __half h_wo[DIM * HQ * D];
__device__ __half h_w1[4 * DIM * DIM];
__device__ __half h_w2[KOUT * DIM * 4 * DIM];

__device__ __forceinline__ uint32_t f2tf32(float v) {
    uint32_t u;
    asm("cvt.rna.tf32.f32 %0, %1;" : "=r"(u) : "f"(v));
    return u;
}

#define MMA_TF32(d, a0,a1,a2,a3, b0,b1)                                       \
    asm volatile(                                                             \
        "mma.sync.aligned.m16n8k8.row.col.f32.tf32.tf32.f32 "                 \
        "{%0,%1,%2,%3}, {%4,%5,%6,%7}, {%8,%9}, {%0,%1,%2,%3};"               \
        : "+f"((d)[0]), "+f"((d)[1]), "+f"((d)[2]), "+f"((d)[3])              \
        : "r"(a0), "r"(a1), "r"(a2), "r"(a3), "r"(b0), "r"(b1))

#define MMA_F16(d, a0,a1,a2,a3, b0,b1)                                        \
    asm volatile(                                                             \
        "mma.sync.aligned.m16n8k16.row.col.f32.f16.f16.f32 "                  \
        "{%0,%1,%2,%3}, {%4,%5,%6,%7}, {%8,%9}, {%0,%1,%2,%3};"               \
        : "+f"((d)[0]), "+f"((d)[1]), "+f"((d)[2]), "+f"((d)[3])              \
        : "r"(a0), "r"(a1), "r"(a2), "r"(a3), "r"(b0), "r"(b1))

__device__ __forceinline__ void cp16(uint32_t saddr, const void* g) {
    asm volatile("cp.async.ca.shared.global [%0], [%1], 16;" :: "r"(saddr), "l"(g));
}
__device__ __forceinline__ void cp_commit() { asm volatile("cp.async.commit_group;"); }
template<int N_>
__device__ __forceinline__ void cp_wait() {
    asm volatile("cp.async.wait_group %0;" :: "n"(N_));
}

// ---------------------------------------------------------------------------
// Pipelined FP16 NT GEMM: C[M,N] = A @ W^T + bias (+SiLU), C fp32 or fp16.
// TBK = 64 halves, row stride 36 words (conflict-free frags), 3-stage cp.async,
// tile 128 x BN_, 8 warps (2m x 4n). mma.m16n8k16.f32.f16.f16.f32.
// ---------------------------------------------------------------------------
#define TBM 128
#define HTBK 64
#define HST 36   // 32 data words + 4 pad

template<int BN_, int NT, int MINCTA>
__global__ void __launch_bounds__(256, MINCTA)
gemm_f16_pipe(const __half* __restrict__ A, const __half* __restrict__ W,
              const float* __restrict__ bias, void* __restrict__ Cout,
              int M, int N, int KK, int act, int out_half)
{
    constexpr int ASTG = TBM * HST;      // words per A stage
    constexpr int BSTG = BN_ * HST;      // words per B stage
    constexpr int ALD  = (TBM * 8) / 256;   // 4 chunks per thread
    constexpr int BLD  = (BN_ * 8) / 256;   // 4 or 8

    extern __shared__ uint32_t sm[];
    uint32_t* As = sm;
    uint32_t* Ws = sm + 3 * ASTG;
    const uint32_t as_base = (uint32_t)__cvta_generic_to_shared(As);
    const uint32_t ws_base = (uint32_t)__cvta_generic_to_shared(Ws);

    const int bm = blockIdx.y * TBM;
    const int bn = blockIdx.x * BN_;
    const int tid = threadIdx.x;
    const int wid = tid >> 5;
    const int lane = tid & 31;
    const int wm = (wid & 1) * 64;
    const int wn = (wid >> 1) * (BN_ / 4);
    const int qrow = lane >> 2;
    const int qcol = lane & 3;

    float acc[4][NT][4];
#pragma unroll
    for (int mt = 0; mt < 4; mt++)
#pragma unroll
        for (int nt = 0; nt < NT; nt++)
#pragma unroll
            for (int r = 0; r < 4; r++) acc[mt][nt][r] = 0.f;

    const int niter = KK / HTBK;

    auto issue = [&](int it, int stg) {
        const int k0 = it * HTBK;
#pragma unroll
        for (int r = 0; r < ALD; r++) {
            const int idx = tid + r * 256;
            const int row = idx >> 3, c = idx & 7;
            cp16(as_base + (uint32_t)(stg * ASTG + row * HST + c * 4) * 4u,
                 A + (size_t)(bm + row) * KK + k0 + c * 8);
        }
#pragma unroll
        for (int r = 0; r < BLD; r++) {
            const int idx = tid + r * 256;
            const int row = idx >> 3, c = idx & 7;
            cp16(ws_base + (uint32_t)(stg * BSTG + row * HST + c * 4) * 4u,
                 W + (size_t)(bn + row) * KK + k0 + c * 8);
        }
    };

    issue(0, 0); cp_commit();
    issue(1, 1); cp_commit();
    cp_wait<1>();
    __syncthreads();

    for (int it = 0; it < niter; it++) {
        const int stg = it % 3;
        const uint32_t* as = As + stg * ASTG;
        const uint32_t* ws = Ws + stg * BSTG;

#pragma unroll
        for (int ks = 0; ks < 4; ks++) {
            const int kw = ks * 8;
            uint32_t af[4][4], bf[NT][2];
#pragma unroll
            for (int mt = 0; mt < 4; mt++) {
                const int r0 = (wm + mt * 16 + qrow) * HST + kw + qcol;
                af[mt][0] = as[r0];
                af[mt][1] = as[r0 + 8 * HST];
                af[mt][2] = as[r0 + 4];
                af[mt][3] = as[r0 + 8 * HST + 4];
            }
#pragma unroll
            for (int nt = 0; nt < NT; nt++) {
                const int c0 = (wn + nt * 8 + qrow) * HST + kw + qcol;
                bf[nt][0] = ws[c0];
                bf[nt][1] = ws[c0 + 4];
            }
#pragma unroll
            for (int mt = 0; mt < 4; mt++)
#pragma unroll
                for (int nt = 0; nt < NT; nt++)
                    MMA_F16(acc[mt][nt], af[mt][0], af[mt][1], af[mt][2], af[mt][3],
                            bf[nt][0], bf[nt][1]);
        }

        if (it + 2 < niter) {
            issue(it + 2, (it + 2) % 3);
            cp_commit();
            cp_wait<1>();
        } else {
            cp_wait<0>();
        }
        __syncthreads();
    }

    // ---- epilogue ----
    float* Cf = (float*)Cout;
    __half* Ch = (__half*)Cout;
#pragma unroll
    for (int mt = 0; mt < 4; mt++) {
        const int row = bm + wm + mt * 16 + qrow;
#pragma unroll
        for (int nt = 0; nt < NT; nt++) {
            const int col = bn + wn + nt * 8 + qcol * 2;
            const float b0 = bias[col];
            const float b1 = bias[col + 1];
            float v0 = acc[mt][nt][0] + b0;
            float v1 = acc[mt][nt][1] + b1;
            float v2 = acc[mt][nt][2] + b0;
            float v3 = acc[mt][nt][3] + b1;
            if (act == 1) {
                v0 = v0 / (1.f + expf(-v0));
                v1 = v1 / (1.f + expf(-v1));
                v2 = v2 / (1.f + expf(-v2));
                v3 = v3 / (1.f + expf(-v3));
            }
            if (out_half) {
                *(half2*)(Ch + (size_t)row * N + col)       = __floats2half2_rn(v0, v1);
                *(half2*)(Ch + (size_t)(row + 8) * N + col) = __floats2half2_rn(v2, v3);
            } else {
                float2 p0; p0.x = v0; p0.y = v1;
                float2 p1; p1.x = v2; p1.y = v3;
                *(float2*)(Cf + (size_t)row * N + col) = p0;
                *(float2*)(Cf + (size_t)(row + 8) * N + col) = p1;
            }
        }
    }
}

#define SMEMH128 (3 * (TBM * HST + 128 * HST) * 4)
#define SMEMH256 (3 * (TBM * HST + 256 * HST) * 4)

// ---------------------------------------------------------------------------
// fp32 -> fp16 conversion pre-pass
// ---------------------------------------------------------------------------
__global__ void f2h_kernel(const float4* __restrict__ src, __half* __restrict__ dst, int n4)
{
    int i = blockIdx.x * 256 + threadIdx.x;
    if (i >= n4) return;
    float4 v = src[i];
    half2 a = __floats2half2_rn(v.x, v.y);
    half2 b = __floats2half2_rn(v.z, v.w);
    uint2 u;
    u.x = *(uint32_t*)&a;
    u.y = *(uint32_t*)&b;
    *(uint2*)(dst + 4 * (size_t)i) = u;
}

__global__ void concat_bias(const float* __restrict__ bq, const float* __restrict__ bk,
                            const float* __restrict__ bv, float* __restrict__ dst)
{
    int i = blockIdx.x * 256 + threadIdx.x;
    if (i < 1024) dst[i] = bq[i];
    else if (i < 1536) dst[i] = bk[i - 1024];
    else if (i < 2048) dst[i] = bv[i - 1536];
}

// ---------------------------------------------------------------------------
// RoPE in place on fused qkv buffer (row stride 2048)
// ---------------------------------------------------------------------------
__global__ void rope_kernel(float* __restrict__ qkv)
{
    const int NQ = S * HQ * 64;
    const int NK = S * G * 64;
    int i = blockIdx.x * blockDim.x + threadIdx.x;
    if (i >= NQ + NK) return;

    int s, d, base;
    if (i < NQ) {
        s = i / (HQ * 64);
        const int hd = i - s * (HQ * 64);
        const int h = hd >> 6;
        d = hd & 63;
        base = s * 2048 + h * D + d;
    } else {
        const int j = i - NQ;
        s = j / (G * 64);
        const int rem = j - s * (G * 64);
        const int g = rem >> 6;
        d = rem & 63;
        base = s * 2048 + 1024 + g * D + d;
    }
    const float inv = powf(10000.f, -(float)(2 * d) / 128.f);
    const float f = (float)s * inv;
    float sn, cs;
    sincosf(f, &sn, &cs);
    const float x1 = qkv[base];
    const float x2 = qkv[base + 64];
    qkv[base]      = x1 * cs - x2 * sn;
    qkv[base + 64] = x2 * cs + x1 * sn;
}

// ---------------------------------------------------------------------------
// Tensor-core flash attention (tf32, unchanged from R7)
// ---------------------------------------------------------------------------
#define BRR 128
#define BCC 64
#define QS_ST 132
#define KS_ST 132
#define VS_ST 136
#define PS_ST 76
#define R0_WORDS (BRR * QS_ST)
#define KS_OFF   R0_WORDS
#define VS_OFF   (KS_OFF + BCC * KS_ST)
#define ATT_SMEM_WORDS (VS_OFF + BCC * VS_ST)

__global__ void __launch_bounds__(256, 1)
attn_tc(const float* __restrict__ qkv, float* __restrict__ outg)
{
    extern __shared__ uint32_t smu[];
    uint32_t* R0 = smu;
    uint32_t* KS = smu + KS_OFF;
    uint32_t* VS = smu + VS_OFF;

    const int rt = (int)(gridDim.x - 1) - (int)blockIdx.x;
    const int h  = blockIdx.y;
    const int g  = blockIdx.z;
    const int row0 = rt * BRR;
    float* out = outg + (size_t)g * (S * HQ * D);

    const int tid = threadIdx.x;
    const int wid = tid >> 5;
    const int lane = tid & 31;
    const int qrow = lane >> 2;
    const int qcol = lane & 3;
    const int wrow = wid * 16;

    for (int idx = tid; idx < BRR * (D / 4); idx += 256) {
        const int r = idx >> 5, c4 = (idx & 31) << 2;
        float4 x = *(const float4*)(qkv + (size_t)(row0 + r) * 2048 + h * D + c4);
        uint4 u = { f2tf32(x.x), f2tf32(x.y), f2tf32(x.z), f2tf32(x.w) };
        *(uint4*)&R0[r * QS_ST + c4] = u;
    }
    __syncthreads();

    uint32_t qf[16][4];
#pragma unroll
    for (int ks = 0; ks < 16; ks++) {
        qf[ks][0] = R0[(wrow + qrow)     * QS_ST + ks * 8 + qcol];
        qf[ks][1] = R0[(wrow + qrow + 8) * QS_ST + ks * 8 + qcol];
        qf[ks][2] = R0[(wrow + qrow)     * QS_ST + ks * 8 + qcol + 4];
        qf[ks][3] = R0[(wrow + qrow + 8) * QS_ST + ks * 8 + qcol + 4];
    }
    __syncthreads();

    float pv[16][4];
#pragma unroll
    for (int nt = 0; nt < 16; nt++)
#pragma unroll
        for (int r = 0; r < 4; r++) pv[nt][r] = 0.f;

    float m0 = -1e30f, m1 = -1e30f, l0 = 0.f, l1 = 0.f;
    const float scale = 0.08838834764831845f;
    const int ri0 = row0 + wrow + qrow;
    const int ri1 = ri0 + 8;
    const int njt = 2 * rt + 2;

    for (int jt = 0; jt < njt; jt++) {
        const int col0 = jt * BCC;

        for (int idx = tid; idx < BCC * (D / 4); idx += 256) {
            const int j = idx >> 5, c4 = (idx & 31) << 2;
            float4 kx = *(const float4*)(qkv + (size_t)(col0 + j) * 2048 + 1024 + g * D + c4);
            uint4 ku = { f2tf32(kx.x), f2tf32(kx.y), f2tf32(kx.z), f2tf32(kx.w) };
            *(uint4*)&KS[j * KS_ST + c4] = ku;
            float4 vx = *(const float4*)(qkv + (size_t)(col0 + j) * 2048 + 1536 + g * D + c4);
            uint4 vu = { f2tf32(vx.x), f2tf32(vx.y), f2tf32(vx.z), f2tf32(vx.w) };
            *(uint4*)&VS[j * VS_ST + c4] = vu;
        }
        __syncthreads();

        float sc[8][4];
#pragma unroll
        for (int nt = 0; nt < 8; nt++)
#pragma unroll
            for (int r = 0; r < 4; r++) sc[nt][r] = 0.f;

#pragma unroll
        for (int ks = 0; ks < 16; ks++) {
#pragma unroll
            for (int nt = 0; nt < 8; nt++) {
                const uint32_t b0 = KS[(nt * 8 + qrow) * KS_ST + ks * 8 + qcol];
                const uint32_t b1 = KS[(nt * 8 + qrow) * KS_ST + ks * 8 + qcol + 4];
                MMA_TF32(sc[nt], qf[ks][0], qf[ks][1], qf[ks][2], qf[ks][3], b0, b1);
            }
        }

        float mt0 = -1e30f, mt1 = -1e30f;
#pragma unroll
        for (int nt = 0; nt < 8; nt++) {
            const int j0 = col0 + nt * 8 + 2 * qcol;
            sc[nt][0] = (j0     <= ri0) ? sc[nt][0] * scale : -1e30f;
            sc[nt][1] = (j0 + 1 <= ri0) ? sc[nt][1] * scale : -1e30f;
            sc[nt][2] = (j0     <= ri1) ? sc[nt][2] * scale : -1e30f;
            sc[nt][3] = (j0 + 1 <= ri1) ? sc[nt][3] * scale : -1e30f;
            mt0 = fmaxf(mt0, fmaxf(sc[nt][0], sc[nt][1]));
            mt1 = fmaxf(mt1, fmaxf(sc[nt][2], sc[nt][3]));
        }
#pragma unroll
        for (int off = 1; off <= 2; off <<= 1) {
            mt0 = fmaxf(mt0, __shfl_xor_sync(0xffffffffu, mt0, off));
            mt1 = fmaxf(mt1, __shfl_xor_sync(0xffffffffu, mt1, off));
        }
        const float mn0 = fmaxf(m0, mt0);
        const float mn1 = fmaxf(m1, mt1);
        const float cr0 = __expf(m0 - mn0);
        const float cr1 = __expf(m1 - mn1);

        float ps0 = 0.f, ps1 = 0.f;
#pragma unroll
        for (int nt = 0; nt < 8; nt++) {
            const float p0 = __expf(sc[nt][0] - mn0);
            const float p1 = __expf(sc[nt][1] - mn0);
            const float p2 = __expf(sc[nt][2] - mn1);
            const float p3 = __expf(sc[nt][3] - mn1);
            ps0 += p0 + p1;
            ps1 += p2 + p3;
            uint2 u01; u01.x = f2tf32(p0); u01.y = f2tf32(p1);
            *(uint2*)&R0[(wrow + qrow) * PS_ST + nt * 8 + 2 * qcol] = u01;
            uint2 u23; u23.x = f2tf32(p2); u23.y = f2tf32(p3);
            *(uint2*)&R0[(wrow + qrow + 8) * PS_ST + nt * 8 + 2 * qcol] = u23;
        }
#pragma unroll
        for (int off = 1; off <= 2; off <<= 1) {
            ps0 += __shfl_xor_sync(0xffffffffu, ps0, off);
            ps1 += __shfl_xor_sync(0xffffffffu, ps1, off);
        }
        l0 = l0 * cr0 + ps0;
        l1 = l1 * cr1 + ps1;
        m0 = mn0;
        m1 = mn1;
#pragma unroll
        for (int nt = 0; nt < 16; nt++) {
            pv[nt][0] *= cr0; pv[nt][1] *= cr0;
            pv[nt][2] *= cr1; pv[nt][3] *= cr1;
        }
        __syncwarp();

#pragma unroll
        for (int ks = 0; ks < 8; ks++) {
            const uint32_t a0 = R0[(wrow + qrow)     * PS_ST + ks * 8 + qcol];
            const uint32_t a1 = R0[(wrow + qrow + 8) * PS_ST + ks * 8 + qcol];
            const uint32_t a2 = R0[(wrow + qrow)     * PS_ST + ks * 8 + qcol + 4];
            const uint32_t a3 = R0[(wrow + qrow + 8) * PS_ST + ks * 8 + qcol + 4];
#pragma unroll
            for (int nt = 0; nt < 16; nt++) {
                const uint32_t b0 = VS[(ks * 8 + qcol)     * VS_ST + nt * 8 + qrow];
                const uint32_t b1 = VS[(ks * 8 + qcol + 4) * VS_ST + nt * 8 + qrow];
                MMA_TF32(pv[nt], a0, a1, a2, a3, b0, b1);
            }
        }
        __syncthreads();
    }

    const float il0 = 1.f / l0;
    const float il1 = 1.f / l1;
#pragma unroll
    for (int nt = 0; nt < 16; nt++) {
        float2 o0; o0.x = pv[nt][0] * il0; o0.y = pv[nt][1] * il0;
        *(float2*)(out + (size_t)ri0 * (HQ * D) + h * D + nt * 8 + 2 * qcol) = o0;
        float2 o1; o1.x = pv[nt][2] * il1; o1.y = pv[nt][3] * il1;
        *(float2*)(out + (size_t)ri1 * (HQ * D) + h * D + nt * 8 + 2 * qcol) = o1;
    }
}

// ---------------------------------------------------------------------------
// Sum 4 per-group outputs -> fp16 (feeds Wo GEMM)
// ---------------------------------------------------------------------------
__global__ void sum4_kernel(const float4* __restrict__ a, __half* __restrict__ o)
{
    const int N4 = S * HQ * D / 4;
    int i = blockIdx.x * 256 + threadIdx.x;
    if (i >= N4) return;
    float4 x0 = a[i];
    float4 x1 = a[i + N4];
    float4 x2 = a[i + 2 * N4];
    float4 x3 = a[i + 3 * N4];
    half2 p0 = __floats2half2_rn(x0.x + x1.x + x2.x + x3.x,
                                 x0.y + x1.y + x2.y + x3.y);
    half2 p1 = __floats2half2_rn(x0.z + x1.z + x2.z + x3.z,
                                 x0.w + x1.w + x2.w + x3.w);
    uint2 u;
    u.x = *(uint32_t*)&p0;
    u.y = *(uint32_t*)&p1;
    *(uint2*)(o + 4 * (size_t)i) = u;
}

// ---------------------------------------------------------------------------
// Launch
// ---------------------------------------------------------------------------
extern "C" void kernel_launch(void* const* d_in, const int* in_sizes, int n_in,
                              void* d_out, int out_size)
{
    const float* x  = (const float*)d_in[0];
    const float* Wq = (const float*)d_in[1];
    const float* bq = (const float*)d_in[2];
    const float* Wk = (const float*)d_in[3];
    const float* bk = (const float*)d_in[4];
    const float* Wv = (const float*)d_in[5];
    const float* bv = (const float*)d_in[6];
    const float* Wo = (const float*)d_in[7];
    const float* bo = (const float*)d_in[8];
    const float* W1 = (const float*)d_in[9];
    const float* b1 = (const float*)d_in[10];
    const float* W2 = (const float*)d_in[11];
    const float* b2 = (const float*)d_in[12];
    float* out = (float*)d_out;

    float *qkvp, *agp, *bqkvr;
    __half *attnh, *oh, *h1h, *xh, *wqkvh, *woh, *w1h, *w2h;
    cudaGetSymbolAddress((void**)&qkvp,  g_qkv);
    cudaGetSymbolAddress((void**)&agp,   g_attng);
    cudaGetSymbolAddress((void**)&bqkvr, g_bqkv);
    cudaGetSymbolAddress((void**)&attnh, h_attn);
    cudaGetSymbolAddress((void**)&oh,    h_o);
    cudaGetSymbolAddress((void**)&h1h,   h_h1);
    cudaGetSymbolAddress((void**)&xh,    h_x);
    cudaGetSymbolAddress((void**)&wqkvh, h_wqkv);
    cudaGetSymbolAddress((void**)&woh,   h_wo);
    cudaGetSymbolAddress((void**)&w1h,   h_w1);
    cudaGetSymbolAddress((void**)&w2h,   h_w2);

    cudaFuncSetAttribute((const void*)gemm_f16_pipe<128, 4, 2>,
                         cudaFuncAttributeMaxDynamicSharedMemorySize, SMEMH128);
    cudaFuncSetAttribute((const void*)gemm_f16_pipe<256, 8, 1>,
                         cudaFuncAttributeMaxDynamicSharedMemorySize, SMEMH256);
    cudaFuncSetAttribute(attn_tc, cudaFuncAttributeMaxDynamicSharedMemorySize,
                         ATT_SMEM_WORDS * 4);

    // fp32 -> fp16 conversion of x and all weights (Wq|Wk|Wv concatenated)
    auto cvt = [&](const float* src, __half* dst, int n) {
        f2h_kernel<<<(n / 4 + 255) / 256, 256>>>((const float4*)src, dst, n / 4);
    };
    cvt(x,  xh,  S * DIM);
    cvt(Wq, wqkvh,              HQ * D * DIM);
    cvt(Wk, wqkvh + 1024 * DIM, G * D * DIM);
    cvt(Wv, wqkvh + 1536 * DIM, G * D * DIM);
    cvt(Wo, woh, DIM * HQ * D);
    cvt(W1, w1h, 4 * DIM * DIM);
    cvt(W2, w2h, KOUT * DIM * 4 * DIM);
    concat_bias<<<8, 256>>>(bq, bk, bv, bqkvr);

    // Fused QKV projection -> fp32 qkv
    gemm_f16_pipe<256, 8, 1><<<dim3(2048 / 256, S / TBM), 256, SMEMH256>>>(
        xh, wqkvh, bqkvr, qkvp, S, 2048, DIM, 0, 0);

    // RoPE (in place)
    {
        const int total = S * HQ * 64 + S * G * 64;
        rope_kernel<<<(total + 255) / 256, 256>>>(qkvp);
    }

    // Attention + g-sum (fp16 out)
    attn_tc<<<dim3(S / BRR, HQ, G), 256, ATT_SMEM_WORDS * 4>>>(qkvp, agp);
    sum4_kernel<<<(S * HQ * D / 4 + 255) / 256, 256>>>((const float4*)agp, attnh);

    // O projection -> fp16 o
    gemm_f16_pipe<128, 4, 2><<<dim3(DIM / 128, S / TBM), 256, SMEMH128>>>(
        attnh, woh, bo, oh, S, DIM, HQ * D, 0, 1);

    // FFN: W1 (SiLU, fp16 out) ; W2 (fp32 final out)
    gemm_f16_pipe<256, 8, 1><<<dim3(4 * DIM / 256, S / TBM), 256, SMEMH256>>>(
        oh, w1h, b1, h1h, S, 4 * DIM, DIM, 1, 1);
    gemm_f16_pipe<256, 8, 1><<<dim3(KOUT * DIM / 256, S / TBM), 256, SMEMH256>>>(
        h1h, w2h, b2, out, S, KOUT * DIM, 4 * DIM, 0, 0);
}

// round 9
// speedup vs baseline: 23.2363x; 1.1921x over previous
#include <cuda_runtime.h>
#include <cuda_fp16.h>
#include <math.h>
#include <stdint.h>

// ---------------------------------------------------------------------------
// Problem constants
// ---------------------------------------------------------------------------
#define S    2048
#define DIM  1024
#define HQ   8
#define G    4
#define D    128
#define KOUT 4

// ---------------------------------------------------------------------------
// Scratch
// ---------------------------------------------------------------------------
__device__ __half h_qkv[S * 2048];          // fused q|k|v (fp16)
__device__ float  g_attng[G * S * HQ * D];
__device__ __half h_attn[S * HQ * D];
__device__ __half h_o[S * DIM];
__device__ __half h_h1[S * DIM * 4];
__device__ __half h_x[S * DIM];
__device__ __half h_wqkv[2048 * DIM];
__device__ float  g_bqkv[2048];
__device__ __half h_wo[DIM * HQ * D];
__device__ __half h_w1[4 * DIM * DIM];
__device__ __half h_w2[KOUT * DIM * 4 * DIM];

#define MMA_F16(d, a0,a1,a2,a3, b0,b1)                                        \
    asm volatile(                                                             \
        "mma.sync.aligned.m16n8k16.row.col.f32.f16.f16.f32 "                  \
        "{%0,%1,%2,%3}, {%4,%5,%6,%7}, {%8,%9}, {%0,%1,%2,%3};"               \
        : "+f"((d)[0]), "+f"((d)[1]), "+f"((d)[2]), "+f"((d)[3])              \
        : "r"(a0), "r"(a1), "r"(a2), "r"(a3), "r"(b0), "r"(b1))

#define LDMX2T(b0, b1, addr)                                                  \
    asm volatile("ldmatrix.sync.aligned.m8n8.x2.trans.shared.b16 {%0,%1}, [%2];" \
        : "=r"(b0), "=r"(b1) : "r"(addr))

__device__ __forceinline__ void cp16(uint32_t saddr, const void* g) {
    asm volatile("cp.async.ca.shared.global [%0], [%1], 16;" :: "r"(saddr), "l"(g));
}
__device__ __forceinline__ void cp_commit() { asm volatile("cp.async.commit_group;"); }
template<int N_>
__device__ __forceinline__ void cp_wait() {
    asm volatile("cp.async.wait_group %0;" :: "n"(N_));
}

// ---------------------------------------------------------------------------
// Pipelined FP16 NT GEMM (unchanged from R8)
// ---------------------------------------------------------------------------
#define TBM 128
#define HTBK 64
#define HST 36

template<int BN_, int NT, int MINCTA>
__global__ void __launch_bounds__(256, MINCTA)
gemm_f16_pipe(const __half* __restrict__ A, const __half* __restrict__ W,
              const float* __restrict__ bias, void* __restrict__ Cout,
              int M, int N, int KK, int act, int out_half)
{
    constexpr int ASTG = TBM * HST;
    constexpr int BSTG = BN_ * HST;
    constexpr int ALD  = (TBM * 8) / 256;
    constexpr int BLD  = (BN_ * 8) / 256;

    extern __shared__ uint32_t sm[];
    uint32_t* As = sm;
    uint32_t* Ws = sm + 3 * ASTG;
    const uint32_t as_base = (uint32_t)__cvta_generic_to_shared(As);
    const uint32_t ws_base = (uint32_t)__cvta_generic_to_shared(Ws);

    const int bm = blockIdx.y * TBM;
    const int bn = blockIdx.x * BN_;
    const int tid = threadIdx.x;
    const int wid = tid >> 5;
    const int lane = tid & 31;
    const int wm = (wid & 1) * 64;
    const int wn = (wid >> 1) * (BN_ / 4);
    const int qrow = lane >> 2;
    const int qcol = lane & 3;

    float acc[4][NT][4];
#pragma unroll
    for (int mt = 0; mt < 4; mt++)
#pragma unroll
        for (int nt = 0; nt < NT; nt++)
#pragma unroll
            for (int r = 0; r < 4; r++) acc[mt][nt][r] = 0.f;

    const int niter = KK / HTBK;

    auto issue = [&](int it, int stg) {
        const int k0 = it * HTBK;
#pragma unroll
        for (int r = 0; r < ALD; r++) {
            const int idx = tid + r * 256;
            const int row = idx >> 3, c = idx & 7;
            cp16(as_base + (uint32_t)(stg * ASTG + row * HST + c * 4) * 4u,
                 A + (size_t)(bm + row) * KK + k0 + c * 8);
        }
#pragma unroll
        for (int r = 0; r < BLD; r++) {
            const int idx = tid + r * 256;
            const int row = idx >> 3, c = idx & 7;
            cp16(ws_base + (uint32_t)(stg * BSTG + row * HST + c * 4) * 4u,
                 W + (size_t)(bn + row) * KK + k0 + c * 8);
        }
    };

    issue(0, 0); cp_commit();
    issue(1, 1); cp_commit();
    cp_wait<1>();
    __syncthreads();

    for (int it = 0; it < niter; it++) {
        const int stg = it % 3;
        const uint32_t* as = As + stg * ASTG;
        const uint32_t* ws = Ws + stg * BSTG;

#pragma unroll
        for (int ks = 0; ks < 4; ks++) {
            const int kw = ks * 8;
            uint32_t af[4][4], bf[NT][2];
#pragma unroll
            for (int mt = 0; mt < 4; mt++) {
                const int r0 = (wm + mt * 16 + qrow) * HST + kw + qcol;
                af[mt][0] = as[r0];
                af[mt][1] = as[r0 + 8 * HST];
                af[mt][2] = as[r0 + 4];
                af[mt][3] = as[r0 + 8 * HST + 4];
            }
#pragma unroll
            for (int nt = 0; nt < NT; nt++) {
                const int c0 = (wn + nt * 8 + qrow) * HST + kw + qcol;
                bf[nt][0] = ws[c0];
                bf[nt][1] = ws[c0 + 4];
            }
#pragma unroll
            for (int mt = 0; mt < 4; mt++)
#pragma unroll
                for (int nt = 0; nt < NT; nt++)
                    MMA_F16(acc[mt][nt], af[mt][0], af[mt][1], af[mt][2], af[mt][3],
                            bf[nt][0], bf[nt][1]);
        }

        if (it + 2 < niter) {
            issue(it + 2, (it + 2) % 3);
            cp_commit();
            cp_wait<1>();
        } else {
            cp_wait<0>();
        }
        __syncthreads();
    }

    float* Cf = (float*)Cout;
    __half* Ch = (__half*)Cout;
#pragma unroll
    for (int mt = 0; mt < 4; mt++) {
        const int row = bm + wm + mt * 16 + qrow;
#pragma unroll
        for (int nt = 0; nt < NT; nt++) {
            const int col = bn + wn + nt * 8 + qcol * 2;
            const float b0 = bias[col];
            const float b1 = bias[col + 1];
            float v0 = acc[mt][nt][0] + b0;
            float v1 = acc[mt][nt][1] + b1;
            float v2 = acc[mt][nt][2] + b0;
            float v3 = acc[mt][nt][3] + b1;
            if (act == 1) {
                v0 = v0 / (1.f + expf(-v0));
                v1 = v1 / (1.f + expf(-v1));
                v2 = v2 / (1.f + expf(-v2));
                v3 = v3 / (1.f + expf(-v3));
            }
            if (out_half) {
                *(half2*)(Ch + (size_t)row * N + col)       = __floats2half2_rn(v0, v1);
                *(half2*)(Ch + (size_t)(row + 8) * N + col) = __floats2half2_rn(v2, v3);
            } else {
                float2 p0; p0.x = v0; p0.y = v1;
                float2 p1; p1.x = v2; p1.y = v3;
                *(float2*)(Cf + (size_t)row * N + col) = p0;
                *(float2*)(Cf + (size_t)(row + 8) * N + col) = p1;
            }
        }
    }
}

#define SMEMH128 (3 * (TBM * HST + 128 * HST) * 4)
#define SMEMH256 (3 * (TBM * HST + 256 * HST) * 4)

// ---------------------------------------------------------------------------
// fp32 -> fp16 conversion pre-pass
// ---------------------------------------------------------------------------
__global__ void f2h_kernel(const float4* __restrict__ src, __half* __restrict__ dst, int n4)
{
    int i = blockIdx.x * 256 + threadIdx.x;
    if (i >= n4) return;
    float4 v = src[i];
    half2 a = __floats2half2_rn(v.x, v.y);
    half2 b = __floats2half2_rn(v.z, v.w);
    uint2 u;
    u.x = *(uint32_t*)&a;
    u.y = *(uint32_t*)&b;
    *(uint2*)(dst + 4 * (size_t)i) = u;
}

__global__ void concat_bias(const float* __restrict__ bq, const float* __restrict__ bk,
                            const float* __restrict__ bv, float* __restrict__ dst)
{
    int i = blockIdx.x * 256 + threadIdx.x;
    if (i < 1024) dst[i] = bq[i];
    else if (i < 1536) dst[i] = bk[i - 1024];
    else if (i < 2048) dst[i] = bv[i - 1536];
}

// ---------------------------------------------------------------------------
// RoPE in place on fp16 fused qkv (fp32 math)
// ---------------------------------------------------------------------------
__global__ void rope_kernel(__half* __restrict__ qkv)
{
    const int NQ = S * HQ * 64;
    const int NK = S * G * 64;
    int i = blockIdx.x * blockDim.x + threadIdx.x;
    if (i >= NQ + NK) return;

    int s, d, base;
    if (i < NQ) {
        s = i / (HQ * 64);
        const int hd = i - s * (HQ * 64);
        const int h = hd >> 6;
        d = hd & 63;
        base = s * 2048 + h * D + d;
    } else {
        const int j = i - NQ;
        s = j / (G * 64);
        const int rem = j - s * (G * 64);
        const int g = rem >> 6;
        d = rem & 63;
        base = s * 2048 + 1024 + g * D + d;
    }
    const float inv = powf(10000.f, -(float)(2 * d) / 128.f);
    const float f = (float)s * inv;
    float sn, cs;
    sincosf(f, &sn, &cs);
    const float x1 = __half2float(qkv[base]);
    const float x2 = __half2float(qkv[base + 64]);
    qkv[base]      = __float2half_rn(x1 * cs - x2 * sn);
    qkv[base + 64] = __float2half_rn(x2 * cs + x1 * sn);
}

// ---------------------------------------------------------------------------
// FP16 tensor-core flash attention.
// Block = (rowtile 128, head, group). 8 warps x 16 rows. BC = 64.
// Q,K row-major stride 136 halves (68 words == 4 mod 32: conflict-free frags).
// P stride 72 halves (36 words == 4 mod 32). V B-frags via ldmatrix.x2.trans.
// ---------------------------------------------------------------------------
#define BRR 128
#define BCC 64
#define QW 68                 // Q/K/V row stride in words (136 halves)
#define PW 36                 // P row stride in words (72 halves)
#define AKS_OFF (BRR * QW)            // 8704 words
#define AVS_OFF (AKS_OFF + BCC * QW)  // 13056 words
#define ATT_WORDS (AVS_OFF + BCC * QW)

__global__ void __launch_bounds__(256, 1)
attn_f16(const __half* __restrict__ qkv, float* __restrict__ outg)
{
    extern __shared__ uint32_t smu[];
    uint32_t* R0 = smu;                 // Q staging, then P
    uint32_t* KS = smu + AKS_OFF;
    uint32_t* VS = smu + AVS_OFF;
    const uint32_t vs_base = (uint32_t)__cvta_generic_to_shared(VS);

    const int rt = (int)(gridDim.x - 1) - (int)blockIdx.x;
    const int h  = blockIdx.y;
    const int g  = blockIdx.z;
    const int row0 = rt * BRR;
    float* out = outg + (size_t)g * (S * HQ * D);

    const int tid = threadIdx.x;
    const int wid = tid >> 5;
    const int lane = tid & 31;
    const int qrow = lane >> 2;
    const int qcol = lane & 3;
    const int wrow = wid * 16;

    // ---- Q: global -> smem (128 rows x 128 halves) ----
    for (int idx = tid; idx < BRR * 16; idx += 256) {
        const int r = idx >> 4, c = idx & 15;
        *(uint4*)&R0[r * QW + c * 4] =
            *(const uint4*)(qkv + (size_t)(row0 + r) * 2048 + h * D + c * 8);
    }
    __syncthreads();

    // ---- Q fragments (fp16 m16n8k16 A): 8 ksteps x 4 regs ----
    uint32_t qf[8][4];
#pragma unroll
    for (int ks = 0; ks < 8; ks++) {
        const int base = (wrow + qrow) * QW + ks * 8 + qcol;
        qf[ks][0] = R0[base];
        qf[ks][1] = R0[base + 8 * QW];
        qf[ks][2] = R0[base + 4];
        qf[ks][3] = R0[base + 8 * QW + 4];
    }
    __syncthreads();   // R0 free for P

    float pv[16][4];
#pragma unroll
    for (int nt = 0; nt < 16; nt++)
#pragma unroll
        for (int r = 0; r < 4; r++) pv[nt][r] = 0.f;

    float m0 = -1e30f, m1 = -1e30f, l0 = 0.f, l1 = 0.f;
    const float scale = 0.08838834764831845f;
    const int ri0 = row0 + wrow + qrow;
    const int ri1 = ri0 + 8;
    const int njt = 2 * rt + 2;

    // ldmatrix row address (lane-dependent, nt-invariant part)
    const int lm_row = (lane & 7) + ((lane >> 3) & 1) * 8;

    for (int jt = 0; jt < njt; jt++) {
        const int col0 = jt * BCC;

        // ---- K, V tiles: 64 rows x 128 halves each ----
        for (int idx = tid; idx < BCC * 16; idx += 256) {
            const int j = idx >> 4, c = idx & 15;
            *(uint4*)&KS[j * QW + c * 4] =
                *(const uint4*)(qkv + (size_t)(col0 + j) * 2048 + 1024 + g * D + c * 8);
            *(uint4*)&VS[j * QW + c * 4] =
                *(const uint4*)(qkv + (size_t)(col0 + j) * 2048 + 1536 + g * D + c * 8);
        }
        __syncthreads();

        // ---- scores: S = Q K^T (8 ksteps x 8 ntiles) ----
        float sc[8][4];
#pragma unroll
        for (int nt = 0; nt < 8; nt++)
#pragma unroll
            for (int r = 0; r < 4; r++) sc[nt][r] = 0.f;

#pragma unroll
        for (int ks = 0; ks < 8; ks++) {
#pragma unroll
            for (int nt = 0; nt < 8; nt++) {
                const int c0 = (nt * 8 + qrow) * QW + ks * 8 + qcol;
                MMA_F16(sc[nt], qf[ks][0], qf[ks][1], qf[ks][2], qf[ks][3],
                        KS[c0], KS[c0 + 4]);
            }
        }

        // ---- mask + scale + row max ----
        float mt0 = -1e30f, mt1 = -1e30f;
#pragma unroll
        for (int nt = 0; nt < 8; nt++) {
            const int j0 = col0 + nt * 8 + 2 * qcol;
            sc[nt][0] = (j0     <= ri0) ? sc[nt][0] * scale : -1e30f;
            sc[nt][1] = (j0 + 1 <= ri0) ? sc[nt][1] * scale : -1e30f;
            sc[nt][2] = (j0     <= ri1) ? sc[nt][2] * scale : -1e30f;
            sc[nt][3] = (j0 + 1 <= ri1) ? sc[nt][3] * scale : -1e30f;
            mt0 = fmaxf(mt0, fmaxf(sc[nt][0], sc[nt][1]));
            mt1 = fmaxf(mt1, fmaxf(sc[nt][2], sc[nt][3]));
        }
#pragma unroll
        for (int off = 1; off <= 2; off <<= 1) {
            mt0 = fmaxf(mt0, __shfl_xor_sync(0xffffffffu, mt0, off));
            mt1 = fmaxf(mt1, __shfl_xor_sync(0xffffffffu, mt1, off));
        }
        const float mn0 = fmaxf(m0, mt0);
        const float mn1 = fmaxf(m1, mt1);
        const float cr0 = __expf(m0 - mn0);
        const float cr1 = __expf(m1 - mn1);

        // ---- exp, P store (half2), row sum ----
        float ps0 = 0.f, ps1 = 0.f;
#pragma unroll
        for (int nt = 0; nt < 8; nt++) {
            const float p0 = __expf(sc[nt][0] - mn0);
            const float p1 = __expf(sc[nt][1] - mn0);
            const float p2 = __expf(sc[nt][2] - mn1);
            const float p3 = __expf(sc[nt][3] - mn1);
            ps0 += p0 + p1;
            ps1 += p2 + p3;
            half2 u01 = __floats2half2_rn(p0, p1);
            half2 u23 = __floats2half2_rn(p2, p3);
            R0[(wrow + qrow) * PW + nt * 4 + qcol]     = *(uint32_t*)&u01;
            R0[(wrow + qrow + 8) * PW + nt * 4 + qcol] = *(uint32_t*)&u23;
        }
#pragma unroll
        for (int off = 1; off <= 2; off <<= 1) {
            ps0 += __shfl_xor_sync(0xffffffffu, ps0, off);
            ps1 += __shfl_xor_sync(0xffffffffu, ps1, off);
        }
        l0 = l0 * cr0 + ps0;
        l1 = l1 * cr1 + ps1;
        m0 = mn0;
        m1 = mn1;
#pragma unroll
        for (int nt = 0; nt < 16; nt++) {
            pv[nt][0] *= cr0; pv[nt][1] *= cr0;
            pv[nt][2] *= cr1; pv[nt][3] *= cr1;
        }
        __syncwarp();   // P is warp-private

        // ---- O += P V (4 ksteps of 16 j, 16 d-tiles); V frags via ldmatrix.trans
#pragma unroll
        for (int kw = 0; kw < 4; kw++) {
            const int a0i = (wrow + qrow) * PW + kw * 8 + qcol;
            const uint32_t a0 = R0[a0i];
            const uint32_t a1 = R0[a0i + 8 * PW];
            const uint32_t a2 = R0[a0i + 4];
            const uint32_t a3 = R0[a0i + 8 * PW + 4];
            const uint32_t vrow = vs_base + (uint32_t)((kw * 16 + lm_row) * QW) * 4u;
#pragma unroll
            for (int nt = 0; nt < 16; nt++) {
                uint32_t b0, b1;
                LDMX2T(b0, b1, vrow + (uint32_t)(nt * 4) * 4u);
                MMA_F16(pv[nt], a0, a1, a2, a3, b0, b1);
            }
        }
        __syncthreads();   // protect KS/VS
    }

    // ---- epilogue ----
    const float il0 = 1.f / l0;
    const float il1 = 1.f / l1;
#pragma unroll
    for (int nt = 0; nt < 16; nt++) {
        float2 o0; o0.x = pv[nt][0] * il0; o0.y = pv[nt][1] * il0;
        *(float2*)(out + (size_t)ri0 * (HQ * D) + h * D + nt * 8 + 2 * qcol) = o0;
        float2 o1; o1.x = pv[nt][2] * il1; o1.y = pv[nt][3] * il1;
        *(float2*)(out + (size_t)ri1 * (HQ * D) + h * D + nt * 8 + 2 * qcol) = o1;
    }
}

// ---------------------------------------------------------------------------
// Sum 4 per-group outputs -> fp16 (feeds Wo GEMM)
// ---------------------------------------------------------------------------
__global__ void sum4_kernel(const float4* __restrict__ a, __half* __restrict__ o)
{
    const int N4 = S * HQ * D / 4;
    int i = blockIdx.x * 256 + threadIdx.x;
    if (i >= N4) return;
    float4 x0 = a[i];
    float4 x1 = a[i + N4];
    float4 x2 = a[i + 2 * N4];
    float4 x3 = a[i + 3 * N4];
    half2 p0 = __floats2half2_rn(x0.x + x1.x + x2.x + x3.x,
                                 x0.y + x1.y + x2.y + x3.y);
    half2 p1 = __floats2half2_rn(x0.z + x1.z + x2.z + x3.z,
                                 x0.w + x1.w + x2.w + x3.w);
    uint2 u;
    u.x = *(uint32_t*)&p0;
    u.y = *(uint32_t*)&p1;
    *(uint2*)(o + 4 * (size_t)i) = u;
}

// ---------------------------------------------------------------------------
// Launch
// ---------------------------------------------------------------------------
extern "C" void kernel_launch(void* const* d_in, const int* in_sizes, int n_in,
                              void* d_out, int out_size)
{
    const float* x  = (const float*)d_in[0];
    const float* Wq = (const float*)d_in[1];
    const float* bq = (const float*)d_in[2];
    const float* Wk = (const float*)d_in[3];
    const float* bk = (const float*)d_in[4];
    const float* Wv = (const float*)d_in[5];
    const float* bv = (const float*)d_in[6];
    const float* Wo = (const float*)d_in[7];
    const float* bo = (const float*)d_in[8];
    const float* W1 = (const float*)d_in[9];
    const float* b1 = (const float*)d_in[10];
    const float* W2 = (const float*)d_in[11];
    const float* b2 = (const float*)d_in[12];
    float* out = (float*)d_out;

    float *agp, *bqkvr;
    __half *qkvh, *attnh, *oh, *h1h, *xh, *wqkvh, *woh, *w1h, *w2h;
    cudaGetSymbolAddress((void**)&qkvh,  h_qkv);
    cudaGetSymbolAddress((void**)&agp,   g_attng);
    cudaGetSymbolAddress((void**)&bqkvr, g_bqkv);
    cudaGetSymbolAddress((void**)&attnh, h_attn);
    cudaGetSymbolAddress((void**)&oh,    h_o);
    cudaGetSymbolAddress((void**)&h1h,   h_h1);
    cudaGetSymbolAddress((void**)&xh,    h_x);
    cudaGetSymbolAddress((void**)&wqkvh, h_wqkv);
    cudaGetSymbolAddress((void**)&woh,   h_wo);
    cudaGetSymbolAddress((void**)&w1h,   h_w1);
    cudaGetSymbolAddress((void**)&w2h,   h_w2);

    cudaFuncSetAttribute((const void*)gemm_f16_pipe<128, 4, 2>,
                         cudaFuncAttributeMaxDynamicSharedMemorySize, SMEMH128);
    cudaFuncSetAttribute((const void*)gemm_f16_pipe<256, 8, 1>,
                         cudaFuncAttributeMaxDynamicSharedMemorySize, SMEMH256);
    cudaFuncSetAttribute(attn_f16, cudaFuncAttributeMaxDynamicSharedMemorySize,
                         ATT_WORDS * 4);

    auto cvt = [&](const float* src, __half* dst, int n) {
        f2h_kernel<<<(n / 4 + 255) / 256, 256>>>((const float4*)src, dst, n / 4);
    };
    cvt(x,  xh,  S * DIM);
    cvt(Wq, wqkvh,              HQ * D * DIM);
    cvt(Wk, wqkvh + 1024 * DIM, G * D * DIM);
    cvt(Wv, wqkvh + 1536 * DIM, G * D * DIM);
    cvt(Wo, woh, DIM * HQ * D);
    cvt(W1, w1h, 4 * DIM * DIM);
    cvt(W2, w2h, KOUT * DIM * 4 * DIM);
    concat_bias<<<8, 256>>>(bq, bk, bv, bqkvr);

    // Fused QKV projection -> fp16
    gemm_f16_pipe<256, 8, 1><<<dim3(2048 / 256, S / TBM), 256, SMEMH256>>>(
        xh, wqkvh, bqkvr, qkvh, S, 2048, DIM, 0, 1);

    // RoPE (fp16 in/out, fp32 math)
    {
        const int total = S * HQ * 64 + S * G * 64;
        rope_kernel<<<(total + 255) / 256, 256>>>(qkvh);
    }

    // Attention (fp16 mma) + g-sum
    attn_f16<<<dim3(S / BRR, HQ, G), 256, ATT_WORDS * 4>>>(qkvh, agp);
    sum4_kernel<<<(S * HQ * D / 4 + 255) / 256, 256>>>((const float4*)agp, attnh);

    // O projection -> fp16
    gemm_f16_pipe<128, 4, 2><<<dim3(DIM / 128, S / TBM), 256, SMEMH128>>>(
        attnh, woh, bo, oh, S, DIM, HQ * D, 0, 1);

    // FFN
    gemm_f16_pipe<256, 8, 1><<<dim3(4 * DIM / 256, S / TBM), 256, SMEMH256>>>(
        oh, w1h, b1, h1h, S, 4 * DIM, DIM, 1, 1);
    gemm_f16_pipe<256, 8, 1><<<dim3(KOUT * DIM / 256, S / TBM), 256, SMEMH256>>>(
        h1h, w2h, b2, out, S, KOUT * DIM, 4 * DIM, 0, 0);
}

// round 10
// speedup vs baseline: 23.8596x; 1.0268x over previous
#include <cuda_runtime.h>
#include <cuda_fp16.h>
#include <math.h>
#include <stdint.h>

// ---------------------------------------------------------------------------
// Problem constants
// ---------------------------------------------------------------------------
#define S    2048
#define DIM  1024
#define HQ   8
#define G    4
#define D    128
#define KOUT 4

// ---------------------------------------------------------------------------
// Scratch
// ---------------------------------------------------------------------------
__device__ __half h_qkv[S * 2048];
__device__ __half h_attng[G * S * HQ * D];
__device__ __half h_attn[S * HQ * D];
__device__ __half h_o[S * DIM];
__device__ __half h_h1[S * DIM * 4];
__device__ __half h_x[S * DIM];
__device__ __half h_wqkv[2048 * DIM];
__device__ float  g_bqkv[2048];
__device__ __half h_wo[DIM * HQ * D];
__device__ __half h_w1[4 * DIM * DIM];
__device__ __half h_w2[KOUT * DIM * 4 * DIM];

#define MMA_F16(d, a0,a1,a2,a3, b0,b1)                                        \
    asm volatile(                                                             \
        "mma.sync.aligned.m16n8k16.row.col.f32.f16.f16.f32 "                  \
        "{%0,%1,%2,%3}, {%4,%5,%6,%7}, {%8,%9}, {%0,%1,%2,%3};"               \
        : "+f"((d)[0]), "+f"((d)[1]), "+f"((d)[2]), "+f"((d)[3])              \
        : "r"(a0), "r"(a1), "r"(a2), "r"(a3), "r"(b0), "r"(b1))

#define LDMX4(r0,r1,r2,r3, addr)                                              \
    asm volatile("ldmatrix.sync.aligned.m8n8.x4.shared.b16 {%0,%1,%2,%3}, [%4];" \
        : "=r"(r0), "=r"(r1), "=r"(r2), "=r"(r3) : "r"(addr))

#define LDMX2T(b0, b1, addr)                                                  \
    asm volatile("ldmatrix.sync.aligned.m8n8.x2.trans.shared.b16 {%0,%1}, [%2];" \
        : "=r"(b0), "=r"(b1) : "r"(addr))

__device__ __forceinline__ void cp16(uint32_t saddr, const void* g) {
    asm volatile("cp.async.ca.shared.global [%0], [%1], 16;" :: "r"(saddr), "l"(g));
}
__device__ __forceinline__ void cp_commit() { asm volatile("cp.async.commit_group;"); }
template<int N_>
__device__ __forceinline__ void cp_wait() {
    asm volatile("cp.async.wait_group %0;" :: "n"(N_));
}

// ---------------------------------------------------------------------------
// Pipelined FP16 NT GEMM with ldmatrix fragment loads.
// TBK = 64 halves, stride 36 words, 3-stage cp.async, tile 128 x BN_,
// 8 warps (2m x 4n). ~32 ldmatrix + 128 HMMA per iter per warp.
// ---------------------------------------------------------------------------
#define TBM 128
#define HTBK 64
#define HST 36

template<int BN_, int NT, int MINCTA>
__global__ void __launch_bounds__(256, MINCTA)
gemm_f16_pipe(const __half* __restrict__ A, const __half* __restrict__ W,
              const float* __restrict__ bias, void* __restrict__ Cout,
              int M, int N, int KK, int act, int out_half)
{
    constexpr int ASTG = TBM * HST;
    constexpr int BSTG = BN_ * HST;
    constexpr int ALD  = (TBM * 8) / 256;
    constexpr int BLD  = (BN_ * 8) / 256;

    extern __shared__ uint32_t sm[];
    uint32_t* As = sm;
    uint32_t* Ws = sm + 3 * ASTG;
    const uint32_t as_base = (uint32_t)__cvta_generic_to_shared(As);
    const uint32_t ws_base = (uint32_t)__cvta_generic_to_shared(Ws);

    const int bm = blockIdx.y * TBM;
    const int bn = blockIdx.x * BN_;
    const int tid = threadIdx.x;
    const int wid = tid >> 5;
    const int lane = tid & 31;
    const int wm = (wid & 1) * 64;
    const int wn = (wid >> 1) * (BN_ / 4);
    const int qrow = lane >> 2;
    const int qcol = lane & 3;

    // ldmatrix lane addressing (word offsets within a stage)
    const int a_lane = (wm + (lane & 15)) * HST + ((lane >> 4) << 2);
    const int b_lane = (wn + ((lane >> 4) & 1) * 8 + (lane & 7)) * HST
                     + (((lane >> 3) & 1) << 2);

    float acc[4][NT][4];
#pragma unroll
    for (int mt = 0; mt < 4; mt++)
#pragma unroll
        for (int nt = 0; nt < NT; nt++)
#pragma unroll
            for (int r = 0; r < 4; r++) acc[mt][nt][r] = 0.f;

    const int niter = KK / HTBK;

    auto issue = [&](int it, int stg) {
        const int k0 = it * HTBK;
#pragma unroll
        for (int r = 0; r < ALD; r++) {
            const int idx = tid + r * 256;
            const int row = idx >> 3, c = idx & 7;
            cp16(as_base + (uint32_t)(stg * ASTG + row * HST + c * 4) * 4u,
                 A + (size_t)(bm + row) * KK + k0 + c * 8);
        }
#pragma unroll
        for (int r = 0; r < BLD; r++) {
            const int idx = tid + r * 256;
            const int row = idx >> 3, c = idx & 7;
            cp16(ws_base + (uint32_t)(stg * BSTG + row * HST + c * 4) * 4u,
                 W + (size_t)(bn + row) * KK + k0 + c * 8);
        }
    };

    issue(0, 0); cp_commit();
    issue(1, 1); cp_commit();
    cp_wait<1>();
    __syncthreads();

    for (int it = 0; it < niter; it++) {
        const int stg = it % 3;
        const uint32_t a_addr = as_base + (uint32_t)(stg * ASTG + a_lane) * 4u;
        const uint32_t b_addr = ws_base + (uint32_t)(stg * BSTG + b_lane) * 4u;

#pragma unroll
        for (int ks = 0; ks < 4; ks++) {
            const int kw = ks * 8;
            uint32_t af[4][4], bf[NT][2];
#pragma unroll
            for (int mt = 0; mt < 4; mt++)
                LDMX4(af[mt][0], af[mt][1], af[mt][2], af[mt][3],
                      a_addr + (uint32_t)((mt * 16 * HST + kw) * 4));
#pragma unroll
            for (int p = 0; p < NT / 2; p++)
                LDMX4(bf[2 * p][0], bf[2 * p][1], bf[2 * p + 1][0], bf[2 * p + 1][1],
                      b_addr + (uint32_t)((p * 16 * HST + kw) * 4));
#pragma unroll
            for (int mt = 0; mt < 4; mt++)
#pragma unroll
                for (int nt = 0; nt < NT; nt++)
                    MMA_F16(acc[mt][nt], af[mt][0], af[mt][1], af[mt][2], af[mt][3],
                            bf[nt][0], bf[nt][1]);
        }

        if (it + 2 < niter) {
            issue(it + 2, (it + 2) % 3);
            cp_commit();
            cp_wait<1>();
        } else {
            cp_wait<0>();
        }
        __syncthreads();
    }

    float* Cf = (float*)Cout;
    __half* Ch = (__half*)Cout;
#pragma unroll
    for (int mt = 0; mt < 4; mt++) {
        const int row = bm + wm + mt * 16 + qrow;
#pragma unroll
        for (int nt = 0; nt < NT; nt++) {
            const int col = bn + wn + nt * 8 + qcol * 2;
            const float b0 = bias[col];
            const float b1 = bias[col + 1];
            float v0 = acc[mt][nt][0] + b0;
            float v1 = acc[mt][nt][1] + b1;
            float v2 = acc[mt][nt][2] + b0;
            float v3 = acc[mt][nt][3] + b1;
            if (act == 1) {
                v0 = v0 / (1.f + expf(-v0));
                v1 = v1 / (1.f + expf(-v1));
                v2 = v2 / (1.f + expf(-v2));
                v3 = v3 / (1.f + expf(-v3));
            }
            if (out_half) {
                *(half2*)(Ch + (size_t)row * N + col)       = __floats2half2_rn(v0, v1);
                *(half2*)(Ch + (size_t)(row + 8) * N + col) = __floats2half2_rn(v2, v3);
            } else {
                float2 p0; p0.x = v0; p0.y = v1;
                float2 p1; p1.x = v2; p1.y = v3;
                *(float2*)(Cf + (size_t)row * N + col) = p0;
                *(float2*)(Cf + (size_t)(row + 8) * N + col) = p1;
            }
        }
    }
}

#define SMEMH128 (3 * (TBM * HST + 128 * HST) * 4)
#define SMEMH256 (3 * (TBM * HST + 256 * HST) * 4)

// ---------------------------------------------------------------------------
// Fused fp32->fp16 conversion of x + all weights (one launch)
// Segments (float4 units): x 524288 | Wq 262144 | Wk 131072 | Wv 131072 |
//                          Wo 262144 | W1 1048576 | W2 4194304
// ---------------------------------------------------------------------------
#define CVT_TOTAL4 6553600

__global__ void cvt_all(const float4* __restrict__ x,  const float4* __restrict__ Wq,
                        const float4* __restrict__ Wk, const float4* __restrict__ Wv,
                        const float4* __restrict__ Wo, const float4* __restrict__ W1,
                        const float4* __restrict__ W2,
                        __half* __restrict__ xh, __half* __restrict__ wqkvh,
                        __half* __restrict__ woh, __half* __restrict__ w1h,
                        __half* __restrict__ w2h)
{
    int i = blockIdx.x * 256 + threadIdx.x;
    if (i >= CVT_TOTAL4) return;

    const float4* src;
    __half* dst;
    int j = i;
    if (j < 524288)            { src = x;  dst = xh; }
    else if ((j -= 524288)  < 262144)  { src = Wq; dst = wqkvh; }
    else if ((j -= 262144)  < 131072)  { src = Wk; dst = wqkvh + 1024 * DIM; }
    else if ((j -= 131072)  < 131072)  { src = Wv; dst = wqkvh + 1536 * DIM; }
    else if ((j -= 131072)  < 262144)  { src = Wo; dst = woh; }
    else if ((j -= 262144)  < 1048576) { src = W1; dst = w1h; }
    else { j -= 1048576; src = W2; dst = w2h; }

    float4 v = src[j];
    half2 a = __floats2half2_rn(v.x, v.y);
    half2 b = __floats2half2_rn(v.z, v.w);
    uint2 u;
    u.x = *(uint32_t*)&a;
    u.y = *(uint32_t*)&b;
    *(uint2*)(dst + 4 * (size_t)j) = u;
}

__global__ void concat_bias(const float* __restrict__ bq, const float* __restrict__ bk,
                            const float* __restrict__ bv, float* __restrict__ dst)
{
    int i = blockIdx.x * 256 + threadIdx.x;
    if (i < 1024) dst[i] = bq[i];
    else if (i < 1536) dst[i] = bk[i - 1024];
    else if (i < 2048) dst[i] = bv[i - 1536];
}

// ---------------------------------------------------------------------------
// RoPE in place on fp16 fused qkv (fp32 math)
// ---------------------------------------------------------------------------
__global__ void rope_kernel(__half* __restrict__ qkv)
{
    const int NQ = S * HQ * 64;
    const int NK = S * G * 64;
    int i = blockIdx.x * blockDim.x + threadIdx.x;
    if (i >= NQ + NK) return;

    int s, d, base;
    if (i < NQ) {
        s = i / (HQ * 64);
        const int hd = i - s * (HQ * 64);
        const int h = hd >> 6;
        d = hd & 63;
        base = s * 2048 + h * D + d;
    } else {
        const int j = i - NQ;
        s = j / (G * 64);
        const int rem = j - s * (G * 64);
        const int g = rem >> 6;
        d = rem & 63;
        base = s * 2048 + 1024 + g * D + d;
    }
    const float inv = powf(10000.f, -(float)(2 * d) / 128.f);
    const float f = (float)s * inv;
    float sn, cs;
    sincosf(f, &sn, &cs);
    const float x1 = __half2float(qkv[base]);
    const float x2 = __half2float(qkv[base + 64]);
    qkv[base]      = __float2half_rn(x1 * cs - x2 * sn);
    qkv[base + 64] = __float2half_rn(x2 * cs + x1 * sn);
}

// ---------------------------------------------------------------------------
// FP16 tensor-core flash attention (fp16 per-group outputs)
// ---------------------------------------------------------------------------
#define BRR 128
#define BCC 64
#define QW 68
#define PW 36
#define AKS_OFF (BRR * QW)
#define AVS_OFF (AKS_OFF + BCC * QW)
#define ATT_WORDS (AVS_OFF + BCC * QW)

__global__ void __launch_bounds__(256, 1)
attn_f16(const __half* __restrict__ qkv, __half* __restrict__ outg)
{
    extern __shared__ uint32_t smu[];
    uint32_t* R0 = smu;
    uint32_t* KS = smu + AKS_OFF;
    uint32_t* VS = smu + AVS_OFF;
    const uint32_t vs_base = (uint32_t)__cvta_generic_to_shared(VS);

    const int rt = (int)(gridDim.x - 1) - (int)blockIdx.x;
    const int h  = blockIdx.y;
    const int g  = blockIdx.z;
    const int row0 = rt * BRR;
    __half* out = outg + (size_t)g * (S * HQ * D);

    const int tid = threadIdx.x;
    const int wid = tid >> 5;
    const int lane = tid & 31;
    const int qrow = lane >> 2;
    const int qcol = lane & 3;
    const int wrow = wid * 16;

    for (int idx = tid; idx < BRR * 16; idx += 256) {
        const int r = idx >> 4, c = idx & 15;
        *(uint4*)&R0[r * QW + c * 4] =
            *(const uint4*)(qkv + (size_t)(row0 + r) * 2048 + h * D + c * 8);
    }
    __syncthreads();

    uint32_t qf[8][4];
#pragma unroll
    for (int ks = 0; ks < 8; ks++) {
        const int base = (wrow + qrow) * QW + ks * 8 + qcol;
        qf[ks][0] = R0[base];
        qf[ks][1] = R0[base + 8 * QW];
        qf[ks][2] = R0[base + 4];
        qf[ks][3] = R0[base + 8 * QW + 4];
    }
    __syncthreads();

    float pv[16][4];
#pragma unroll
    for (int nt = 0; nt < 16; nt++)
#pragma unroll
        for (int r = 0; r < 4; r++) pv[nt][r] = 0.f;

    float m0 = -1e30f, m1 = -1e30f, l0 = 0.f, l1 = 0.f;
    const float scale = 0.08838834764831845f;
    const int ri0 = row0 + wrow + qrow;
    const int ri1 = ri0 + 8;
    const int njt = 2 * rt + 2;

    const int lm_row = (lane & 7) + ((lane >> 3) & 1) * 8;

    for (int jt = 0; jt < njt; jt++) {
        const int col0 = jt * BCC;

        for (int idx = tid; idx < BCC * 16; idx += 256) {
            const int j = idx >> 4, c = idx & 15;
            *(uint4*)&KS[j * QW + c * 4] =
                *(const uint4*)(qkv + (size_t)(col0 + j) * 2048 + 1024 + g * D + c * 8);
            *(uint4*)&VS[j * QW + c * 4] =
                *(const uint4*)(qkv + (size_t)(col0 + j) * 2048 + 1536 + g * D + c * 8);
        }
        __syncthreads();

        float sc[8][4];
#pragma unroll
        for (int nt = 0; nt < 8; nt++)
#pragma unroll
            for (int r = 0; r < 4; r++) sc[nt][r] = 0.f;

#pragma unroll
        for (int ks = 0; ks < 8; ks++) {
#pragma unroll
            for (int nt = 0; nt < 8; nt++) {
                const int c0 = (nt * 8 + qrow) * QW + ks * 8 + qcol;
                MMA_F16(sc[nt], qf[ks][0], qf[ks][1], qf[ks][2], qf[ks][3],
                        KS[c0], KS[c0 + 4]);
            }
        }

        float mt0 = -1e30f, mt1 = -1e30f;
#pragma unroll
        for (int nt = 0; nt < 8; nt++) {
            const int j0 = col0 + nt * 8 + 2 * qcol;
            sc[nt][0] = (j0     <= ri0) ? sc[nt][0] * scale : -1e30f;
            sc[nt][1] = (j0 + 1 <= ri0) ? sc[nt][1] * scale : -1e30f;
            sc[nt][2] = (j0     <= ri1) ? sc[nt][2] * scale : -1e30f;
            sc[nt][3] = (j0 + 1 <= ri1) ? sc[nt][3] * scale : -1e30f;
            mt0 = fmaxf(mt0, fmaxf(sc[nt][0], sc[nt][1]));
            mt1 = fmaxf(mt1, fmaxf(sc[nt][2], sc[nt][3]));
        }
#pragma unroll
        for (int off = 1; off <= 2; off <<= 1) {
            mt0 = fmaxf(mt0, __shfl_xor_sync(0xffffffffu, mt0, off));
            mt1 = fmaxf(mt1, __shfl_xor_sync(0xffffffffu, mt1, off));
        }
        const float mn0 = fmaxf(m0, mt0);
        const float mn1 = fmaxf(m1, mt1);
        const float cr0 = __expf(m0 - mn0);
        const float cr1 = __expf(m1 - mn1);

        float ps0 = 0.f, ps1 = 0.f;
#pragma unroll
        for (int nt = 0; nt < 8; nt++) {
            const float p0 = __expf(sc[nt][0] - mn0);
            const float p1 = __expf(sc[nt][1] - mn0);
            const float p2 = __expf(sc[nt][2] - mn1);
            const float p3 = __expf(sc[nt][3] - mn1);
            ps0 += p0 + p1;
            ps1 += p2 + p3;
            half2 u01 = __floats2half2_rn(p0, p1);
            half2 u23 = __floats2half2_rn(p2, p3);
            R0[(wrow + qrow) * PW + nt * 4 + qcol]     = *(uint32_t*)&u01;
            R0[(wrow + qrow + 8) * PW + nt * 4 + qcol] = *(uint32_t*)&u23;
        }
#pragma unroll
        for (int off = 1; off <= 2; off <<= 1) {
            ps0 += __shfl_xor_sync(0xffffffffu, ps0, off);
            ps1 += __shfl_xor_sync(0xffffffffu, ps1, off);
        }
        l0 = l0 * cr0 + ps0;
        l1 = l1 * cr1 + ps1;
        m0 = mn0;
        m1 = mn1;
#pragma unroll
        for (int nt = 0; nt < 16; nt++) {
            pv[nt][0] *= cr0; pv[nt][1] *= cr0;
            pv[nt][2] *= cr1; pv[nt][3] *= cr1;
        }
        __syncwarp();

#pragma unroll
        for (int kw = 0; kw < 4; kw++) {
            const int a0i = (wrow + qrow) * PW + kw * 8 + qcol;
            const uint32_t a0 = R0[a0i];
            const uint32_t a1 = R0[a0i + 8 * PW];
            const uint32_t a2 = R0[a0i + 4];
            const uint32_t a3 = R0[a0i + 8 * PW + 4];
            const uint32_t vrow = vs_base + (uint32_t)((kw * 16 + lm_row) * QW) * 4u;
#pragma unroll
            for (int nt = 0; nt < 16; nt++) {
                uint32_t b0, b1;
                LDMX2T(b0, b1, vrow + (uint32_t)(nt * 4) * 4u);
                MMA_F16(pv[nt], a0, a1, a2, a3, b0, b1);
            }
        }
        __syncthreads();
    }

    const float il0 = 1.f / l0;
    const float il1 = 1.f / l1;
#pragma unroll
    for (int nt = 0; nt < 16; nt++) {
        half2 o0 = __floats2half2_rn(pv[nt][0] * il0, pv[nt][1] * il0);
        *(half2*)(out + (size_t)ri0 * (HQ * D) + h * D + nt * 8 + 2 * qcol) = o0;
        half2 o1 = __floats2half2_rn(pv[nt][2] * il1, pv[nt][3] * il1);
        *(half2*)(out + (size_t)ri1 * (HQ * D) + h * D + nt * 8 + 2 * qcol) = o1;
    }
}

// ---------------------------------------------------------------------------
// Sum 4 per-group fp16 outputs -> fp16
// ---------------------------------------------------------------------------
__global__ void sum4_kernel(const __half* __restrict__ a, __half* __restrict__ o)
{
    const int NW = S * HQ * D;           // elements
    int i = (blockIdx.x * 256 + threadIdx.x) * 4;
    if (i >= NW) return;
    float r[4] = {0.f, 0.f, 0.f, 0.f};
#pragma unroll
    for (int g = 0; g < 4; g++) {
        uint2 u = *(const uint2*)(a + (size_t)g * NW + i);
        half2 p0 = *(half2*)&u.x;
        half2 p1 = *(half2*)&u.y;
        r[0] += __half2float(__low2half(p0));
        r[1] += __half2float(__high2half(p0));
        r[2] += __half2float(__low2half(p1));
        r[3] += __half2float(__high2half(p1));
    }
    half2 q0 = __floats2half2_rn(r[0], r[1]);
    half2 q1 = __floats2half2_rn(r[2], r[3]);
    uint2 u;
    u.x = *(uint32_t*)&q0;
    u.y = *(uint32_t*)&q1;
    *(uint2*)(o + i) = u;
}

// ---------------------------------------------------------------------------
// Launch
// ---------------------------------------------------------------------------
extern "C" void kernel_launch(void* const* d_in, const int* in_sizes, int n_in,
                              void* d_out, int out_size)
{
    const float* x  = (const float*)d_in[0];
    const float* Wq = (const float*)d_in[1];
    const float* bq = (const float*)d_in[2];
    const float* Wk = (const float*)d_in[3];
    const float* bk = (const float*)d_in[4];
    const float* Wv = (const float*)d_in[5];
    const float* bv = (const float*)d_in[6];
    const float* Wo = (const float*)d_in[7];
    const float* bo = (const float*)d_in[8];
    const float* W1 = (const float*)d_in[9];
    const float* b1 = (const float*)d_in[10];
    const float* W2 = (const float*)d_in[11];
    const float* b2 = (const float*)d_in[12];
    float* out = (float*)d_out;

    float *bqkvr;
    __half *qkvh, *agh, *attnh, *oh, *h1h, *xh, *wqkvh, *woh, *w1h, *w2h;
    cudaGetSymbolAddress((void**)&qkvh,  h_qkv);
    cudaGetSymbolAddress((void**)&agh,   h_attng);
    cudaGetSymbolAddress((void**)&bqkvr, g_bqkv);
    cudaGetSymbolAddress((void**)&attnh, h_attn);
    cudaGetSymbolAddress((void**)&oh,    h_o);
    cudaGetSymbolAddress((void**)&h1h,   h_h1);
    cudaGetSymbolAddress((void**)&xh,    h_x);
    cudaGetSymbolAddress((void**)&wqkvh, h_wqkv);
    cudaGetSymbolAddress((void**)&woh,   h_wo);
    cudaGetSymbolAddress((void**)&w1h,   h_w1);
    cudaGetSymbolAddress((void**)&w2h,   h_w2);

    cudaFuncSetAttribute((const void*)gemm_f16_pipe<128, 4, 2>,
                         cudaFuncAttributeMaxDynamicSharedMemorySize, SMEMH128);
    cudaFuncSetAttribute((const void*)gemm_f16_pipe<256, 8, 1>,
                         cudaFuncAttributeMaxDynamicSharedMemorySize, SMEMH256);
    cudaFuncSetAttribute(attn_f16, cudaFuncAttributeMaxDynamicSharedMemorySize,
                         ATT_WORDS * 4);

    // single fused conversion pass
    cvt_all<<<(CVT_TOTAL4 + 255) / 256, 256>>>(
        (const float4*)x, (const float4*)Wq, (const float4*)Wk, (const float4*)Wv,
        (const float4*)Wo, (const float4*)W1, (const float4*)W2,
        xh, wqkvh, woh, w1h, w2h);
    concat_bias<<<8, 256>>>(bq, bk, bv, bqkvr);

    // Fused QKV projection -> fp16
    gemm_f16_pipe<256, 8, 1><<<dim3(2048 / 256, S / TBM), 256, SMEMH256>>>(
        xh, wqkvh, bqkvr, qkvh, S, 2048, DIM, 0, 1);

    // RoPE
    {
        const int total = S * HQ * 64 + S * G * 64;
        rope_kernel<<<(total + 255) / 256, 256>>>(qkvh);
    }

    // Attention + g-sum
    attn_f16<<<dim3(S / BRR, HQ, G), 256, ATT_WORDS * 4>>>(qkvh, agh);
    sum4_kernel<<<(S * HQ * D / 4 + 255) / 256, 256>>>(agh, attnh);

    // O projection -> fp16
    gemm_f16_pipe<128, 4, 2><<<dim3(DIM / 128, S / TBM), 256, SMEMH128>>>(
        attnh, woh, bo, oh, S, DIM, HQ * D, 0, 1);

    // FFN
    gemm_f16_pipe<256, 8, 1><<<dim3(4 * DIM / 256, S / TBM), 256, SMEMH256>>>(
        oh, w1h, b1, h1h, S, 4 * DIM, DIM, 1, 1);
    gemm_f16_pipe<256, 8, 1><<<dim3(KOUT * DIM / 256, S / TBM), 256, SMEMH256>>>(
        h1h, w2h, b2, out, S, KOUT * DIM, 4 * DIM, 0, 0);
}

// round 11
// speedup vs baseline: 26.4233x; 1.1074x over previous
#include <cuda_runtime.h>
#include <cuda_fp16.h>
#include <math.h>
#include <stdint.h>

// ---------------------------------------------------------------------------
// Problem constants
// ---------------------------------------------------------------------------
#define S    2048
#define DIM  1024
#define HQ   8
#define G    4
#define D    128
#define KOUT 4

// ---------------------------------------------------------------------------
// Scratch
// ---------------------------------------------------------------------------
__device__ __half h_qkv[S * 2048];
__device__ __half h_attng[G * S * HQ * D];
__device__ __half h_attn[S * HQ * D];
__device__ __half h_o[S * DIM];
__device__ __half h_h1[S * DIM * 4];
__device__ __half h_x[S * DIM];
__device__ __half h_wqkv[2048 * DIM];
__device__ float  g_bqkv[2048];
__device__ __half h_wo[DIM * HQ * D];
__device__ __half h_w1[4 * DIM * DIM];
__device__ __half h_w2[KOUT * DIM * 4 * DIM];

#define MMA_F16(d, a0,a1,a2,a3, b0,b1)                                        \
    asm volatile(                                                             \
        "mma.sync.aligned.m16n8k16.row.col.f32.f16.f16.f32 "                  \
        "{%0,%1,%2,%3}, {%4,%5,%6,%7}, {%8,%9}, {%0,%1,%2,%3};"               \
        : "+f"((d)[0]), "+f"((d)[1]), "+f"((d)[2]), "+f"((d)[3])              \
        : "r"(a0), "r"(a1), "r"(a2), "r"(a3), "r"(b0), "r"(b1))

#define LDMX4(r0,r1,r2,r3, addr)                                              \
    asm volatile("ldmatrix.sync.aligned.m8n8.x4.shared.b16 {%0,%1,%2,%3}, [%4];" \
        : "=r"(r0), "=r"(r1), "=r"(r2), "=r"(r3) : "r"(addr))

#define LDMX2T(b0, b1, addr)                                                  \
    asm volatile("ldmatrix.sync.aligned.m8n8.x2.trans.shared.b16 {%0,%1}, [%2];" \
        : "=r"(b0), "=r"(b1) : "r"(addr))

__device__ __forceinline__ void cp16(uint32_t saddr, const void* g) {
    asm volatile("cp.async.ca.shared.global [%0], [%1], 16;" :: "r"(saddr), "l"(g));
}
__device__ __forceinline__ void cp_commit() { asm volatile("cp.async.commit_group;"); }
template<int N_>
__device__ __forceinline__ void cp_wait() {
    asm volatile("cp.async.wait_group %0;" :: "n"(N_));
}

// ---------------------------------------------------------------------------
// Pipelined FP16 NT GEMM (unchanged from R10)
// ---------------------------------------------------------------------------
#define TBM 128
#define HTBK 64
#define HST 36

template<int BN_, int NT, int MINCTA>
__global__ void __launch_bounds__(256, MINCTA)
gemm_f16_pipe(const __half* __restrict__ A, const __half* __restrict__ W,
              const float* __restrict__ bias, void* __restrict__ Cout,
              int M, int N, int KK, int act, int out_half)
{
    constexpr int ASTG = TBM * HST;
    constexpr int BSTG = BN_ * HST;
    constexpr int ALD  = (TBM * 8) / 256;
    constexpr int BLD  = (BN_ * 8) / 256;

    extern __shared__ uint32_t sm[];
    uint32_t* As = sm;
    uint32_t* Ws = sm + 3 * ASTG;
    const uint32_t as_base = (uint32_t)__cvta_generic_to_shared(As);
    const uint32_t ws_base = (uint32_t)__cvta_generic_to_shared(Ws);

    const int bm = blockIdx.y * TBM;
    const int bn = blockIdx.x * BN_;
    const int tid = threadIdx.x;
    const int wid = tid >> 5;
    const int lane = tid & 31;
    const int wm = (wid & 1) * 64;
    const int wn = (wid >> 1) * (BN_ / 4);
    const int qrow = lane >> 2;
    const int qcol = lane & 3;

    const int a_lane = (wm + (lane & 15)) * HST + ((lane >> 4) << 2);
    const int b_lane = (wn + ((lane >> 4) & 1) * 8 + (lane & 7)) * HST
                     + (((lane >> 3) & 1) << 2);

    float acc[4][NT][4];
#pragma unroll
    for (int mt = 0; mt < 4; mt++)
#pragma unroll
        for (int nt = 0; nt < NT; nt++)
#pragma unroll
            for (int r = 0; r < 4; r++) acc[mt][nt][r] = 0.f;

    const int niter = KK / HTBK;

    auto issue = [&](int it, int stg) {
        const int k0 = it * HTBK;
#pragma unroll
        for (int r = 0; r < ALD; r++) {
            const int idx = tid + r * 256;
            const int row = idx >> 3, c = idx & 7;
            cp16(as_base + (uint32_t)(stg * ASTG + row * HST + c * 4) * 4u,
                 A + (size_t)(bm + row) * KK + k0 + c * 8);
        }
#pragma unroll
        for (int r = 0; r < BLD; r++) {
            const int idx = tid + r * 256;
            const int row = idx >> 3, c = idx & 7;
            cp16(ws_base + (uint32_t)(stg * BSTG + row * HST + c * 4) * 4u,
                 W + (size_t)(bn + row) * KK + k0 + c * 8);
        }
    };

    issue(0, 0); cp_commit();
    issue(1, 1); cp_commit();
    cp_wait<1>();
    __syncthreads();

    for (int it = 0; it < niter; it++) {
        const int stg = it % 3;
        const uint32_t a_addr = as_base + (uint32_t)(stg * ASTG + a_lane) * 4u;
        const uint32_t b_addr = ws_base + (uint32_t)(stg * BSTG + b_lane) * 4u;

#pragma unroll
        for (int ks = 0; ks < 4; ks++) {
            const int kw = ks * 8;
            uint32_t af[4][4], bf[NT][2];
#pragma unroll
            for (int mt = 0; mt < 4; mt++)
                LDMX4(af[mt][0], af[mt][1], af[mt][2], af[mt][3],
                      a_addr + (uint32_t)((mt * 16 * HST + kw) * 4));
#pragma unroll
            for (int p = 0; p < NT / 2; p++)
                LDMX4(bf[2 * p][0], bf[2 * p][1], bf[2 * p + 1][0], bf[2 * p + 1][1],
                      b_addr + (uint32_t)((p * 16 * HST + kw) * 4));
#pragma unroll
            for (int mt = 0; mt < 4; mt++)
#pragma unroll
                for (int nt = 0; nt < NT; nt++)
                    MMA_F16(acc[mt][nt], af[mt][0], af[mt][1], af[mt][2], af[mt][3],
                            bf[nt][0], bf[nt][1]);
        }

        if (it + 2 < niter) {
            issue(it + 2, (it + 2) % 3);
            cp_commit();
            cp_wait<1>();
        } else {
            cp_wait<0>();
        }
        __syncthreads();
    }

    float* Cf = (float*)Cout;
    __half* Ch = (__half*)Cout;
#pragma unroll
    for (int mt = 0; mt < 4; mt++) {
        const int row = bm + wm + mt * 16 + qrow;
#pragma unroll
        for (int nt = 0; nt < NT; nt++) {
            const int col = bn + wn + nt * 8 + qcol * 2;
            const float b0 = bias[col];
            const float b1 = bias[col + 1];
            float v0 = acc[mt][nt][0] + b0;
            float v1 = acc[mt][nt][1] + b1;
            float v2 = acc[mt][nt][2] + b0;
            float v3 = acc[mt][nt][3] + b1;
            if (act == 1) {
                v0 = v0 / (1.f + expf(-v0));
                v1 = v1 / (1.f + expf(-v1));
                v2 = v2 / (1.f + expf(-v2));
                v3 = v3 / (1.f + expf(-v3));
            }
            if (out_half) {
                *(half2*)(Ch + (size_t)row * N + col)       = __floats2half2_rn(v0, v1);
                *(half2*)(Ch + (size_t)(row + 8) * N + col) = __floats2half2_rn(v2, v3);
            } else {
                float2 p0; p0.x = v0; p0.y = v1;
                float2 p1; p1.x = v2; p1.y = v3;
                *(float2*)(Cf + (size_t)row * N + col) = p0;
                *(float2*)(Cf + (size_t)(row + 8) * N + col) = p1;
            }
        }
    }
}

#define SMEMH128 (3 * (TBM * HST + 128 * HST) * 4)
#define SMEMH256 (3 * (TBM * HST + 256 * HST) * 4)

// ---------------------------------------------------------------------------
// Fused fp32->fp16 conversion (one launch)
// ---------------------------------------------------------------------------
#define CVT_TOTAL4 6553600

__global__ void cvt_all(const float4* __restrict__ x,  const float4* __restrict__ Wq,
                        const float4* __restrict__ Wk, const float4* __restrict__ Wv,
                        const float4* __restrict__ Wo, const float4* __restrict__ W1,
                        const float4* __restrict__ W2,
                        __half* __restrict__ xh, __half* __restrict__ wqkvh,
                        __half* __restrict__ woh, __half* __restrict__ w1h,
                        __half* __restrict__ w2h)
{
    int i = blockIdx.x * 256 + threadIdx.x;
    if (i >= CVT_TOTAL4) return;

    const float4* src;
    __half* dst;
    int j = i;
    if (j < 524288)            { src = x;  dst = xh; }
    else if ((j -= 524288)  < 262144)  { src = Wq; dst = wqkvh; }
    else if ((j -= 262144)  < 131072)  { src = Wk; dst = wqkvh + 1024 * DIM; }
    else if ((j -= 131072)  < 131072)  { src = Wv; dst = wqkvh + 1536 * DIM; }
    else if ((j -= 131072)  < 262144)  { src = Wo; dst = woh; }
    else if ((j -= 262144)  < 1048576) { src = W1; dst = w1h; }
    else { j -= 1048576; src = W2; dst = w2h; }

    float4 v = src[j];
    half2 a = __floats2half2_rn(v.x, v.y);
    half2 b = __floats2half2_rn(v.z, v.w);
    uint2 u;
    u.x = *(uint32_t*)&a;
    u.y = *(uint32_t*)&b;
    *(uint2*)(dst + 4 * (size_t)j) = u;
}

__global__ void concat_bias(const float* __restrict__ bq, const float* __restrict__ bk,
                            const float* __restrict__ bv, float* __restrict__ dst)
{
    int i = blockIdx.x * 256 + threadIdx.x;
    if (i < 1024) dst[i] = bq[i];
    else if (i < 1536) dst[i] = bk[i - 1024];
    else if (i < 2048) dst[i] = bv[i - 1536];
}

// ---------------------------------------------------------------------------
// RoPE (unchanged)
// ---------------------------------------------------------------------------
__global__ void rope_kernel(__half* __restrict__ qkv)
{
    const int NQ = S * HQ * 64;
    const int NK = S * G * 64;
    int i = blockIdx.x * blockDim.x + threadIdx.x;
    if (i >= NQ + NK) return;

    int s, d, base;
    if (i < NQ) {
        s = i / (HQ * 64);
        const int hd = i - s * (HQ * 64);
        const int h = hd >> 6;
        d = hd & 63;
        base = s * 2048 + h * D + d;
    } else {
        const int j = i - NQ;
        s = j / (G * 64);
        const int rem = j - s * (G * 64);
        const int g = rem >> 6;
        d = rem & 63;
        base = s * 2048 + 1024 + g * D + d;
    }
    const float inv = powf(10000.f, -(float)(2 * d) / 128.f);
    const float f = (float)s * inv;
    float sn, cs;
    sincosf(f, &sn, &cs);
    const float x1 = __half2float(qkv[base]);
    const float x2 = __half2float(qkv[base + 64]);
    qkv[base]      = __float2half_rn(x1 * cs - x2 * sn);
    qkv[base + 64] = __float2half_rn(x2 * cs + x1 * sn);
}

// ---------------------------------------------------------------------------
// FP16 flash attention with double-buffered cp.async K/V tiles.
// Smem: Q/P region (8704 w) | K bufs 2x4352 w | V bufs 2x4352 w = 102 KB
// ---------------------------------------------------------------------------
#define BRR 128
#define BCC 64
#define QW 68
#define PW 36
#define AK_OFF  (BRR * QW)                 // 8704
#define AV_OFF  (AK_OFF + 2 * BCC * QW)    // 17408
#define ATT_WORDS (AV_OFF + 2 * BCC * QW)  // 26112 words = 104448 B

__global__ void __launch_bounds__(256, 1)
attn_f16(const __half* __restrict__ qkv, __half* __restrict__ outg)
{
    extern __shared__ uint32_t smu[];
    uint32_t* R0 = smu;
    const uint32_t sm_base = (uint32_t)__cvta_generic_to_shared(smu);

    const int rt = (int)(gridDim.x - 1) - (int)blockIdx.x;
    const int h  = blockIdx.y;
    const int g  = blockIdx.z;
    const int row0 = rt * BRR;
    __half* out = outg + (size_t)g * (S * HQ * D);

    const int tid = threadIdx.x;
    const int wid = tid >> 5;
    const int lane = tid & 31;
    const int qrow = lane >> 2;
    const int qcol = lane & 3;
    const int wrow = wid * 16;

    // ---- Q: global -> smem ----
    for (int idx = tid; idx < BRR * 16; idx += 256) {
        const int r = idx >> 4, c = idx & 15;
        *(uint4*)&R0[r * QW + c * 4] =
            *(const uint4*)(qkv + (size_t)(row0 + r) * 2048 + h * D + c * 8);
    }
    __syncthreads();

    uint32_t qf[8][4];
#pragma unroll
    for (int ks = 0; ks < 8; ks++) {
        const int base = (wrow + qrow) * QW + ks * 8 + qcol;
        qf[ks][0] = R0[base];
        qf[ks][1] = R0[base + 8 * QW];
        qf[ks][2] = R0[base + 4];
        qf[ks][3] = R0[base + 8 * QW + 4];
    }
    __syncthreads();   // R0 free for P

    float pv[16][4];
#pragma unroll
    for (int nt = 0; nt < 16; nt++)
#pragma unroll
        for (int r = 0; r < 4; r++) pv[nt][r] = 0.f;

    float m0 = -1e30f, m1 = -1e30f, l0 = 0.f, l1 = 0.f;
    const float scale = 0.08838834764831845f;
    const int ri0 = row0 + wrow + qrow;
    const int ri1 = ri0 + 8;
    const int njt = 2 * rt + 2;

    const int lm_row = (lane & 7) + ((lane >> 3) & 1) * 8;

    // cp.async issue of K+V tiles for col-tile jt into buffer stg
    auto issue_kv = [&](int jt, int stg) {
        const int col0 = jt * BCC;
        const uint32_t kbuf = sm_base + (uint32_t)(AK_OFF + stg * BCC * QW) * 4u;
        const uint32_t vbuf = sm_base + (uint32_t)(AV_OFF + stg * BCC * QW) * 4u;
#pragma unroll
        for (int r = 0; r < 4; r++) {                   // K: 1024 chunks
            const int idx = tid + r * 256;
            const int j = idx >> 4, c = idx & 15;
            cp16(kbuf + (uint32_t)(j * QW + c * 4) * 4u,
                 qkv + (size_t)(col0 + j) * 2048 + 1024 + g * D + c * 8);
        }
#pragma unroll
        for (int r = 0; r < 4; r++) {                   // V: 1024 chunks
            const int idx = tid + r * 256;
            const int j = idx >> 4, c = idx & 15;
            cp16(vbuf + (uint32_t)(j * QW + c * 4) * 4u,
                 qkv + (size_t)(col0 + j) * 2048 + 1536 + g * D + c * 8);
        }
    };

    issue_kv(0, 0);
    cp_commit();

    for (int jt = 0; jt < njt; jt++) {
        const int col0 = jt * BCC;
        const int cur = jt & 1;

        if (jt + 1 < njt) {
            issue_kv(jt + 1, cur ^ 1);
            cp_commit();
            cp_wait<1>();     // current tile ready; next in flight
        } else {
            cp_wait<0>();
        }
        __syncthreads();

        const uint32_t* KS = smu + AK_OFF + cur * BCC * QW;
        const uint32_t vs_base = sm_base + (uint32_t)(AV_OFF + cur * BCC * QW) * 4u;

        // ---- scores ----
        float sc[8][4];
#pragma unroll
        for (int nt = 0; nt < 8; nt++)
#pragma unroll
            for (int r = 0; r < 4; r++) sc[nt][r] = 0.f;

#pragma unroll
        for (int ks = 0; ks < 8; ks++) {
#pragma unroll
            for (int nt = 0; nt < 8; nt++) {
                const int c0 = (nt * 8 + qrow) * QW + ks * 8 + qcol;
                MMA_F16(sc[nt], qf[ks][0], qf[ks][1], qf[ks][2], qf[ks][3],
                        KS[c0], KS[c0 + 4]);
            }
        }

        // ---- mask + scale + row max ----
        float mt0 = -1e30f, mt1 = -1e30f;
#pragma unroll
        for (int nt = 0; nt < 8; nt++) {
            const int j0 = col0 + nt * 8 + 2 * qcol;
            sc[nt][0] = (j0     <= ri0) ? sc[nt][0] * scale : -1e30f;
            sc[nt][1] = (j0 + 1 <= ri0) ? sc[nt][1] * scale : -1e30f;
            sc[nt][2] = (j0     <= ri1) ? sc[nt][2] * scale : -1e30f;
            sc[nt][3] = (j0 + 1 <= ri1) ? sc[nt][3] * scale : -1e30f;
            mt0 = fmaxf(mt0, fmaxf(sc[nt][0], sc[nt][1]));
            mt1 = fmaxf(mt1, fmaxf(sc[nt][2], sc[nt][3]));
        }
#pragma unroll
        for (int off = 1; off <= 2; off <<= 1) {
            mt0 = fmaxf(mt0, __shfl_xor_sync(0xffffffffu, mt0, off));
            mt1 = fmaxf(mt1, __shfl_xor_sync(0xffffffffu, mt1, off));
        }
        const float mn0 = fmaxf(m0, mt0);
        const float mn1 = fmaxf(m1, mt1);
        const float cr0 = __expf(m0 - mn0);
        const float cr1 = __expf(m1 - mn1);

        // ---- exp + P store + row sum ----
        float ps0 = 0.f, ps1 = 0.f;
#pragma unroll
        for (int nt = 0; nt < 8; nt++) {
            const float p0 = __expf(sc[nt][0] - mn0);
            const float p1 = __expf(sc[nt][1] - mn0);
            const float p2 = __expf(sc[nt][2] - mn1);
            const float p3 = __expf(sc[nt][3] - mn1);
            ps0 += p0 + p1;
            ps1 += p2 + p3;
            half2 u01 = __floats2half2_rn(p0, p1);
            half2 u23 = __floats2half2_rn(p2, p3);
            R0[(wrow + qrow) * PW + nt * 4 + qcol]     = *(uint32_t*)&u01;
            R0[(wrow + qrow + 8) * PW + nt * 4 + qcol] = *(uint32_t*)&u23;
        }
#pragma unroll
        for (int off = 1; off <= 2; off <<= 1) {
            ps0 += __shfl_xor_sync(0xffffffffu, ps0, off);
            ps1 += __shfl_xor_sync(0xffffffffu, ps1, off);
        }
        l0 = l0 * cr0 + ps0;
        l1 = l1 * cr1 + ps1;
        m0 = mn0;
        m1 = mn1;
#pragma unroll
        for (int nt = 0; nt < 16; nt++) {
            pv[nt][0] *= cr0; pv[nt][1] *= cr0;
            pv[nt][2] *= cr1; pv[nt][3] *= cr1;
        }
        __syncwarp();

        // ---- O += P V ----
#pragma unroll
        for (int kw = 0; kw < 4; kw++) {
            const int a0i = (wrow + qrow) * PW + kw * 8 + qcol;
            const uint32_t a0 = R0[a0i];
            const uint32_t a1 = R0[a0i + 8 * PW];
            const uint32_t a2 = R0[a0i + 4];
            const uint32_t a3 = R0[a0i + 8 * PW + 4];
            const uint32_t vrow = vs_base + (uint32_t)((kw * 16 + lm_row) * QW) * 4u;
#pragma unroll
            for (int nt = 0; nt < 16; nt++) {
                uint32_t b0, b1;
                LDMX2T(b0, b1, vrow + (uint32_t)(nt * 4) * 4u);
                MMA_F16(pv[nt], a0, a1, a2, a3, b0, b1);
            }
        }
        __syncthreads();   // all warps done with cur bufs before next issue reuses
    }

    const float il0 = 1.f / l0;
    const float il1 = 1.f / l1;
#pragma unroll
    for (int nt = 0; nt < 16; nt++) {
        half2 o0 = __floats2half2_rn(pv[nt][0] * il0, pv[nt][1] * il0);
        *(half2*)(out + (size_t)ri0 * (HQ * D) + h * D + nt * 8 + 2 * qcol) = o0;
        half2 o1 = __floats2half2_rn(pv[nt][2] * il1, pv[nt][3] * il1);
        *(half2*)(out + (size_t)ri1 * (HQ * D) + h * D + nt * 8 + 2 * qcol) = o1;
    }
}

// ---------------------------------------------------------------------------
// Sum 4 per-group fp16 outputs -> fp16
// ---------------------------------------------------------------------------
__global__ void sum4_kernel(const __half* __restrict__ a, __half* __restrict__ o)
{
    const int NW = S * HQ * D;
    int i = (blockIdx.x * 256 + threadIdx.x) * 4;
    if (i >= NW) return;
    float r[4] = {0.f, 0.f, 0.f, 0.f};
#pragma unroll
    for (int g = 0; g < 4; g++) {
        uint2 u = *(const uint2*)(a + (size_t)g * NW + i);
        half2 p0 = *(half2*)&u.x;
        half2 p1 = *(half2*)&u.y;
        r[0] += __half2float(__low2half(p0));
        r[1] += __half2float(__high2half(p0));
        r[2] += __half2float(__low2half(p1));
        r[3] += __half2float(__high2half(p1));
    }
    half2 q0 = __floats2half2_rn(r[0], r[1]);
    half2 q1 = __floats2half2_rn(r[2], r[3]);
    uint2 u;
    u.x = *(uint32_t*)&q0;
    u.y = *(uint32_t*)&q1;
    *(uint2*)(o + i) = u;
}

// ---------------------------------------------------------------------------
// Launch
// ---------------------------------------------------------------------------
extern "C" void kernel_launch(void* const* d_in, const int* in_sizes, int n_in,
                              void* d_out, int out_size)
{
    const float* x  = (const float*)d_in[0];
    const float* Wq = (const float*)d_in[1];
    const float* bq = (const float*)d_in[2];
    const float* Wk = (const float*)d_in[3];
    const float* bk = (const float*)d_in[4];
    const float* Wv = (const float*)d_in[5];
    const float* bv = (const float*)d_in[6];
    const float* Wo = (const float*)d_in[7];
    const float* bo = (const float*)d_in[8];
    const float* W1 = (const float*)d_in[9];
    const float* b1 = (const float*)d_in[10];
    const float* W2 = (const float*)d_in[11];
    const float* b2 = (const float*)d_in[12];
    float* out = (float*)d_out;

    float *bqkvr;
    __half *qkvh, *agh, *attnh, *oh, *h1h, *xh, *wqkvh, *woh, *w1h, *w2h;
    cudaGetSymbolAddress((void**)&qkvh,  h_qkv);
    cudaGetSymbolAddress((void**)&agh,   h_attng);
    cudaGetSymbolAddress((void**)&bqkvr, g_bqkv);
    cudaGetSymbolAddress((void**)&attnh, h_attn);
    cudaGetSymbolAddress((void**)&oh,    h_o);
    cudaGetSymbolAddress((void**)&h1h,   h_h1);
    cudaGetSymbolAddress((void**)&xh,    h_x);
    cudaGetSymbolAddress((void**)&wqkvh, h_wqkv);
    cudaGetSymbolAddress((void**)&woh,   h_wo);
    cudaGetSymbolAddress((void**)&w1h,   h_w1);
    cudaGetSymbolAddress((void**)&w2h,   h_w2);

    cudaFuncSetAttribute((const void*)gemm_f16_pipe<128, 4, 2>,
                         cudaFuncAttributeMaxDynamicSharedMemorySize, SMEMH128);
    cudaFuncSetAttribute((const void*)gemm_f16_pipe<256, 8, 1>,
                         cudaFuncAttributeMaxDynamicSharedMemorySize, SMEMH256);
    cudaFuncSetAttribute(attn_f16, cudaFuncAttributeMaxDynamicSharedMemorySize,
                         ATT_WORDS * 4);

    cvt_all<<<(CVT_TOTAL4 + 255) / 256, 256>>>(
        (const float4*)x, (const float4*)Wq, (const float4*)Wk, (const float4*)Wv,
        (const float4*)Wo, (const float4*)W1, (const float4*)W2,
        xh, wqkvh, woh, w1h, w2h);
    concat_bias<<<8, 256>>>(bq, bk, bv, bqkvr);

    gemm_f16_pipe<256, 8, 1><<<dim3(2048 / 256, S / TBM), 256, SMEMH256>>>(
        xh, wqkvh, bqkvr, qkvh, S, 2048, DIM, 0, 1);

    {
        const int total = S * HQ * 64 + S * G * 64;
        rope_kernel<<<(total + 255) / 256, 256>>>(qkvh);
    }

    attn_f16<<<dim3(S / BRR, HQ, G), 256, ATT_WORDS * 4>>>(qkvh, agh);
    sum4_kernel<<<(S * HQ * D / 4 + 255) / 256, 256>>>(agh, attnh);

    gemm_f16_pipe<128, 4, 2><<<dim3(DIM / 128, S / TBM), 256, SMEMH128>>>(
        attnh, woh, bo, oh, S, DIM, HQ * D, 0, 1);

    gemm_f16_pipe<256, 8, 1><<<dim3(4 * DIM / 256, S / TBM), 256, SMEMH256>>>(
        oh, w1h, b1, h1h, S, 4 * DIM, DIM, 1, 1);
    gemm_f16_pipe<256, 8, 1><<<dim3(KOUT * DIM / 256, S / TBM), 256, SMEMH256>>>(
        h1h, w2h, b2, out, S, KOUT * DIM, 4 * DIM, 0, 0);
}